// round 2
// baseline (speedup 1.0000x reference)
#include <cuda_runtime.h>
#include <cstdint>

// Problem constants
#define EMBED 1024
#define HEADS 16
#define HDIM  64
#define BATCH 2
#define TSEQ  2048
#define MTOT  4096   // BATCH*TSEQ

// -------------------- device scratch (no allocations allowed) --------------------
__device__ float g_v[MTOT * EMBED];            // v projection, [m, 1024] natural layout
__device__ float g_ctx[MTOT * EMBED];          // attention output, [m, 1024]
__device__ unsigned char g_qb[MTOT * EMBED];   // q spikes as bytes
__device__ unsigned char g_kb[MTOT * EMBED];   // k spikes as bytes
__device__ unsigned long long g_qm[MTOT * HEADS]; // packed q spike masks [m*16+h]
__device__ unsigned long long g_km[MTOT * HEADS]; // packed k spike masks

// -------------------- f32x2 helpers (Blackwell packed fp32) --------------------
__device__ __forceinline__ unsigned long long pk2(float lo, float hi) {
    unsigned long long r;
    asm("mov.b64 %0, {%1, %2};" : "=l"(r)
        : "r"(__float_as_uint(lo)), "r"(__float_as_uint(hi)));
    return r;
}
__device__ __forceinline__ void upk2(unsigned long long p, float& lo, float& hi) {
    unsigned int a, b;
    asm("mov.b64 {%0, %1}, %2;" : "=r"(a), "=r"(b) : "l"(p));
    lo = __uint_as_float(a);
    hi = __uint_as_float(b);
}
__device__ __forceinline__ void ffma2(unsigned long long& d, unsigned long long a,
                                      unsigned long long b) {
    asm("fma.rn.f32x2 %0, %1, %2, %0;" : "+l"(d) : "l"(a), "l"(b));
}

// -------------------- GEMM: C[M,N] = A[M,K] * W[N,K]^T + bias --------------------
// MODE 0: fused QKV (grid.y 0..23 -> region q/k/v), epilogue writes spike bytes or v floats
// MODE 1: output projection: A = g_ctx, writes float out
template <int MODE>
__global__ __launch_bounds__(256) void gemm_kernel(
    const float* __restrict__ A,
    const float* __restrict__ W0, const float* __restrict__ W1, const float* __restrict__ W2,
    const float* __restrict__ b0v, const float* __restrict__ b1v, const float* __restrict__ b2v,
    float* __restrict__ outf)
{
    __shared__ float As[16][132];
    __shared__ float Bs[16][132];

    const int tid = threadIdx.x;
    const int m0 = blockIdx.x * 128;

    int region, nb;
    const float* W;
    const float* bias;
    if (MODE == 0) {
        region = blockIdx.y >> 3;
        nb = (blockIdx.y & 7) * 128;
        W = (region == 0) ? W0 : ((region == 1) ? W1 : W2);
        bias = (region == 0) ? b0v : ((region == 1) ? b1v : b2v);
    } else {
        region = 0;
        nb = blockIdx.y * 128;
        W = W0;
        bias = b0v;
    }

    const float* Aptr = (MODE == 1) ? (const float*)g_ctx : A;

    const int tm = tid >> 4;   // 0..15
    const int tn = tid & 15;   // 0..15

    unsigned long long acc[8][4];
#pragma unroll
    for (int i = 0; i < 8; i++)
#pragma unroll
        for (int j = 0; j < 4; j++) acc[i][j] = 0ULL;

    const float* Ab = Aptr + (size_t)m0 * EMBED;
    const float* Wb = W + (size_t)nb * EMBED;

    float4 pa[2], pb[2];
    // prologue: load k-tile 0
#pragma unroll
    for (int l = 0; l < 2; l++) {
        int gi = tid + l * 256;
        int r = gi >> 2, kq = gi & 3;
        pa[l] = *(const float4*)(Ab + (size_t)r * EMBED + kq * 4);
        pb[l] = *(const float4*)(Wb + (size_t)r * EMBED + kq * 4);
    }
#pragma unroll
    for (int l = 0; l < 2; l++) {
        int gi = tid + l * 256;
        int r = gi >> 2, kq = gi & 3;
        As[kq * 4 + 0][r] = pa[l].x; As[kq * 4 + 1][r] = pa[l].y;
        As[kq * 4 + 2][r] = pa[l].z; As[kq * 4 + 3][r] = pa[l].w;
        Bs[kq * 4 + 0][r] = pb[l].x; Bs[kq * 4 + 1][r] = pb[l].y;
        Bs[kq * 4 + 2][r] = pb[l].z; Bs[kq * 4 + 3][r] = pb[l].w;
    }
    __syncthreads();

    for (int kt = 0; kt < 64; ++kt) {
        if (kt < 63) {
            int koff = (kt + 1) * 16;
#pragma unroll
            for (int l = 0; l < 2; l++) {
                int gi = tid + l * 256;
                int r = gi >> 2, kq = gi & 3;
                pa[l] = *(const float4*)(Ab + (size_t)r * EMBED + koff + kq * 4);
                pb[l] = *(const float4*)(Wb + (size_t)r * EMBED + koff + kq * 4);
            }
        }
        // compute 16 k-steps from smem
#pragma unroll
        for (int k = 0; k < 16; k++) {
            float4 a0 = *(const float4*)&As[k][tm * 4];
            float4 a1 = *(const float4*)&As[k][tm * 4 + 64];
            float4 bb0 = *(const float4*)&Bs[k][tn * 4];
            float4 bb1 = *(const float4*)&Bs[k][tn * 4 + 64];
            float av[8] = {a0.x, a0.y, a0.z, a0.w, a1.x, a1.y, a1.z, a1.w};
            unsigned long long bp[4];
            bp[0] = pk2(bb0.x, bb0.y);
            bp[1] = pk2(bb0.z, bb0.w);
            bp[2] = pk2(bb1.x, bb1.y);
            bp[3] = pk2(bb1.z, bb1.w);
#pragma unroll
            for (int i = 0; i < 8; i++) {
                unsigned long long ap = pk2(av[i], av[i]);
#pragma unroll
                for (int j = 0; j < 4; j++) ffma2(acc[i][j], ap, bp[j]);
            }
        }
        if (kt < 63) {
            __syncthreads();
#pragma unroll
            for (int l = 0; l < 2; l++) {
                int gi = tid + l * 256;
                int r = gi >> 2, kq = gi & 3;
                As[kq * 4 + 0][r] = pa[l].x; As[kq * 4 + 1][r] = pa[l].y;
                As[kq * 4 + 2][r] = pa[l].z; As[kq * 4 + 3][r] = pa[l].w;
                Bs[kq * 4 + 0][r] = pb[l].x; Bs[kq * 4 + 1][r] = pb[l].y;
                Bs[kq * 4 + 2][r] = pb[l].z; Bs[kq * 4 + 3][r] = pb[l].w;
            }
            __syncthreads();
        }
    }

    // hoisted bias loads (depend only on column)
    float4 bias4[2];
    bias4[0] = *(const float4*)(bias + nb + tn * 4);
    bias4[1] = *(const float4*)(bias + nb + 64 + tn * 4);

    // epilogue
#pragma unroll
    for (int i = 0; i < 8; i++) {
        int ml = (i < 4) ? (tm * 4 + i) : (64 + tm * 4 + (i - 4));
        size_t m = (size_t)(m0 + ml);
        float c[8];
        upk2(acc[i][0], c[0], c[1]);
        upk2(acc[i][1], c[2], c[3]);
        upk2(acc[i][2], c[4], c[5]);
        upk2(acc[i][3], c[6], c[7]);
#pragma unroll
        for (int g = 0; g < 2; ++g) {
            int nl = nb + g * 64 + tn * 4;  // column within this region [0,1024)
            float bx = (g == 0) ? bias4[0].x : bias4[1].x;
            float by = (g == 0) ? bias4[0].y : bias4[1].y;
            float bz = (g == 0) ? bias4[0].z : bias4[1].z;
            float bw = (g == 0) ? bias4[0].w : bias4[1].w;
            float v0 = c[g * 4 + 0] + bx;
            float v1 = c[g * 4 + 1] + by;
            float v2 = c[g * 4 + 2] + bz;
            float v3 = c[g * 4 + 3] + bw;
            if (MODE == 0) {
                if (region == 2) {
                    *(float4*)(g_v + m * EMBED + nl) = make_float4(v0, v1, v2, v3);
                } else {
                    uchar4 s;
                    s.x = (unsigned char)(v0 >= 1.0f ? 1 : 0);
                    s.y = (unsigned char)(v1 >= 1.0f ? 1 : 0);
                    s.z = (unsigned char)(v2 >= 1.0f ? 1 : 0);
                    s.w = (unsigned char)(v3 >= 1.0f ? 1 : 0);
                    unsigned char* dst = (region == 0) ? g_qb : g_kb;
                    *(uchar4*)(dst + m * EMBED + nl) = s;
                }
            } else {
                *(float4*)(outf + m * EMBED + nl) = make_float4(v0, v1, v2, v3);
            }
        }
    }
}

// -------------------- pack spike bytes into per-head uint64 masks --------------------
__global__ void pack_kernel() {
    int idx = blockIdx.x * 256 + threadIdx.x;  // [0, 65536) = m*16 + h
    int m = idx >> 4, h = idx & 15;
    const unsigned long long* pq =
        (const unsigned long long*)(g_qb + (size_t)m * EMBED + h * 64);
    const unsigned long long* pk =
        (const unsigned long long*)(g_kb + (size_t)m * EMBED + h * 64);
    unsigned long long mq = 0, mk = 0;
#pragma unroll
    for (int w = 0; w < 8; ++w) {
        mq |= (((pq[w] & 0x0101010101010101ULL) * 0x0102040810204080ULL) >> 56)
              << (8 * w);
        mk |= (((pk[w] & 0x0101010101010101ULL) * 0x0102040810204080ULL) >> 56)
              << (8 * w);
    }
    g_qm[idx] = mq;
    g_km[idx] = mk;
}

// -------------------- attention: popcount scores + softmax + attn@v --------------------
// block: (qtile of 64 queries) x (b,h). threads 256.
__global__ __launch_bounds__(256) void attn_kernel() {
    __shared__ float Ws[64][64];   // weights [k][q]
    __shared__ float Vs[64][64];   // v tile  [k][d]
    __shared__ unsigned long long qm_s[64], km_s[64];
    __shared__ float ssum[4][64];

    const int tid = threadIdx.x;
    const int qt = blockIdx.x;        // 0..31
    const int bh = blockIdx.y;        // 0..31
    const int b = bh >> 4, h = bh & 15;
    const int q0 = qt * 64;
    const size_t mbase = (size_t)b * TSEQ;

    if (tid < 64) qm_s[tid] = g_qm[(mbase + q0 + tid) * HEADS + h];

    const int qa = tid & 63, kg = tid >> 6;   // phase A mapping
    const int tq = tid >> 4, td = tid & 15;   // phase B mapping

    unsigned long long acc[4][2];
#pragma unroll
    for (int qq = 0; qq < 4; qq++) { acc[qq][0] = 0ULL; acc[qq][1] = 0ULL; }
    float rsum = 0.0f;

    const float* vbase = g_v + mbase * EMBED + h * HDIM;

    for (int kt = 0; kt < 32; ++kt) {
        __syncthreads();  // prior phase B done; first iter: qm_s visible
        if (tid < 64) km_s[tid] = g_km[(mbase + kt * 64 + tid) * HEADS + h];
#pragma unroll
        for (int l = 0; l < 4; l++) {
            int gi = tid + l * 256;          // 0..1023
            int r = gi >> 4, c4 = (gi & 15) * 4;
            *(float4*)&Vs[r][c4] =
                *(const float4*)(vbase + (size_t)(kt * 64 + r) * EMBED + c4);
        }
        __syncthreads();
        // phase A: weights = exp(score/8) = 2^(s * 1/(8 ln2)); score integer via popcount
        unsigned long long q64 = qm_s[qa];
#pragma unroll
        for (int i = 0; i < 16; i++) {
            int k = kg * 16 + i;
            int s = __popcll(q64 & km_s[k]);
            float w = exp2f((float)s * 0.18033688011112042f);
            Ws[k][qa] = w;
            rsum += w;
        }
        __syncthreads();
        // phase B: acc[64q x 64d] += Ws[64k x 64q]^T @ Vs[64k x 64d]
#pragma unroll 4
        for (int k = 0; k < 64; k++) {
            float4 w4 = *(const float4*)&Ws[k][tq * 4];
            float4 v4 = *(const float4*)&Vs[k][td * 4];
            unsigned long long vp0 = pk2(v4.x, v4.y);
            unsigned long long vp1 = pk2(v4.z, v4.w);
            float wv[4] = {w4.x, w4.y, w4.z, w4.w};
#pragma unroll
            for (int qq = 0; qq < 4; ++qq) {
                unsigned long long wp = pk2(wv[qq], wv[qq]);
                ffma2(acc[qq][0], wp, vp0);
                ffma2(acc[qq][1], wp, vp1);
            }
        }
    }
    __syncthreads();
    ssum[kg][qa] = rsum;
    __syncthreads();

    // epilogue: normalize, write ctx
    float* obase = g_ctx + (mbase + q0) * EMBED + h * HDIM;
#pragma unroll
    for (int qq = 0; qq < 4; qq++) {
        int q = tq * 4 + qq;
        float S = ssum[0][q] + ssum[1][q] + ssum[2][q] + ssum[3][q];
        float inv = 1.0f / S;
        float o0, o1, o2, o3;
        upk2(acc[qq][0], o0, o1);
        upk2(acc[qq][1], o2, o3);
        *(float4*)(obase + (size_t)q * EMBED + td * 4) =
            make_float4(o0 * inv, o1 * inv, o2 * inv, o3 * inv);
    }
}

// -------------------- launch --------------------
extern "C" void kernel_launch(void* const* d_in, const int* in_sizes, int n_in,
                              void* d_out, int out_size) {
    const float* x  = (const float*)d_in[0];
    const float* Wq = (const float*)d_in[1];
    const float* bq = (const float*)d_in[2];
    const float* Wk = (const float*)d_in[3];
    const float* bk = (const float*)d_in[4];
    const float* Wv = (const float*)d_in[5];
    const float* bv = (const float*)d_in[6];
    const float* Wo = (const float*)d_in[7];
    const float* bo = (const float*)d_in[8];
    float* out = (float*)d_out;

    // 1) fused QKV projection (N=3072 split over 24 y-blocks; q/k -> spike bytes, v -> floats)
    gemm_kernel<0><<<dim3(32, 24), 256>>>(x, Wq, Wk, Wv, bq, bk, bv, nullptr);
    // 2) pack spike bytes -> per-head 64-bit masks
    pack_kernel<<<256, 256>>>();
    // 3) attention: popcount scores, exp weights, attn@v, normalize
    attn_kernel<<<dim3(32, 32), 256>>>();
    // 4) output projection -> d_out
    gemm_kernel<1><<<dim3(32, 8), 256>>>(nullptr, Wo, nullptr, nullptr, bo, nullptr,
                                         nullptr, out);
}

// round 4
// speedup vs baseline: 1.3937x; 1.3937x over previous
#include <cuda_runtime.h>
#include <cuda_bf16.h>
#include <cstdint>

// Problem constants
#define EMBED 1024
#define HEADS 16
#define HDIM  64
#define BATCH 2
#define TSEQ  2048
#define MTOT  4096   // BATCH*TSEQ

// -------------------- device scratch --------------------
__device__ float g_v[MTOT * EMBED];
__device__ float g_ctx[MTOT * EMBED];
__device__ unsigned long long g_qm[MTOT * HEADS];
__device__ unsigned long long g_km[MTOT * HEADS];
__device__ __nv_bfloat16 g_xh[MTOT * EMBED];
__device__ __nv_bfloat16 g_xl[MTOT * EMBED];
__device__ __nv_bfloat16 g_wh[4096 * EMBED];   // Wq|Wk|Wv|Wo rows
__device__ __nv_bfloat16 g_wl[4096 * EMBED];
__device__ __nv_bfloat16 g_ch[MTOT * EMBED];
__device__ __nv_bfloat16 g_cl[MTOT * EMBED];

// -------------------- helpers --------------------
__device__ __forceinline__ uint32_t smem_u32(const void* p) {
    uint32_t a;
    asm("{ .reg .u64 t; cvta.to.shared.u64 t, %1; cvt.u32.u64 %0, t; }" : "=r"(a) : "l"(p));
    return a;
}
__device__ __forceinline__ void ldsm_x4(uint32_t& r0, uint32_t& r1, uint32_t& r2,
                                        uint32_t& r3, uint32_t addr) {
    asm volatile("ldmatrix.sync.aligned.m8n8.x4.shared.b16 {%0,%1,%2,%3}, [%4];"
                 : "=r"(r0), "=r"(r1), "=r"(r2), "=r"(r3) : "r"(addr));
}
__device__ __forceinline__ void mma16816(float* d, const uint32_t* a, const uint32_t* b) {
    asm volatile(
        "mma.sync.aligned.m16n8k16.row.col.f32.bf16.bf16.f32 "
        "{%0,%1,%2,%3}, {%4,%5,%6,%7}, {%8,%9}, {%0,%1,%2,%3};"
        : "+f"(d[0]), "+f"(d[1]), "+f"(d[2]), "+f"(d[3])
        : "r"(a[0]), "r"(a[1]), "r"(a[2]), "r"(a[3]), "r"(b[0]), "r"(b[1]));
}

// -------------------- f32x2 helpers --------------------
__device__ __forceinline__ unsigned long long pk2(float lo, float hi) {
    unsigned long long r;
    asm("mov.b64 %0, {%1, %2};" : "=l"(r) : "r"(__float_as_uint(lo)), "r"(__float_as_uint(hi)));
    return r;
}
__device__ __forceinline__ void upk2(unsigned long long p, float& lo, float& hi) {
    unsigned int a, b;
    asm("mov.b64 {%0, %1}, %2;" : "=r"(a), "=r"(b) : "l"(p));
    lo = __uint_as_float(a); hi = __uint_as_float(b);
}
__device__ __forceinline__ void ffma2(unsigned long long& d, unsigned long long a,
                                      unsigned long long b) {
    asm("fma.rn.f32x2 %0, %1, %2, %0;" : "+l"(d) : "l"(a), "l"(b));
}

// -------------------- convert kernels: fp32 -> bf16 hi/lo split --------------------
__device__ __forceinline__ void split_store(float v, __nv_bfloat16* ph, __nv_bfloat16* pl) {
    __nv_bfloat16 h = __float2bfloat16_rn(v);
    float r = v - __bfloat162float(h);
    *ph = h;
    *pl = __float2bfloat16_rn(r);
}

__global__ __launch_bounds__(256) void convert_x_kernel(const float* __restrict__ x) {
    int i = (blockIdx.x * 256 + threadIdx.x) * 4;
    float4 v = *(const float4*)(x + i);
    split_store(v.x, g_xh + i, g_xl + i);
    split_store(v.y, g_xh + i + 1, g_xl + i + 1);
    split_store(v.z, g_xh + i + 2, g_xl + i + 2);
    split_store(v.w, g_xh + i + 3, g_xl + i + 3);
}

__global__ __launch_bounds__(256) void convert_w_kernel(
    const float* __restrict__ Wq, const float* __restrict__ Wk,
    const float* __restrict__ Wv, const float* __restrict__ Wo) {
    int i = (blockIdx.x * 256 + threadIdx.x) * 4;
    int row = i >> 10, col = i & 1023;
    const float* src;
    if (row < 1024)      src = Wq + (size_t)row * EMBED + col;
    else if (row < 2048) src = Wk + (size_t)(row - 1024) * EMBED + col;
    else if (row < 3072) src = Wv + (size_t)(row - 2048) * EMBED + col;
    else                 src = Wo + (size_t)(row - 3072) * EMBED + col;
    float4 v = *(const float4*)src;
    split_store(v.x, g_wh + i, g_wl + i);
    split_store(v.y, g_wh + i + 1, g_wl + i + 1);
    split_store(v.z, g_wh + i + 2, g_wl + i + 2);
    split_store(v.w, g_wh + i + 3, g_wl + i + 3);
}

__global__ __launch_bounds__(256) void convert_ctx_kernel() {
    int i = (blockIdx.x * 256 + threadIdx.x) * 4;
    float4 v = *(const float4*)(g_ctx + i);
    split_store(v.x, g_ch + i, g_cl + i);
    split_store(v.y, g_ch + i + 1, g_cl + i + 1);
    split_store(v.z, g_ch + i + 2, g_cl + i + 2);
    split_store(v.w, g_ch + i + 3, g_cl + i + 3);
}

// -------------------- mma.sync GEMM --------------------
// C[128,128] = A[128,1024] * W_rows[128,1024]^T via split-bf16 (3 accumulating passes)
// MODE 0: A = x, W rows 0..3071 (Wq|Wk|Wv). grid (32, 24).
// MODE 1: A = ctx, W rows 3072..4095 (Wo). grid (32, 8).
#define KC 32                 // k-chunk
#define TPAD 40               // padded bf16 row stride (80 B)
#define TILE_B (128 * TPAD * 2)   // 10240 bytes per sub-tile
#define BUF_B (4 * TILE_B)        // AH, AL, BH, BL

template <int MODE>
__global__ __launch_bounds__(256, 1) void mma_gemm_kernel(
    const float* __restrict__ bq, const float* __restrict__ bk,
    const float* __restrict__ bv, const float* __restrict__ bo,
    float* __restrict__ outf)
{
    extern __shared__ char smem[];
    const int tid = threadIdx.x;
    const int wid = tid >> 5, lane = tid & 31;
    const int m0 = blockIdx.x * 128;
    const int nb_glob = blockIdx.y * 128;

    const __nv_bfloat16* Ah = (MODE == 0) ? g_xh : g_ch;
    const __nv_bfloat16* Al = (MODE == 0) ? g_xl : g_cl;
    const int wrow0 = (MODE == 0) ? nb_glob : (3072 + nb_glob);
    const __nv_bfloat16* Bh = g_wh + (size_t)wrow0 * EMBED;
    const __nv_bfloat16* Bl = g_wl + (size_t)wrow0 * EMBED;
    const __nv_bfloat16* Aoff = Ah + (size_t)m0 * EMBED;
    const __nv_bfloat16* ALoff = Al + (size_t)m0 * EMBED;

    // warp coords: 2 (m) x 4 (n)
    const int wm = wid >> 2, wn = wid & 3;
    const int mrow0 = wm * 64, ncol0 = wn * 32;

    // ldmatrix lane-address components
    const int aRow = lane & 15, aCol = (lane >> 4) * 8;
    const int bRow = ((lane >> 4) & 1) * 8 + (lane & 7);
    const int bCol = ((lane >> 3) & 1) * 8;

    float acc[4][4][4];
#pragma unroll
    for (int i = 0; i < 4; i++)
#pragma unroll
        for (int j = 0; j < 4; j++)
#pragma unroll
            for (int r = 0; r < 4; r++) acc[i][j][r] = 0.0f;

    // global->smem loader mapping: 512 16B-groups per sub-tile, 2 per thread
    const int lr0 = tid >> 2, lg0 = (tid & 3);          // item 0: row, group
    const int lr1 = (tid + 256) >> 2, lg1 = ((tid + 256) & 3);

    const uint32_t sb = smem_u32(smem);

    uint4 sa[2], sal[2], sbh[2], sbl[2];
    // prologue: load chunk 0
    {
        size_t o0 = (size_t)lr0 * EMBED + lg0 * 8;
        size_t o1 = (size_t)lr1 * EMBED + lg1 * 8;
        sa[0] = *(const uint4*)(Aoff + o0);  sa[1] = *(const uint4*)(Aoff + o1);
        sal[0] = *(const uint4*)(ALoff + o0); sal[1] = *(const uint4*)(ALoff + o1);
        sbh[0] = *(const uint4*)(Bh + o0);   sbh[1] = *(const uint4*)(Bh + o1);
        sbl[0] = *(const uint4*)(Bl + o0);   sbl[1] = *(const uint4*)(Bl + o1);
        char* p = smem;  // buffer 0
        uint32_t s0 = (uint32_t)(lr0 * TPAD + lg0 * 8) * 2;
        uint32_t s1 = (uint32_t)(lr1 * TPAD + lg1 * 8) * 2;
        *(uint4*)(p + 0 * TILE_B + s0) = sa[0];  *(uint4*)(p + 0 * TILE_B + s1) = sa[1];
        *(uint4*)(p + 1 * TILE_B + s0) = sal[0]; *(uint4*)(p + 1 * TILE_B + s1) = sal[1];
        *(uint4*)(p + 2 * TILE_B + s0) = sbh[0]; *(uint4*)(p + 2 * TILE_B + s1) = sbh[1];
        *(uint4*)(p + 3 * TILE_B + s0) = sbl[0]; *(uint4*)(p + 3 * TILE_B + s1) = sbl[1];
    }
    __syncthreads();

    for (int c = 0; c < 32; ++c) {
        const int buf = c & 1;
        if (c < 31) {
            const int kc = (c + 1) * KC;
            size_t o0 = (size_t)lr0 * EMBED + kc + lg0 * 8;
            size_t o1 = (size_t)lr1 * EMBED + kc + lg1 * 8;
            sa[0] = *(const uint4*)(Aoff + o0);  sa[1] = *(const uint4*)(Aoff + o1);
            sal[0] = *(const uint4*)(ALoff + o0); sal[1] = *(const uint4*)(ALoff + o1);
            sbh[0] = *(const uint4*)(Bh + o0);   sbh[1] = *(const uint4*)(Bh + o1);
            sbl[0] = *(const uint4*)(Bl + o0);   sbl[1] = *(const uint4*)(Bl + o1);
        }
        // compute from buf
        const uint32_t pAh = sb + buf * BUF_B + 0 * TILE_B;
        const uint32_t pAl = sb + buf * BUF_B + 1 * TILE_B;
        const uint32_t pBh = sb + buf * BUF_B + 2 * TILE_B;
        const uint32_t pBl = sb + buf * BUF_B + 3 * TILE_B;
#pragma unroll
        for (int kk = 0; kk < KC; kk += 16) {
            uint32_t aF[2][4][4], bF[2][4][2];
#pragma unroll
            for (int mi = 0; mi < 4; ++mi) {
                uint32_t off = (uint32_t)((mrow0 + mi * 16 + aRow) * TPAD + kk + aCol) * 2;
                ldsm_x4(aF[0][mi][0], aF[0][mi][1], aF[0][mi][2], aF[0][mi][3], pAh + off);
                ldsm_x4(aF[1][mi][0], aF[1][mi][1], aF[1][mi][2], aF[1][mi][3], pAl + off);
            }
#pragma unroll
            for (int n2 = 0; n2 < 2; ++n2) {
                uint32_t off = (uint32_t)((ncol0 + n2 * 16 + bRow) * TPAD + kk + bCol) * 2;
                ldsm_x4(bF[0][n2 * 2][0], bF[0][n2 * 2][1],
                        bF[0][n2 * 2 + 1][0], bF[0][n2 * 2 + 1][1], pBh + off);
                ldsm_x4(bF[1][n2 * 2][0], bF[1][n2 * 2][1],
                        bF[1][n2 * 2 + 1][0], bF[1][n2 * 2 + 1][1], pBl + off);
            }
            // 3 passes: hh, hl, lh
#pragma unroll
            for (int mi = 0; mi < 4; ++mi)
#pragma unroll
                for (int ni = 0; ni < 4; ++ni) mma16816(acc[mi][ni], aF[0][mi], bF[0][ni]);
#pragma unroll
            for (int mi = 0; mi < 4; ++mi)
#pragma unroll
                for (int ni = 0; ni < 4; ++ni) mma16816(acc[mi][ni], aF[0][mi], bF[1][ni]);
#pragma unroll
            for (int mi = 0; mi < 4; ++mi)
#pragma unroll
                for (int ni = 0; ni < 4; ++ni) mma16816(acc[mi][ni], aF[1][mi], bF[0][ni]);
        }
        if (c < 31) {
            char* p = smem + ((c + 1) & 1) * BUF_B;
            uint32_t s0 = (uint32_t)(lr0 * TPAD + lg0 * 8) * 2;
            uint32_t s1 = (uint32_t)(lr1 * TPAD + lg1 * 8) * 2;
            *(uint4*)(p + 0 * TILE_B + s0) = sa[0];  *(uint4*)(p + 0 * TILE_B + s1) = sa[1];
            *(uint4*)(p + 1 * TILE_B + s0) = sal[0]; *(uint4*)(p + 1 * TILE_B + s1) = sal[1];
            *(uint4*)(p + 2 * TILE_B + s0) = sbh[0]; *(uint4*)(p + 2 * TILE_B + s1) = sbh[1];
            *(uint4*)(p + 3 * TILE_B + s0) = sbl[0]; *(uint4*)(p + 3 * TILE_B + s1) = sbl[1];
            __syncthreads();
        }
    }

    // ---- epilogue ----
    const int region = (MODE == 0) ? (nb_glob >> 10) : 3;      // 0 q, 1 k, 2 v, 3 out
    const int nloc = nb_glob & 1023;
    const float* bias = (MODE == 1) ? bo : ((region == 0) ? bq : ((region == 1) ? bk : bv));

    const int trow = lane >> 2;       // 0..7
    const int tcol = (lane & 3) * 2;  // 0,2,4,6

    if (region <= 1) {
        // stage spike bytes in smem [128][128], then pack bit-masks
        __syncthreads();
        unsigned char* Sb = (unsigned char*)smem;
#pragma unroll
        for (int mi = 0; mi < 4; ++mi)
#pragma unroll
            for (int ni = 0; ni < 4; ++ni)
#pragma unroll
                for (int ci = 0; ci < 4; ++ci) {
                    int gr = mrow0 + mi * 16 + trow + ((ci >> 1) ? 8 : 0);
                    int gc = ncol0 + ni * 8 + tcol + (ci & 1);
                    float v = acc[mi][ni][ci] + bias[nloc + gc];
                    Sb[gr * 128 + gc] = (unsigned char)(v >= 1.0f ? 1 : 0);
                }
        __syncthreads();
        // pack: each thread handles one (row, head-half)
        int row = tid >> 1, half = tid & 1;
        const unsigned long long* pp = (const unsigned long long*)(Sb + row * 128 + half * 64);
        unsigned long long mask = 0;
#pragma unroll
        for (int w = 0; w < 8; ++w)
            mask |= (((pp[w] & 0x0101010101010101ULL) * 0x0102040810204080ULL) >> 56)
                    << (8 * w);
        unsigned long long* dst = (region == 0) ? g_qm : g_km;
        int h0 = nloc >> 6;
        dst[(size_t)(m0 + row) * HEADS + h0 + half] = mask;
    } else {
        float* dst = (MODE == 0) ? g_v : outf;
#pragma unroll
        for (int mi = 0; mi < 4; ++mi)
#pragma unroll
            for (int ni = 0; ni < 4; ++ni)
#pragma unroll
                for (int ci = 0; ci < 4; ci += 2) {
                    int gr = m0 + mrow0 + mi * 16 + trow + (ci ? 8 : 0);
                    int gc = ncol0 + ni * 8 + tcol;
                    int col = ((MODE == 0) ? nloc : nb_glob) + gc;
                    float2 o;
                    o.x = acc[mi][ni][ci] + bias[col];
                    o.y = acc[mi][ni][ci + 1] + bias[col + 1];
                    *(float2*)(dst + (size_t)gr * EMBED + col) = o;
                }
    }
}

// -------------------- attention --------------------
__global__ __launch_bounds__(256) void attn_kernel() {
    __shared__ float Ws[64][64];
    __shared__ float Vs[64][64];
    __shared__ unsigned long long qm_s[64], km_s[64];
    __shared__ float ssum[4][64];

    const int tid = threadIdx.x;
    const int qt = blockIdx.x;
    const int bh = blockIdx.y;
    const int b = bh >> 4, h = bh & 15;
    const int q0 = qt * 64;
    const size_t mbase = (size_t)b * TSEQ;

    if (tid < 64) qm_s[tid] = g_qm[(mbase + q0 + tid) * HEADS + h];

    const int qa = tid & 63, kg = tid >> 6;
    const int tq = tid >> 4, td = tid & 15;

    unsigned long long acc[4][2];
#pragma unroll
    for (int qq = 0; qq < 4; qq++) { acc[qq][0] = 0ULL; acc[qq][1] = 0ULL; }
    float rsum = 0.0f;

    const float* vbase = g_v + mbase * EMBED + h * HDIM;

    for (int kt = 0; kt < 32; ++kt) {
        __syncthreads();
        if (tid < 64) km_s[tid] = g_km[(mbase + kt * 64 + tid) * HEADS + h];
#pragma unroll
        for (int l = 0; l < 4; l++) {
            int gi = tid + l * 256;
            int r = gi >> 4, c4 = (gi & 15) * 4;
            *(float4*)&Vs[r][c4] =
                *(const float4*)(vbase + (size_t)(kt * 64 + r) * EMBED + c4);
        }
        __syncthreads();
        unsigned long long q64 = qm_s[qa];
#pragma unroll
        for (int i = 0; i < 16; i++) {
            int k = kg * 16 + i;
            int s = __popcll(q64 & km_s[k]);
            float w = exp2f((float)s * 0.18033688011112042f);
            Ws[k][qa] = w;
            rsum += w;
        }
        __syncthreads();
#pragma unroll 4
        for (int k = 0; k < 64; k++) {
            float4 w4 = *(const float4*)&Ws[k][tq * 4];
            float4 v4 = *(const float4*)&Vs[k][td * 4];
            unsigned long long vp0 = pk2(v4.x, v4.y);
            unsigned long long vp1 = pk2(v4.z, v4.w);
            float wv[4] = {w4.x, w4.y, w4.z, w4.w};
#pragma unroll
            for (int qq = 0; qq < 4; ++qq) {
                unsigned long long wp = pk2(wv[qq], wv[qq]);
                ffma2(acc[qq][0], wp, vp0);
                ffma2(acc[qq][1], wp, vp1);
            }
        }
    }
    __syncthreads();
    ssum[kg][qa] = rsum;
    __syncthreads();

    float* obase = g_ctx + (mbase + q0) * EMBED + h * HDIM;
#pragma unroll
    for (int qq = 0; qq < 4; qq++) {
        int q = tq * 4 + qq;
        float S = ssum[0][q] + ssum[1][q] + ssum[2][q] + ssum[3][q];
        float inv = 1.0f / S;
        float o0, o1, o2, o3;
        upk2(acc[qq][0], o0, o1);
        upk2(acc[qq][1], o2, o3);
        *(float4*)(obase + (size_t)q * EMBED + td * 4) =
            make_float4(o0 * inv, o1 * inv, o2 * inv, o3 * inv);
    }
}

// -------------------- launch --------------------
extern "C" void kernel_launch(void* const* d_in, const int* in_sizes, int n_in,
                              void* d_out, int out_size) {
    const float* x  = (const float*)d_in[0];
    const float* Wq = (const float*)d_in[1];
    const float* bq = (const float*)d_in[2];
    const float* Wk = (const float*)d_in[3];
    const float* bk = (const float*)d_in[4];
    const float* Wv = (const float*)d_in[5];
    const float* bv = (const float*)d_in[6];
    const float* Wo = (const float*)d_in[7];
    const float* bo = (const float*)d_in[8];
    float* out = (float*)d_out;

    const int SMEM_MMA = 2 * BUF_B;   // 81920 bytes
    cudaFuncSetAttribute(mma_gemm_kernel<0>, cudaFuncAttributeMaxDynamicSharedMemorySize, SMEM_MMA);
    cudaFuncSetAttribute(mma_gemm_kernel<1>, cudaFuncAttributeMaxDynamicSharedMemorySize, SMEM_MMA);

    convert_x_kernel<<<4096, 256>>>(x);
    convert_w_kernel<<<4096, 256>>>(Wq, Wk, Wv, Wo);
    mma_gemm_kernel<0><<<dim3(32, 24), 256, SMEM_MMA>>>(bq, bk, bv, bo, nullptr);
    attn_kernel<<<dim3(32, 32), 256>>>();
    convert_ctx_kernel<<<4096, 256>>>();
    mma_gemm_kernel<1><<<dim3(32, 8), 256, SMEM_MMA>>>(bq, bk, bv, bo, out);
}

// round 5
// speedup vs baseline: 1.7011x; 1.2205x over previous
#include <cuda_runtime.h>
#include <cuda_bf16.h>
#include <cstdint>

// Problem constants
#define EMBED 1024
#define HEADS 16
#define HDIM  64
#define BATCH 2
#define TSEQ  2048
#define MTOT  4096   // BATCH*TSEQ

// -------------------- device scratch --------------------
__device__ unsigned long long g_qm[MTOT * HEADS];
__device__ unsigned long long g_km[MTOT * HEADS];
__device__ __nv_bfloat16 g_vh[MTOT * EMBED];   // v projection split hi/lo
__device__ __nv_bfloat16 g_vl[MTOT * EMBED];
__device__ __nv_bfloat16 g_xh[MTOT * EMBED];
__device__ __nv_bfloat16 g_xl[MTOT * EMBED];
__device__ __nv_bfloat16 g_wh[4096 * EMBED];   // Wq|Wk|Wv|Wo rows
__device__ __nv_bfloat16 g_wl[4096 * EMBED];
__device__ __nv_bfloat16 g_ch[MTOT * EMBED];   // ctx split hi/lo (written by attn)
__device__ __nv_bfloat16 g_cl[MTOT * EMBED];

// -------------------- helpers --------------------
__device__ __forceinline__ uint32_t smem_u32(const void* p) {
    uint32_t a;
    asm("{ .reg .u64 t; cvta.to.shared.u64 t, %1; cvt.u32.u64 %0, t; }" : "=r"(a) : "l"(p));
    return a;
}
__device__ __forceinline__ void ldsm_x4(uint32_t& r0, uint32_t& r1, uint32_t& r2,
                                        uint32_t& r3, uint32_t addr) {
    asm volatile("ldmatrix.sync.aligned.m8n8.x4.shared.b16 {%0,%1,%2,%3}, [%4];"
                 : "=r"(r0), "=r"(r1), "=r"(r2), "=r"(r3) : "r"(addr));
}
__device__ __forceinline__ void ldsm_x4t(uint32_t& r0, uint32_t& r1, uint32_t& r2,
                                         uint32_t& r3, uint32_t addr) {
    asm volatile("ldmatrix.sync.aligned.m8n8.x4.trans.shared.b16 {%0,%1,%2,%3}, [%4];"
                 : "=r"(r0), "=r"(r1), "=r"(r2), "=r"(r3) : "r"(addr));
}
__device__ __forceinline__ void mma16816(float* d, const uint32_t* a, const uint32_t* b) {
    asm volatile(
        "mma.sync.aligned.m16n8k16.row.col.f32.bf16.bf16.f32 "
        "{%0,%1,%2,%3}, {%4,%5,%6,%7}, {%8,%9}, {%0,%1,%2,%3};"
        : "+f"(d[0]), "+f"(d[1]), "+f"(d[2]), "+f"(d[3])
        : "r"(a[0]), "r"(a[1]), "r"(a[2]), "r"(a[3]), "r"(b[0]), "r"(b[1]));
}

// -------------------- convert kernels: fp32 -> bf16 hi/lo split --------------------
__device__ __forceinline__ void split_store(float v, __nv_bfloat16* ph, __nv_bfloat16* pl) {
    __nv_bfloat16 h = __float2bfloat16_rn(v);
    float r = v - __bfloat162float(h);
    *ph = h;
    *pl = __float2bfloat16_rn(r);
}

__global__ __launch_bounds__(256) void convert_x_kernel(const float* __restrict__ x) {
    int i = (blockIdx.x * 256 + threadIdx.x) * 4;
    float4 v = *(const float4*)(x + i);
    split_store(v.x, g_xh + i, g_xl + i);
    split_store(v.y, g_xh + i + 1, g_xl + i + 1);
    split_store(v.z, g_xh + i + 2, g_xl + i + 2);
    split_store(v.w, g_xh + i + 3, g_xl + i + 3);
}

__global__ __launch_bounds__(256) void convert_w_kernel(
    const float* __restrict__ Wq, const float* __restrict__ Wk,
    const float* __restrict__ Wv, const float* __restrict__ Wo) {
    int i = (blockIdx.x * 256 + threadIdx.x) * 4;
    int row = i >> 10, col = i & 1023;
    const float* src;
    if (row < 1024)      src = Wq + (size_t)row * EMBED + col;
    else if (row < 2048) src = Wk + (size_t)(row - 1024) * EMBED + col;
    else if (row < 3072) src = Wv + (size_t)(row - 2048) * EMBED + col;
    else                 src = Wo + (size_t)(row - 3072) * EMBED + col;
    float4 v = *(const float4*)src;
    split_store(v.x, g_wh + i, g_wl + i);
    split_store(v.y, g_wh + i + 1, g_wl + i + 1);
    split_store(v.z, g_wh + i + 2, g_wl + i + 2);
    split_store(v.w, g_wh + i + 3, g_wl + i + 3);
}

// -------------------- mma.sync GEMM --------------------
// C[128,128] = A[128,1024] * W_rows[128,1024]^T via split-bf16 (3 accumulating passes)
// MODE 0: A = x, W rows 0..3071 (Wq|Wk|Wv). grid (32, 24).
// MODE 1: A = ctx (g_ch/g_cl), W rows 3072..4095 (Wo). grid (32, 8).
#define KC 32
#define TPAD 40
#define TILE_B (128 * TPAD * 2)
#define BUF_B (4 * TILE_B)

template <int MODE>
__global__ __launch_bounds__(256, 1) void mma_gemm_kernel(
    const float* __restrict__ bq, const float* __restrict__ bk,
    const float* __restrict__ bv, const float* __restrict__ bo,
    float* __restrict__ outf)
{
    extern __shared__ char smem[];
    const int tid = threadIdx.x;
    const int wid = tid >> 5, lane = tid & 31;
    const int m0 = blockIdx.x * 128;
    const int nb_glob = blockIdx.y * 128;

    const __nv_bfloat16* Ah = (MODE == 0) ? g_xh : g_ch;
    const __nv_bfloat16* Al = (MODE == 0) ? g_xl : g_cl;
    const int wrow0 = (MODE == 0) ? nb_glob : (3072 + nb_glob);
    const __nv_bfloat16* Bh = g_wh + (size_t)wrow0 * EMBED;
    const __nv_bfloat16* Bl = g_wl + (size_t)wrow0 * EMBED;
    const __nv_bfloat16* Aoff = Ah + (size_t)m0 * EMBED;
    const __nv_bfloat16* ALoff = Al + (size_t)m0 * EMBED;

    const int wm = wid >> 2, wn = wid & 3;
    const int mrow0 = wm * 64, ncol0 = wn * 32;

    const int aRow = lane & 15, aCol = (lane >> 4) * 8;
    const int bRow = ((lane >> 4) & 1) * 8 + (lane & 7);
    const int bCol = ((lane >> 3) & 1) * 8;

    float acc[4][4][4];
#pragma unroll
    for (int i = 0; i < 4; i++)
#pragma unroll
        for (int j = 0; j < 4; j++)
#pragma unroll
            for (int r = 0; r < 4; r++) acc[i][j][r] = 0.0f;

    const int lr0 = tid >> 2, lg0 = (tid & 3);
    const int lr1 = (tid + 256) >> 2, lg1 = ((tid + 256) & 3);

    const uint32_t sb = smem_u32(smem);

    uint4 sa[2], sal[2], sbh[2], sbl[2];
    {
        size_t o0 = (size_t)lr0 * EMBED + lg0 * 8;
        size_t o1 = (size_t)lr1 * EMBED + lg1 * 8;
        sa[0] = *(const uint4*)(Aoff + o0);  sa[1] = *(const uint4*)(Aoff + o1);
        sal[0] = *(const uint4*)(ALoff + o0); sal[1] = *(const uint4*)(ALoff + o1);
        sbh[0] = *(const uint4*)(Bh + o0);   sbh[1] = *(const uint4*)(Bh + o1);
        sbl[0] = *(const uint4*)(Bl + o0);   sbl[1] = *(const uint4*)(Bl + o1);
        char* p = smem;
        uint32_t s0 = (uint32_t)(lr0 * TPAD + lg0 * 8) * 2;
        uint32_t s1 = (uint32_t)(lr1 * TPAD + lg1 * 8) * 2;
        *(uint4*)(p + 0 * TILE_B + s0) = sa[0];  *(uint4*)(p + 0 * TILE_B + s1) = sa[1];
        *(uint4*)(p + 1 * TILE_B + s0) = sal[0]; *(uint4*)(p + 1 * TILE_B + s1) = sal[1];
        *(uint4*)(p + 2 * TILE_B + s0) = sbh[0]; *(uint4*)(p + 2 * TILE_B + s1) = sbh[1];
        *(uint4*)(p + 3 * TILE_B + s0) = sbl[0]; *(uint4*)(p + 3 * TILE_B + s1) = sbl[1];
    }
    __syncthreads();

    for (int c = 0; c < 32; ++c) {
        const int buf = c & 1;
        if (c < 31) {
            const int kc = (c + 1) * KC;
            size_t o0 = (size_t)lr0 * EMBED + kc + lg0 * 8;
            size_t o1 = (size_t)lr1 * EMBED + kc + lg1 * 8;
            sa[0] = *(const uint4*)(Aoff + o0);  sa[1] = *(const uint4*)(Aoff + o1);
            sal[0] = *(const uint4*)(ALoff + o0); sal[1] = *(const uint4*)(ALoff + o1);
            sbh[0] = *(const uint4*)(Bh + o0);   sbh[1] = *(const uint4*)(Bh + o1);
            sbl[0] = *(const uint4*)(Bl + o0);   sbl[1] = *(const uint4*)(Bl + o1);
        }
        const uint32_t pAh = sb + buf * BUF_B + 0 * TILE_B;
        const uint32_t pAl = sb + buf * BUF_B + 1 * TILE_B;
        const uint32_t pBh = sb + buf * BUF_B + 2 * TILE_B;
        const uint32_t pBl = sb + buf * BUF_B + 3 * TILE_B;
#pragma unroll
        for (int kk = 0; kk < KC; kk += 16) {
            uint32_t aF[2][4][4], bF[2][4][2];
#pragma unroll
            for (int mi = 0; mi < 4; ++mi) {
                uint32_t off = (uint32_t)((mrow0 + mi * 16 + aRow) * TPAD + kk + aCol) * 2;
                ldsm_x4(aF[0][mi][0], aF[0][mi][1], aF[0][mi][2], aF[0][mi][3], pAh + off);
                ldsm_x4(aF[1][mi][0], aF[1][mi][1], aF[1][mi][2], aF[1][mi][3], pAl + off);
            }
#pragma unroll
            for (int n2 = 0; n2 < 2; ++n2) {
                uint32_t off = (uint32_t)((ncol0 + n2 * 16 + bRow) * TPAD + kk + bCol) * 2;
                ldsm_x4(bF[0][n2 * 2][0], bF[0][n2 * 2][1],
                        bF[0][n2 * 2 + 1][0], bF[0][n2 * 2 + 1][1], pBh + off);
                ldsm_x4(bF[1][n2 * 2][0], bF[1][n2 * 2][1],
                        bF[1][n2 * 2 + 1][0], bF[1][n2 * 2 + 1][1], pBl + off);
            }
#pragma unroll
            for (int mi = 0; mi < 4; ++mi)
#pragma unroll
                for (int ni = 0; ni < 4; ++ni) mma16816(acc[mi][ni], aF[0][mi], bF[0][ni]);
#pragma unroll
            for (int mi = 0; mi < 4; ++mi)
#pragma unroll
                for (int ni = 0; ni < 4; ++ni) mma16816(acc[mi][ni], aF[0][mi], bF[1][ni]);
#pragma unroll
            for (int mi = 0; mi < 4; ++mi)
#pragma unroll
                for (int ni = 0; ni < 4; ++ni) mma16816(acc[mi][ni], aF[1][mi], bF[0][ni]);
        }
        if (c < 31) {
            char* p = smem + ((c + 1) & 1) * BUF_B;
            uint32_t s0 = (uint32_t)(lr0 * TPAD + lg0 * 8) * 2;
            uint32_t s1 = (uint32_t)(lr1 * TPAD + lg1 * 8) * 2;
            *(uint4*)(p + 0 * TILE_B + s0) = sa[0];  *(uint4*)(p + 0 * TILE_B + s1) = sa[1];
            *(uint4*)(p + 1 * TILE_B + s0) = sal[0]; *(uint4*)(p + 1 * TILE_B + s1) = sal[1];
            *(uint4*)(p + 2 * TILE_B + s0) = sbh[0]; *(uint4*)(p + 2 * TILE_B + s1) = sbh[1];
            *(uint4*)(p + 3 * TILE_B + s0) = sbl[0]; *(uint4*)(p + 3 * TILE_B + s1) = sbl[1];
            __syncthreads();
        }
    }

    // ---- epilogue ----
    const int region = (MODE == 0) ? (nb_glob >> 10) : 3;   // 0 q, 1 k, 2 v, 3 out
    const int nloc = nb_glob & 1023;
    const float* bias = (MODE == 1) ? bo : ((region == 0) ? bq : ((region == 1) ? bk : bv));

    const int trow = lane >> 2;
    const int tcol = (lane & 3) * 2;

    if (region <= 1) {
        __syncthreads();
        unsigned char* Sb = (unsigned char*)smem;
#pragma unroll
        for (int mi = 0; mi < 4; ++mi)
#pragma unroll
            for (int ni = 0; ni < 4; ++ni)
#pragma unroll
                for (int ci = 0; ci < 4; ++ci) {
                    int gr = mrow0 + mi * 16 + trow + ((ci >> 1) ? 8 : 0);
                    int gc = ncol0 + ni * 8 + tcol + (ci & 1);
                    float v = acc[mi][ni][ci] + bias[nloc + gc];
                    Sb[gr * 128 + gc] = (unsigned char)(v >= 1.0f ? 1 : 0);
                }
        __syncthreads();
        int row = tid >> 1, half = tid & 1;
        const unsigned long long* pp = (const unsigned long long*)(Sb + row * 128 + half * 64);
        unsigned long long mask = 0;
#pragma unroll
        for (int w = 0; w < 8; ++w)
            mask |= (((pp[w] & 0x0101010101010101ULL) * 0x0102040810204080ULL) >> 56)
                    << (8 * w);
        unsigned long long* dst = (region == 0) ? g_qm : g_km;
        int h0 = nloc >> 6;
        dst[(size_t)(m0 + row) * HEADS + h0 + half] = mask;
    } else if (MODE == 0) {
        // v region: split-store bf16 hi/lo
#pragma unroll
        for (int mi = 0; mi < 4; ++mi)
#pragma unroll
            for (int ni = 0; ni < 4; ++ni)
#pragma unroll
                for (int ci = 0; ci < 4; ci += 2) {
                    int gr = m0 + mrow0 + mi * 16 + trow + (ci ? 8 : 0);
                    int gc = ncol0 + ni * 8 + tcol;
                    int col = nloc + gc;
                    float o0 = acc[mi][ni][ci] + bias[col];
                    float o1 = acc[mi][ni][ci + 1] + bias[col + 1];
                    __nv_bfloat16 h0 = __float2bfloat16_rn(o0);
                    __nv_bfloat16 h1 = __float2bfloat16_rn(o1);
                    __nv_bfloat162 hh; hh.x = h0; hh.y = h1;
                    __nv_bfloat162 ll;
                    ll.x = __float2bfloat16_rn(o0 - __bfloat162float(h0));
                    ll.y = __float2bfloat16_rn(o1 - __bfloat162float(h1));
                    *(__nv_bfloat162*)(g_vh + (size_t)gr * EMBED + col) = hh;
                    *(__nv_bfloat162*)(g_vl + (size_t)gr * EMBED + col) = ll;
                }
    } else {
#pragma unroll
        for (int mi = 0; mi < 4; ++mi)
#pragma unroll
            for (int ni = 0; ni < 4; ++ni)
#pragma unroll
                for (int ci = 0; ci < 4; ci += 2) {
                    int gr = m0 + mrow0 + mi * 16 + trow + (ci ? 8 : 0);
                    int gc = ncol0 + ni * 8 + tcol;
                    int col = nb_glob + gc;
                    float2 o;
                    o.x = acc[mi][ni][ci] + bias[col];
                    o.y = acc[mi][ni][ci + 1] + bias[col + 1];
                    *(float2*)(outf + (size_t)gr * EMBED + col) = o;
                }
    }
}

// -------------------- attention: popcount scores + exp + tensor-core AV --------------------
// block 128 threads (4 warps), tile 64 q x 64 d (one head). 32 k-tiles of 64.
#define PST 72     // padded bf16 row stride (144 B = 9 x 16B -> conflict-free ldmatrix)

__global__ __launch_bounds__(128) void attn_kernel() {
    __shared__ __nv_bfloat16 Ph[64 * PST], Pl[64 * PST];   // P^T: [k][q]
    __shared__ __nv_bfloat16 Vh[64 * PST], Vl[64 * PST];   // V:   [k][d]
    __shared__ unsigned long long qm_s[64], km_s[64];
    __shared__ float ssum[2][64];

    const int tid = threadIdx.x;
    const int lane = tid & 31, wid = tid >> 5;
    const int qt = blockIdx.x;
    const int bh = blockIdx.y;
    const int b = bh >> 4, h = bh & 15;
    const int q0 = qt * 64;
    const size_t mbase = (size_t)b * TSEQ;

    if (tid < 64) qm_s[tid] = g_qm[(mbase + q0 + tid) * HEADS + h];

    const int qa = tid & 63, kg = tid >> 6;   // phase A: thread -> (q col, k half)

    const uint32_t sPh = smem_u32(Ph), sPl = smem_u32(Pl);
    const uint32_t sVh = smem_u32(Vh), sVl = smem_u32(Vl);

    // ldmatrix.x4.trans lane addressing
    // A (from P^T [k][q]): groups (k0-7,q0),(k0-7,q8),(k8-15,q0),(k8-15,q8)
    const int aRow = (lane & 7) + ((lane >> 4) << 3);      // + kc*16
    const int aCol = wid * 16 + ((lane >> 3) & 1) * 8;
    // B (from V [k][d]): groups (k0-7,n0),(k8-15,n0),(k0-7,n8),(k8-15,n8)
    const int bRow = (lane & 7) + ((lane >> 3) & 1) * 8;   // + kc*16
    const int bColOff = ((lane >> 4) & 1) * 8;             // + nt*16

    float acc[8][4];
#pragma unroll
    for (int i = 0; i < 8; i++)
#pragma unroll
        for (int j = 0; j < 4; j++) acc[i][j] = 0.0f;
    float rsum = 0.0f;

    const __nv_bfloat16* vhb = g_vh + mbase * EMBED + h * HDIM;
    const __nv_bfloat16* vlb = g_vl + mbase * EMBED + h * HDIM;

    for (int kt = 0; kt < 32; ++kt) {
        __syncthreads();   // previous phase B done with Ph/Vh/km
        if (tid < 64) km_s[tid] = g_km[(mbase + kt * 64 + tid) * HEADS + h];
        __syncthreads();   // km visible
        // phase A: weights -> Ph/Pl; V tile loads interleaved (latency hidden by exp)
#pragma unroll
        for (int j = 0; j < 4; ++j) {
            int gi = tid + j * 128;
            int r = gi >> 3, cb = gi & 7;
            uint32_t soff = (uint32_t)(r * PST + cb * 8) * 2;
            size_t goff = (size_t)(kt * 64 + r) * EMBED + cb * 8;
            *(uint4*)((char*)Vh + soff) = *(const uint4*)(vhb + goff);
            *(uint4*)((char*)Vl + soff) = *(const uint4*)(vlb + goff);
        }
        {
            unsigned long long q64 = qm_s[qa];
#pragma unroll
            for (int i = 0; i < 32; ++i) {
                int k = kg * 32 + i;
                int s = __popcll(q64 & km_s[k]);
                float w = exp2f((float)s * 0.18033688011112042f);
                __nv_bfloat16 whh = __float2bfloat16_rn(w);
                Ph[k * PST + qa] = whh;
                Pl[k * PST + qa] = __float2bfloat16_rn(w - __bfloat162float(whh));
                rsum += w;
            }
        }
        __syncthreads();   // Ph/Pl/V visible
        // phase B: acc[16q x 64d per warp] += P^T^T @ V  (3 split passes)
        uint32_t aH[4][4], aL[4][4];
#pragma unroll
        for (int kc = 0; kc < 4; ++kc) {
            uint32_t off = (uint32_t)((kc * 16 + aRow) * PST + aCol) * 2;
            ldsm_x4t(aH[kc][0], aH[kc][1], aH[kc][2], aH[kc][3], sPh + off);
            ldsm_x4t(aL[kc][0], aL[kc][1], aL[kc][2], aL[kc][3], sPl + off);
        }
#pragma unroll
        for (int nt = 0; nt < 4; ++nt) {
            uint32_t bH[4][4], bL[4][4];
#pragma unroll
            for (int kc = 0; kc < 4; ++kc) {
                uint32_t off = (uint32_t)((kc * 16 + bRow) * PST + nt * 16 + bColOff) * 2;
                ldsm_x4t(bH[kc][0], bH[kc][1], bH[kc][2], bH[kc][3], sVh + off);
                ldsm_x4t(bL[kc][0], bL[kc][1], bL[kc][2], bL[kc][3], sVl + off);
            }
#pragma unroll
            for (int kc = 0; kc < 4; ++kc) {
                mma16816(acc[nt * 2 + 0], aH[kc], &bH[kc][0]);
                mma16816(acc[nt * 2 + 1], aH[kc], &bH[kc][2]);
                mma16816(acc[nt * 2 + 0], aH[kc], &bL[kc][0]);
                mma16816(acc[nt * 2 + 1], aH[kc], &bL[kc][2]);
                mma16816(acc[nt * 2 + 0], aL[kc], &bH[kc][0]);
                mma16816(acc[nt * 2 + 1], aL[kc], &bH[kc][2]);
            }
        }
    }

    ssum[kg][qa] = rsum;
    __syncthreads();

    // epilogue: normalize, split-store ctx hi/lo
    const int r0 = wid * 16 + (lane >> 2);
    const int r1 = r0 + 8;
    const float inv0 = 1.0f / (ssum[0][r0] + ssum[1][r0]);
    const float inv1 = 1.0f / (ssum[0][r1] + ssum[1][r1]);
    const size_t row0 = (mbase + q0 + r0) * EMBED + h * HDIM;
    const size_t row1 = (mbase + q0 + r1) * EMBED + h * HDIM;
#pragma unroll
    for (int nt = 0; nt < 8; ++nt) {
        int col = nt * 8 + (lane & 3) * 2;
        float o0 = acc[nt][0] * inv0, o1 = acc[nt][1] * inv0;
        float o2 = acc[nt][2] * inv1, o3 = acc[nt][3] * inv1;
        __nv_bfloat16 h0 = __float2bfloat16_rn(o0), h1 = __float2bfloat16_rn(o1);
        __nv_bfloat16 h2 = __float2bfloat16_rn(o2), h3 = __float2bfloat16_rn(o3);
        __nv_bfloat162 hh0; hh0.x = h0; hh0.y = h1;
        __nv_bfloat162 hh1; hh1.x = h2; hh1.y = h3;
        __nv_bfloat162 ll0, ll1;
        ll0.x = __float2bfloat16_rn(o0 - __bfloat162float(h0));
        ll0.y = __float2bfloat16_rn(o1 - __bfloat162float(h1));
        ll1.x = __float2bfloat16_rn(o2 - __bfloat162float(h2));
        ll1.y = __float2bfloat16_rn(o3 - __bfloat162float(h3));
        *(__nv_bfloat162*)(g_ch + row0 + col) = hh0;
        *(__nv_bfloat162*)(g_cl + row0 + col) = ll0;
        *(__nv_bfloat162*)(g_ch + row1 + col) = hh1;
        *(__nv_bfloat162*)(g_cl + row1 + col) = ll1;
    }
}

// -------------------- launch --------------------
extern "C" void kernel_launch(void* const* d_in, const int* in_sizes, int n_in,
                              void* d_out, int out_size) {
    const float* x  = (const float*)d_in[0];
    const float* Wq = (const float*)d_in[1];
    const float* bq = (const float*)d_in[2];
    const float* Wk = (const float*)d_in[3];
    const float* bk = (const float*)d_in[4];
    const float* Wv = (const float*)d_in[5];
    const float* bv = (const float*)d_in[6];
    const float* Wo = (const float*)d_in[7];
    const float* bo = (const float*)d_in[8];
    float* out = (float*)d_out;

    const int SMEM_MMA = 2 * BUF_B;
    cudaFuncSetAttribute(mma_gemm_kernel<0>, cudaFuncAttributeMaxDynamicSharedMemorySize, SMEM_MMA);
    cudaFuncSetAttribute(mma_gemm_kernel<1>, cudaFuncAttributeMaxDynamicSharedMemorySize, SMEM_MMA);

    convert_x_kernel<<<4096, 256>>>(x);
    convert_w_kernel<<<4096, 256>>>(Wq, Wk, Wv, Wo);
    mma_gemm_kernel<0><<<dim3(32, 24), 256, SMEM_MMA>>>(bq, bk, bv, bo, nullptr);
    attn_kernel<<<dim3(32, 32), 128>>>();
    mma_gemm_kernel<1><<<dim3(32, 8), 256, SMEM_MMA>>>(bq, bk, bv, bo, out);
}

// round 6
// speedup vs baseline: 1.7093x; 1.0048x over previous
#include <cuda_runtime.h>
#include <cuda_bf16.h>
#include <cstdint>

// Problem constants
#define EMBED 1024
#define HEADS 16
#define HDIM  64
#define BATCH 2
#define TSEQ  2048
#define MTOT  4096   // BATCH*TSEQ

// -------------------- device scratch --------------------
__device__ unsigned long long g_qm[MTOT * HEADS];
__device__ unsigned long long g_km[MTOT * HEADS];
__device__ __nv_bfloat16 g_vh[MTOT * EMBED];   // v projection split hi/lo
__device__ __nv_bfloat16 g_vl[MTOT * EMBED];
__device__ __nv_bfloat16 g_xh[MTOT * EMBED];
__device__ __nv_bfloat16 g_xl[MTOT * EMBED];
__device__ __nv_bfloat16 g_wh[4096 * EMBED];   // Wq|Wk|Wv|Wo rows
__device__ __nv_bfloat16 g_wl[4096 * EMBED];
__device__ __nv_bfloat16 g_ch[MTOT * EMBED];   // ctx split hi/lo (written by attn)
__device__ __nv_bfloat16 g_cl[MTOT * EMBED];

// -------------------- helpers --------------------
__device__ __forceinline__ uint32_t smem_u32(const void* p) {
    uint32_t a;
    asm("{ .reg .u64 t; cvta.to.shared.u64 t, %1; cvt.u32.u64 %0, t; }" : "=r"(a) : "l"(p));
    return a;
}
__device__ __forceinline__ void ldsm_x4(uint32_t& r0, uint32_t& r1, uint32_t& r2,
                                        uint32_t& r3, uint32_t addr) {
    asm volatile("ldmatrix.sync.aligned.m8n8.x4.shared.b16 {%0,%1,%2,%3}, [%4];"
                 : "=r"(r0), "=r"(r1), "=r"(r2), "=r"(r3) : "r"(addr));
}
__device__ __forceinline__ void ldsm_x4t(uint32_t& r0, uint32_t& r1, uint32_t& r2,
                                         uint32_t& r3, uint32_t addr) {
    asm volatile("ldmatrix.sync.aligned.m8n8.x4.trans.shared.b16 {%0,%1,%2,%3}, [%4];"
                 : "=r"(r0), "=r"(r1), "=r"(r2), "=r"(r3) : "r"(addr));
}
__device__ __forceinline__ void mma16816(float* d, const uint32_t* a, const uint32_t* b) {
    asm volatile(
        "mma.sync.aligned.m16n8k16.row.col.f32.bf16.bf16.f32 "
        "{%0,%1,%2,%3}, {%4,%5,%6,%7}, {%8,%9}, {%0,%1,%2,%3};"
        : "+f"(d[0]), "+f"(d[1]), "+f"(d[2]), "+f"(d[3])
        : "r"(a[0]), "r"(a[1]), "r"(a[2]), "r"(a[3]), "r"(b[0]), "r"(b[1]));
}

// -------------------- convert kernels: fp32 -> bf16 hi/lo split --------------------
__device__ __forceinline__ void split_store(float v, __nv_bfloat16* ph, __nv_bfloat16* pl) {
    __nv_bfloat16 h = __float2bfloat16_rn(v);
    float r = v - __bfloat162float(h);
    *ph = h;
    *pl = __float2bfloat16_rn(r);
}

__global__ __launch_bounds__(256) void convert_x_kernel(const float* __restrict__ x) {
    int i = (blockIdx.x * 256 + threadIdx.x) * 4;
    float4 v = *(const float4*)(x + i);
    split_store(v.x, g_xh + i, g_xl + i);
    split_store(v.y, g_xh + i + 1, g_xl + i + 1);
    split_store(v.z, g_xh + i + 2, g_xl + i + 2);
    split_store(v.w, g_xh + i + 3, g_xl + i + 3);
}

__global__ __launch_bounds__(256) void convert_w_kernel(
    const float* __restrict__ Wq, const float* __restrict__ Wk,
    const float* __restrict__ Wv, const float* __restrict__ Wo) {
    int i = (blockIdx.x * 256 + threadIdx.x) * 4;
    int row = i >> 10, col = i & 1023;
    const float* src;
    if (row < 1024)      src = Wq + (size_t)row * EMBED + col;
    else if (row < 2048) src = Wk + (size_t)(row - 1024) * EMBED + col;
    else if (row < 3072) src = Wv + (size_t)(row - 2048) * EMBED + col;
    else                 src = Wo + (size_t)(row - 3072) * EMBED + col;
    float4 v = *(const float4*)src;
    split_store(v.x, g_wh + i, g_wl + i);
    split_store(v.y, g_wh + i + 1, g_wl + i + 1);
    split_store(v.z, g_wh + i + 2, g_wl + i + 2);
    split_store(v.w, g_wh + i + 3, g_wl + i + 3);
}

// -------------------- mma.sync GEMM --------------------
// C[128,128] = A[128,1024] * W_rows[128,1024]^T via split-bf16 (3 accumulating passes)
// MODE 0: A = x, W rows 0..3071 (Wq|Wk|Wv). grid (32, 24).
// MODE 1: A = ctx (g_ch/g_cl), W rows 3072..4095 (Wo). grid (32, 8).
#define KC 32
#define TPAD 40
#define TILE_B (128 * TPAD * 2)
#define BUF_B (4 * TILE_B)

template <int MODE>
__global__ __launch_bounds__(256, 1) void mma_gemm_kernel(
    const float* __restrict__ bq, const float* __restrict__ bk,
    const float* __restrict__ bv, const float* __restrict__ bo,
    float* __restrict__ outf)
{
    extern __shared__ char smem[];
    const int tid = threadIdx.x;
    const int wid = tid >> 5, lane = tid & 31;
    const int m0 = blockIdx.x * 128;
    const int nb_glob = blockIdx.y * 128;

    const __nv_bfloat16* Ah = (MODE == 0) ? g_xh : g_ch;
    const __nv_bfloat16* Al = (MODE == 0) ? g_xl : g_cl;
    const int wrow0 = (MODE == 0) ? nb_glob : (3072 + nb_glob);
    const __nv_bfloat16* Bh = g_wh + (size_t)wrow0 * EMBED;
    const __nv_bfloat16* Bl = g_wl + (size_t)wrow0 * EMBED;
    const __nv_bfloat16* Aoff = Ah + (size_t)m0 * EMBED;
    const __nv_bfloat16* ALoff = Al + (size_t)m0 * EMBED;

    const int wm = wid >> 2, wn = wid & 3;
    const int mrow0 = wm * 64, ncol0 = wn * 32;

    const int aRow = lane & 15, aCol = (lane >> 4) * 8;
    const int bRow = ((lane >> 4) & 1) * 8 + (lane & 7);
    const int bCol = ((lane >> 3) & 1) * 8;

    float acc[4][4][4];
#pragma unroll
    for (int i = 0; i < 4; i++)
#pragma unroll
        for (int j = 0; j < 4; j++)
#pragma unroll
            for (int r = 0; r < 4; r++) acc[i][j][r] = 0.0f;

    const int lr0 = tid >> 2, lg0 = (tid & 3);
    const int lr1 = (tid + 256) >> 2, lg1 = ((tid + 256) & 3);

    const uint32_t sb = smem_u32(smem);

    uint4 sa[2], sal[2], sbh[2], sbl[2];
    {
        size_t o0 = (size_t)lr0 * EMBED + lg0 * 8;
        size_t o1 = (size_t)lr1 * EMBED + lg1 * 8;
        sa[0] = *(const uint4*)(Aoff + o0);  sa[1] = *(const uint4*)(Aoff + o1);
        sal[0] = *(const uint4*)(ALoff + o0); sal[1] = *(const uint4*)(ALoff + o1);
        sbh[0] = *(const uint4*)(Bh + o0);   sbh[1] = *(const uint4*)(Bh + o1);
        sbl[0] = *(const uint4*)(Bl + o0);   sbl[1] = *(const uint4*)(Bl + o1);
        char* p = smem;
        uint32_t s0 = (uint32_t)(lr0 * TPAD + lg0 * 8) * 2;
        uint32_t s1 = (uint32_t)(lr1 * TPAD + lg1 * 8) * 2;
        *(uint4*)(p + 0 * TILE_B + s0) = sa[0];  *(uint4*)(p + 0 * TILE_B + s1) = sa[1];
        *(uint4*)(p + 1 * TILE_B + s0) = sal[0]; *(uint4*)(p + 1 * TILE_B + s1) = sal[1];
        *(uint4*)(p + 2 * TILE_B + s0) = sbh[0]; *(uint4*)(p + 2 * TILE_B + s1) = sbh[1];
        *(uint4*)(p + 3 * TILE_B + s0) = sbl[0]; *(uint4*)(p + 3 * TILE_B + s1) = sbl[1];
    }
    __syncthreads();

    for (int c = 0; c < 32; ++c) {
        const int buf = c & 1;
        if (c < 31) {
            const int kc = (c + 1) * KC;
            size_t o0 = (size_t)lr0 * EMBED + kc + lg0 * 8;
            size_t o1 = (size_t)lr1 * EMBED + kc + lg1 * 8;
            sa[0] = *(const uint4*)(Aoff + o0);  sa[1] = *(const uint4*)(Aoff + o1);
            sal[0] = *(const uint4*)(ALoff + o0); sal[1] = *(const uint4*)(ALoff + o1);
            sbh[0] = *(const uint4*)(Bh + o0);   sbh[1] = *(const uint4*)(Bh + o1);
            sbl[0] = *(const uint4*)(Bl + o0);   sbl[1] = *(const uint4*)(Bl + o1);
        }
        const uint32_t pAh = sb + buf * BUF_B + 0 * TILE_B;
        const uint32_t pAl = sb + buf * BUF_B + 1 * TILE_B;
        const uint32_t pBh = sb + buf * BUF_B + 2 * TILE_B;
        const uint32_t pBl = sb + buf * BUF_B + 3 * TILE_B;
#pragma unroll
        for (int kk = 0; kk < KC; kk += 16) {
            uint32_t aF[2][4][4], bF[2][4][2];
#pragma unroll
            for (int mi = 0; mi < 4; ++mi) {
                uint32_t off = (uint32_t)((mrow0 + mi * 16 + aRow) * TPAD + kk + aCol) * 2;
                ldsm_x4(aF[0][mi][0], aF[0][mi][1], aF[0][mi][2], aF[0][mi][3], pAh + off);
                ldsm_x4(aF[1][mi][0], aF[1][mi][1], aF[1][mi][2], aF[1][mi][3], pAl + off);
            }
#pragma unroll
            for (int n2 = 0; n2 < 2; ++n2) {
                uint32_t off = (uint32_t)((ncol0 + n2 * 16 + bRow) * TPAD + kk + bCol) * 2;
                ldsm_x4(bF[0][n2 * 2][0], bF[0][n2 * 2][1],
                        bF[0][n2 * 2 + 1][0], bF[0][n2 * 2 + 1][1], pBh + off);
                ldsm_x4(bF[1][n2 * 2][0], bF[1][n2 * 2][1],
                        bF[1][n2 * 2 + 1][0], bF[1][n2 * 2 + 1][1], pBl + off);
            }
#pragma unroll
            for (int mi = 0; mi < 4; ++mi)
#pragma unroll
                for (int ni = 0; ni < 4; ++ni) mma16816(acc[mi][ni], aF[0][mi], bF[0][ni]);
#pragma unroll
            for (int mi = 0; mi < 4; ++mi)
#pragma unroll
                for (int ni = 0; ni < 4; ++ni) mma16816(acc[mi][ni], aF[0][mi], bF[1][ni]);
#pragma unroll
            for (int mi = 0; mi < 4; ++mi)
#pragma unroll
                for (int ni = 0; ni < 4; ++ni) mma16816(acc[mi][ni], aF[1][mi], bF[0][ni]);
        }
        if (c < 31) {
            char* p = smem + ((c + 1) & 1) * BUF_B;
            uint32_t s0 = (uint32_t)(lr0 * TPAD + lg0 * 8) * 2;
            uint32_t s1 = (uint32_t)(lr1 * TPAD + lg1 * 8) * 2;
            *(uint4*)(p + 0 * TILE_B + s0) = sa[0];  *(uint4*)(p + 0 * TILE_B + s1) = sa[1];
            *(uint4*)(p + 1 * TILE_B + s0) = sal[0]; *(uint4*)(p + 1 * TILE_B + s1) = sal[1];
            *(uint4*)(p + 2 * TILE_B + s0) = sbh[0]; *(uint4*)(p + 2 * TILE_B + s1) = sbh[1];
            *(uint4*)(p + 3 * TILE_B + s0) = sbl[0]; *(uint4*)(p + 3 * TILE_B + s1) = sbl[1];
            __syncthreads();
        }
    }

    // ---- epilogue ----
    const int region = (MODE == 0) ? (nb_glob >> 10) : 3;   // 0 q, 1 k, 2 v, 3 out
    const int nloc = nb_glob & 1023;
    const float* bias = (MODE == 1) ? bo : ((region == 0) ? bq : ((region == 1) ? bk : bv));

    const int trow = lane >> 2;
    const int tcol = (lane & 3) * 2;

    if (region <= 1) {
        __syncthreads();
        unsigned char* Sb = (unsigned char*)smem;
#pragma unroll
        for (int mi = 0; mi < 4; ++mi)
#pragma unroll
            for (int ni = 0; ni < 4; ++ni)
#pragma unroll
                for (int ci = 0; ci < 4; ++ci) {
                    int gr = mrow0 + mi * 16 + trow + ((ci >> 1) ? 8 : 0);
                    int gc = ncol0 + ni * 8 + tcol + (ci & 1);
                    float v = acc[mi][ni][ci] + bias[nloc + gc];
                    Sb[gr * 128 + gc] = (unsigned char)(v >= 1.0f ? 1 : 0);
                }
        __syncthreads();
        int row = tid >> 1, half = tid & 1;
        const unsigned long long* pp = (const unsigned long long*)(Sb + row * 128 + half * 64);
        unsigned long long mask = 0;
#pragma unroll
        for (int w = 0; w < 8; ++w)
            mask |= (((pp[w] & 0x0101010101010101ULL) * 0x0102040810204080ULL) >> 56)
                    << (8 * w);
        unsigned long long* dst = (region == 0) ? g_qm : g_km;
        int h0 = nloc >> 6;
        dst[(size_t)(m0 + row) * HEADS + h0 + half] = mask;
    } else if (MODE == 0) {
        // v region: split-store bf16 hi/lo
#pragma unroll
        for (int mi = 0; mi < 4; ++mi)
#pragma unroll
            for (int ni = 0; ni < 4; ++ni)
#pragma unroll
                for (int ci = 0; ci < 4; ci += 2) {
                    int gr = m0 + mrow0 + mi * 16 + trow + (ci ? 8 : 0);
                    int gc = ncol0 + ni * 8 + tcol;
                    int col = nloc + gc;
                    float o0 = acc[mi][ni][ci] + bias[col];
                    float o1 = acc[mi][ni][ci + 1] + bias[col + 1];
                    __nv_bfloat16 h0 = __float2bfloat16_rn(o0);
                    __nv_bfloat16 h1 = __float2bfloat16_rn(o1);
                    __nv_bfloat162 hh; hh.x = h0; hh.y = h1;
                    __nv_bfloat162 ll;
                    ll.x = __float2bfloat16_rn(o0 - __bfloat162float(h0));
                    ll.y = __float2bfloat16_rn(o1 - __bfloat162float(h1));
                    *(__nv_bfloat162*)(g_vh + (size_t)gr * EMBED + col) = hh;
                    *(__nv_bfloat162*)(g_vl + (size_t)gr * EMBED + col) = ll;
                }
    } else {
#pragma unroll
        for (int mi = 0; mi < 4; ++mi)
#pragma unroll
            for (int ni = 0; ni < 4; ++ni)
#pragma unroll
                for (int ci = 0; ci < 4; ci += 2) {
                    int gr = m0 + mrow0 + mi * 16 + trow + (ci ? 8 : 0);
                    int gc = ncol0 + ni * 8 + tcol;
                    int col = nb_glob + gc;
                    float2 o;
                    o.x = acc[mi][ni][ci] + bias[col];
                    o.y = acc[mi][ni][ci + 1] + bias[col + 1];
                    *(float2*)(outf + (size_t)gr * EMBED + col) = o;
                }
    }
}

// -------------------- attention: popcount scores + exp + tensor-core AV --------------------
// block 128 threads (4 warps), tile 64 q x 64 d (one head). 32 k-tiles of 64.
#define PST 72     // padded bf16 row stride (144 B = 9 x 16B -> conflict-free ldmatrix)

__global__ __launch_bounds__(128) void attn_kernel() {
    __shared__ __nv_bfloat16 Ph[64 * PST], Pl[64 * PST];   // P^T: [k][q]
    __shared__ __nv_bfloat16 Vh[64 * PST], Vl[64 * PST];   // V:   [k][d]
    __shared__ unsigned long long qm_s[64], km_s[64];
    __shared__ float ssum[2][64];

    const int tid = threadIdx.x;
    const int lane = tid & 31, wid = tid >> 5;
    const int qt = blockIdx.x;
    const int bh = blockIdx.y;
    const int b = bh >> 4, h = bh & 15;
    const int q0 = qt * 64;
    const size_t mbase = (size_t)b * TSEQ;

    if (tid < 64) qm_s[tid] = g_qm[(mbase + q0 + tid) * HEADS + h];

    const int qa = tid & 63, kg = tid >> 6;   // phase A: thread -> (q col, k half)

    const uint32_t sPh = smem_u32(Ph), sPl = smem_u32(Pl);
    const uint32_t sVh = smem_u32(Vh), sVl = smem_u32(Vl);

    // ldmatrix.x4.trans lane addressing
    // A (from P^T [k][q]): groups (k0-7,q0),(k0-7,q8),(k8-15,q0),(k8-15,q8)
    const int aRow = (lane & 7) + ((lane >> 4) << 3);      // + kc*16
    const int aCol = wid * 16 + ((lane >> 3) & 1) * 8;
    // B (from V [k][d]): groups (k0-7,n0),(k8-15,n0),(k0-7,n8),(k8-15,n8)
    const int bRow = (lane & 7) + ((lane >> 3) & 1) * 8;   // + kc*16
    const int bColOff = ((lane >> 4) & 1) * 8;             // + nt*16

    float acc[8][4];
#pragma unroll
    for (int i = 0; i < 8; i++)
#pragma unroll
        for (int j = 0; j < 4; j++) acc[i][j] = 0.0f;
    float rsum = 0.0f;

    const __nv_bfloat16* vhb = g_vh + mbase * EMBED + h * HDIM;
    const __nv_bfloat16* vlb = g_vl + mbase * EMBED + h * HDIM;

    for (int kt = 0; kt < 32; ++kt) {
        __syncthreads();   // previous phase B done with Ph/Vh/km
        if (tid < 64) km_s[tid] = g_km[(mbase + kt * 64 + tid) * HEADS + h];
        __syncthreads();   // km visible
        // phase A: weights -> Ph/Pl; V tile loads interleaved (latency hidden by exp)
#pragma unroll
        for (int j = 0; j < 4; ++j) {
            int gi = tid + j * 128;
            int r = gi >> 3, cb = gi & 7;
            uint32_t soff = (uint32_t)(r * PST + cb * 8) * 2;
            size_t goff = (size_t)(kt * 64 + r) * EMBED + cb * 8;
            *(uint4*)((char*)Vh + soff) = *(const uint4*)(vhb + goff);
            *(uint4*)((char*)Vl + soff) = *(const uint4*)(vlb + goff);
        }
        {
            unsigned long long q64 = qm_s[qa];
#pragma unroll
            for (int i = 0; i < 32; ++i) {
                int k = kg * 32 + i;
                int s = __popcll(q64 & km_s[k]);
                float w = exp2f((float)s * 0.18033688011112042f);
                __nv_bfloat16 whh = __float2bfloat16_rn(w);
                Ph[k * PST + qa] = whh;
                Pl[k * PST + qa] = __float2bfloat16_rn(w - __bfloat162float(whh));
                rsum += w;
            }
        }
        __syncthreads();   // Ph/Pl/V visible
        // phase B: acc[16q x 64d per warp] += P^T^T @ V  (3 split passes)
        uint32_t aH[4][4], aL[4][4];
#pragma unroll
        for (int kc = 0; kc < 4; ++kc) {
            uint32_t off = (uint32_t)((kc * 16 + aRow) * PST + aCol) * 2;
            ldsm_x4t(aH[kc][0], aH[kc][1], aH[kc][2], aH[kc][3], sPh + off);
            ldsm_x4t(aL[kc][0], aL[kc][1], aL[kc][2], aL[kc][3], sPl + off);
        }
#pragma unroll
        for (int nt = 0; nt < 4; ++nt) {
            uint32_t bH[4][4], bL[4][4];
#pragma unroll
            for (int kc = 0; kc < 4; ++kc) {
                uint32_t off = (uint32_t)((kc * 16 + bRow) * PST + nt * 16 + bColOff) * 2;
                ldsm_x4t(bH[kc][0], bH[kc][1], bH[kc][2], bH[kc][3], sVh + off);
                ldsm_x4t(bL[kc][0], bL[kc][1], bL[kc][2], bL[kc][3], sVl + off);
            }
#pragma unroll
            for (int kc = 0; kc < 4; ++kc) {
                mma16816(acc[nt * 2 + 0], aH[kc], &bH[kc][0]);
                mma16816(acc[nt * 2 + 1], aH[kc], &bH[kc][2]);
                mma16816(acc[nt * 2 + 0], aH[kc], &bL[kc][0]);
                mma16816(acc[nt * 2 + 1], aH[kc], &bL[kc][2]);
                mma16816(acc[nt * 2 + 0], aL[kc], &bH[kc][0]);
                mma16816(acc[nt * 2 + 1], aL[kc], &bH[kc][2]);
            }
        }
    }

    ssum[kg][qa] = rsum;
    __syncthreads();

    // epilogue: normalize, split-store ctx hi/lo
    const int r0 = wid * 16 + (lane >> 2);
    const int r1 = r0 + 8;
    const float inv0 = 1.0f / (ssum[0][r0] + ssum[1][r0]);
    const float inv1 = 1.0f / (ssum[0][r1] + ssum[1][r1]);
    const size_t row0 = (mbase + q0 + r0) * EMBED + h * HDIM;
    const size_t row1 = (mbase + q0 + r1) * EMBED + h * HDIM;
#pragma unroll
    for (int nt = 0; nt < 8; ++nt) {
        int col = nt * 8 + (lane & 3) * 2;
        float o0 = acc[nt][0] * inv0, o1 = acc[nt][1] * inv0;
        float o2 = acc[nt][2] * inv1, o3 = acc[nt][3] * inv1;
        __nv_bfloat16 h0 = __float2bfloat16_rn(o0), h1 = __float2bfloat16_rn(o1);
        __nv_bfloat16 h2 = __float2bfloat16_rn(o2), h3 = __float2bfloat16_rn(o3);
        __nv_bfloat162 hh0; hh0.x = h0; hh0.y = h1;
        __nv_bfloat162 hh1; hh1.x = h2; hh1.y = h3;
        __nv_bfloat162 ll0, ll1;
        ll0.x = __float2bfloat16_rn(o0 - __bfloat162float(h0));
        ll0.y = __float2bfloat16_rn(o1 - __bfloat162float(h1));
        ll1.x = __float2bfloat16_rn(o2 - __bfloat162float(h2));
        ll1.y = __float2bfloat16_rn(o3 - __bfloat162float(h3));
        *(__nv_bfloat162*)(g_ch + row0 + col) = hh0;
        *(__nv_bfloat162*)(g_cl + row0 + col) = ll0;
        *(__nv_bfloat162*)(g_ch + row1 + col) = hh1;
        *(__nv_bfloat162*)(g_cl + row1 + col) = ll1;
    }
}

// -------------------- launch --------------------
extern "C" void kernel_launch(void* const* d_in, const int* in_sizes, int n_in,
                              void* d_out, int out_size) {
    const float* x  = (const float*)d_in[0];
    const float* Wq = (const float*)d_in[1];
    const float* bq = (const float*)d_in[2];
    const float* Wk = (const float*)d_in[3];
    const float* bk = (const float*)d_in[4];
    const float* Wv = (const float*)d_in[5];
    const float* bv = (const float*)d_in[6];
    const float* Wo = (const float*)d_in[7];
    const float* bo = (const float*)d_in[8];
    float* out = (float*)d_out;

    const int SMEM_MMA = 2 * BUF_B;
    cudaFuncSetAttribute(mma_gemm_kernel<0>, cudaFuncAttributeMaxDynamicSharedMemorySize, SMEM_MMA);
    cudaFuncSetAttribute(mma_gemm_kernel<1>, cudaFuncAttributeMaxDynamicSharedMemorySize, SMEM_MMA);

    convert_x_kernel<<<4096, 256>>>(x);
    convert_w_kernel<<<4096, 256>>>(Wq, Wk, Wv, Wo);
    mma_gemm_kernel<0><<<dim3(32, 24), 256, SMEM_MMA>>>(bq, bk, bv, bo, nullptr);
    attn_kernel<<<dim3(32, 32), 128>>>();
    mma_gemm_kernel<1><<<dim3(32, 8), 256, SMEM_MMA>>>(bq, bk, bv, bo, out);
}

// round 8
// speedup vs baseline: 1.8668x; 1.0922x over previous
#include <cuda_runtime.h>
#include <cuda_bf16.h>
#include <cstdint>

// Problem constants
#define EMBED 1024
#define HEADS 16
#define BATCH 2
#define TSEQ  2048
#define MTOT  4096   // BATCH*TSEQ

// -------------------- device scratch --------------------
// masks are stored TRANSPOSED: [head][m] so per-head tiles are contiguous
__device__ unsigned long long g_qm[HEADS * MTOT];
__device__ unsigned long long g_km[HEADS * MTOT];
__device__ __nv_bfloat16 g_vh[MTOT * EMBED];   // v projection split hi/lo
__device__ __nv_bfloat16 g_vl[MTOT * EMBED];
__device__ __nv_bfloat16 g_xh[MTOT * EMBED];
__device__ __nv_bfloat16 g_xl[MTOT * EMBED];
__device__ __nv_bfloat16 g_wh[4096 * EMBED];   // Wq|Wk|Wv|Wo rows
__device__ __nv_bfloat16 g_wl[4096 * EMBED];
__device__ __nv_bfloat16 g_ch[MTOT * EMBED];   // ctx split hi/lo (written by attn)
__device__ __nv_bfloat16 g_cl[MTOT * EMBED];

// -------------------- helpers --------------------
__device__ __forceinline__ uint32_t smem_u32(const void* p) {
    uint32_t a;
    asm("{ .reg .u64 t; cvta.to.shared.u64 t, %1; cvt.u32.u64 %0, t; }" : "=r"(a) : "l"(p));
    return a;
}
__device__ __forceinline__ void ldsm_x4(uint32_t& r0, uint32_t& r1, uint32_t& r2,
                                        uint32_t& r3, uint32_t addr) {
    asm volatile("ldmatrix.sync.aligned.m8n8.x4.shared.b16 {%0,%1,%2,%3}, [%4];"
                 : "=r"(r0), "=r"(r1), "=r"(r2), "=r"(r3) : "r"(addr));
}
__device__ __forceinline__ void ldsm_x4t(uint32_t& r0, uint32_t& r1, uint32_t& r2,
                                         uint32_t& r3, uint32_t addr) {
    asm volatile("ldmatrix.sync.aligned.m8n8.x4.trans.shared.b16 {%0,%1,%2,%3}, [%4];"
                 : "=r"(r0), "=r"(r1), "=r"(r2), "=r"(r3) : "r"(addr));
}
__device__ __forceinline__ void mma16816(float* d, const uint32_t* a, const uint32_t* b) {
    asm volatile(
        "mma.sync.aligned.m16n8k16.row.col.f32.bf16.bf16.f32 "
        "{%0,%1,%2,%3}, {%4,%5,%6,%7}, {%8,%9}, {%0,%1,%2,%3};"
        : "+f"(d[0]), "+f"(d[1]), "+f"(d[2]), "+f"(d[3])
        : "r"(a[0]), "r"(a[1]), "r"(a[2]), "r"(a[3]), "r"(b[0]), "r"(b[1]));
}
__device__ __forceinline__ void cpa16(uint32_t dst, const void* src) {
    asm volatile("cp.async.cg.shared.global [%0], [%1], 16;" :: "r"(dst), "l"(src));
}
#define CP_COMMIT()   asm volatile("cp.async.commit_group;" ::: "memory")
#define CP_WAIT_ALL() asm volatile("cp.async.wait_group 0;" ::: "memory")

__device__ __forceinline__ uint32_t sw128(uint32_t off) {
    return off ^ ((off >> 3) & 0x70);
}

// -------------------- convert kernels: fp32 -> bf16 hi/lo split --------------------
__device__ __forceinline__ void split_store(float v, __nv_bfloat16* ph, __nv_bfloat16* pl) {
    __nv_bfloat16 h = __float2bfloat16_rn(v);
    float r = v - __bfloat162float(h);
    *ph = h;
    *pl = __float2bfloat16_rn(r);
}

__global__ __launch_bounds__(256) void convert_x_kernel(const float* __restrict__ x) {
    int i = (blockIdx.x * 256 + threadIdx.x) * 4;
    float4 v = *(const float4*)(x + i);
    split_store(v.x, g_xh + i, g_xl + i);
    split_store(v.y, g_xh + i + 1, g_xl + i + 1);
    split_store(v.z, g_xh + i + 2, g_xl + i + 2);
    split_store(v.w, g_xh + i + 3, g_xl + i + 3);
}

__global__ __launch_bounds__(256) void convert_w_kernel(
    const float* __restrict__ Wq, const float* __restrict__ Wk,
    const float* __restrict__ Wv, const float* __restrict__ Wo) {
    int i = (blockIdx.x * 256 + threadIdx.x) * 4;
    int row = i >> 10, col = i & 1023;
    const float* src;
    if (row < 1024)      src = Wq + (size_t)row * EMBED + col;
    else if (row < 2048) src = Wk + (size_t)(row - 1024) * EMBED + col;
    else if (row < 3072) src = Wv + (size_t)(row - 2048) * EMBED + col;
    else                 src = Wo + (size_t)(row - 3072) * EMBED + col;
    float4 v = *(const float4*)src;
    split_store(v.x, g_wh + i, g_wl + i);
    split_store(v.y, g_wh + i + 1, g_wl + i + 1);
    split_store(v.z, g_wh + i + 2, g_wl + i + 2);
    split_store(v.w, g_wh + i + 3, g_wl + i + 3);
}

// -------------------- mma.sync GEMM (cp.async pipelined) --------------------
#define KC 32
#define TPAD 40
#define TILE_B (128 * TPAD * 2)   // 10240 B per sub-tile
#define BUF_B (4 * TILE_B)        // AH, AL, BH, BL

#define GEMM_ISSUE(c_, buf_) do {                                              \
    const int kc_ = (c_) * KC;                                                 \
    _Pragma("unroll")                                                          \
    for (int l = 0; l < 8; ++l) {                                              \
        const int st = l >> 1;                                                 \
        const int j = tid + (l & 1) * 256;                                     \
        const int r = j >> 2, g = j & 3;                                       \
        const __nv_bfloat16* src =                                             \
            (st == 0) ? Aoff : ((st == 1) ? ALoff : ((st == 2) ? Bh : Bl));    \
        uint32_t dst = sb + (buf_) * BUF_B + st * TILE_B +                     \
                       (uint32_t)(r * TPAD + g * 8) * 2;                       \
        cpa16(dst, src + (size_t)r * EMBED + kc_ + g * 8);                     \
    }                                                                          \
    CP_COMMIT();                                                               \
} while (0)

// MODE 0: A = x, W rows 0..3071 (Wq|Wk|Wv). grid (32, 24).
// MODE 1: A = ctx (g_ch/g_cl), W rows 3072..4095 (Wo). grid (32, 8).
template <int MODE>
__global__ __launch_bounds__(256, 2) void mma_gemm_kernel(
    const float* __restrict__ bq, const float* __restrict__ bk,
    const float* __restrict__ bv, const float* __restrict__ bo,
    float* __restrict__ outf)
{
    extern __shared__ char smem[];
    const int tid = threadIdx.x;
    const int wid = tid >> 5, lane = tid & 31;
    const int m0 = blockIdx.x * 128;
    const int nb_glob = blockIdx.y * 128;

    const __nv_bfloat16* Ah = (MODE == 0) ? g_xh : g_ch;
    const __nv_bfloat16* Al = (MODE == 0) ? g_xl : g_cl;
    const int wrow0 = (MODE == 0) ? nb_glob : (3072 + nb_glob);
    const __nv_bfloat16* Bh = g_wh + (size_t)wrow0 * EMBED;
    const __nv_bfloat16* Bl = g_wl + (size_t)wrow0 * EMBED;
    const __nv_bfloat16* Aoff = Ah + (size_t)m0 * EMBED;
    const __nv_bfloat16* ALoff = Al + (size_t)m0 * EMBED;

    const int wm = wid >> 2, wn = wid & 3;
    const int mrow0 = wm * 64, ncol0 = wn * 32;

    const int aRow = lane & 15, aCol = (lane >> 4) * 8;
    const int bRow = ((lane >> 4) & 1) * 8 + (lane & 7);
    const int bCol = ((lane >> 3) & 1) * 8;

    float acc[4][4][4];
#pragma unroll
    for (int i = 0; i < 4; i++)
#pragma unroll
        for (int j = 0; j < 4; j++)
#pragma unroll
            for (int r = 0; r < 4; r++) acc[i][j][r] = 0.0f;

    const uint32_t sb = smem_u32(smem);

    GEMM_ISSUE(0, 0);

    for (int c = 0; c < 32; ++c) {
        const int buf = c & 1;
        CP_WAIT_ALL();
        __syncthreads();
        if (c < 31) GEMM_ISSUE(c + 1, buf ^ 1);

        const uint32_t pAh = sb + buf * BUF_B + 0 * TILE_B;
        const uint32_t pAl = sb + buf * BUF_B + 1 * TILE_B;
        const uint32_t pBh = sb + buf * BUF_B + 2 * TILE_B;
        const uint32_t pBl = sb + buf * BUF_B + 3 * TILE_B;
#pragma unroll
        for (int kk = 0; kk < KC; kk += 16) {
            uint32_t aF[2][4][4], bF[2][4][2];
#pragma unroll
            for (int mi = 0; mi < 4; ++mi) {
                uint32_t off = (uint32_t)((mrow0 + mi * 16 + aRow) * TPAD + kk + aCol) * 2;
                ldsm_x4(aF[0][mi][0], aF[0][mi][1], aF[0][mi][2], aF[0][mi][3], pAh + off);
                ldsm_x4(aF[1][mi][0], aF[1][mi][1], aF[1][mi][2], aF[1][mi][3], pAl + off);
            }
#pragma unroll
            for (int n2 = 0; n2 < 2; ++n2) {
                uint32_t off = (uint32_t)((ncol0 + n2 * 16 + bRow) * TPAD + kk + bCol) * 2;
                ldsm_x4(bF[0][n2 * 2][0], bF[0][n2 * 2][1],
                        bF[0][n2 * 2 + 1][0], bF[0][n2 * 2 + 1][1], pBh + off);
                ldsm_x4(bF[1][n2 * 2][0], bF[1][n2 * 2][1],
                        bF[1][n2 * 2 + 1][0], bF[1][n2 * 2 + 1][1], pBl + off);
            }
#pragma unroll
            for (int mi = 0; mi < 4; ++mi)
#pragma unroll
                for (int ni = 0; ni < 4; ++ni) mma16816(acc[mi][ni], aF[0][mi], bF[0][ni]);
#pragma unroll
            for (int mi = 0; mi < 4; ++mi)
#pragma unroll
                for (int ni = 0; ni < 4; ++ni) mma16816(acc[mi][ni], aF[0][mi], bF[1][ni]);
#pragma unroll
            for (int mi = 0; mi < 4; ++mi)
#pragma unroll
                for (int ni = 0; ni < 4; ++ni) mma16816(acc[mi][ni], aF[1][mi], bF[0][ni]);
        }
    }

    // ---- epilogue ----
    const int region = (MODE == 0) ? (nb_glob >> 10) : 3;   // 0 q, 1 k, 2 v, 3 out
    const int nloc = nb_glob & 1023;
    const float* bias = (MODE == 1) ? bo : ((region == 0) ? bq : ((region == 1) ? bk : bv));

    const int trow = lane >> 2;
    const int tcol = (lane & 3) * 2;

    if (region <= 1) {
        __syncthreads();
        unsigned char* Sb = (unsigned char*)smem;
#pragma unroll
        for (int mi = 0; mi < 4; ++mi)
#pragma unroll
            for (int ni = 0; ni < 4; ++ni)
#pragma unroll
                for (int ci = 0; ci < 4; ++ci) {
                    int gr = mrow0 + mi * 16 + trow + ((ci >> 1) ? 8 : 0);
                    int gc = ncol0 + ni * 8 + tcol + (ci & 1);
                    float v = acc[mi][ni][ci] + bias[nloc + gc];
                    Sb[gr * 128 + gc] = (unsigned char)(v >= 1.0f ? 1 : 0);
                }
        __syncthreads();
        int row = tid >> 1, half = tid & 1;
        const unsigned long long* pp = (const unsigned long long*)(Sb + row * 128 + half * 64);
        unsigned long long mask = 0;
#pragma unroll
        for (int w = 0; w < 8; ++w)
            mask |= (((pp[w] & 0x0101010101010101ULL) * 0x0102040810204080ULL) >> 56)
                    << (8 * w);
        unsigned long long* dst = (region == 0) ? g_qm : g_km;
        int h0 = nloc >> 6;
        dst[(size_t)(h0 + half) * MTOT + m0 + row] = mask;   // transposed layout
    } else if (MODE == 0) {
#pragma unroll
        for (int mi = 0; mi < 4; ++mi)
#pragma unroll
            for (int ni = 0; ni < 4; ++ni)
#pragma unroll
                for (int ci = 0; ci < 4; ci += 2) {
                    int gr = m0 + mrow0 + mi * 16 + trow + (ci ? 8 : 0);
                    int gc = ncol0 + ni * 8 + tcol;
                    int col = nloc + gc;
                    float o0 = acc[mi][ni][ci] + bias[col];
                    float o1 = acc[mi][ni][ci + 1] + bias[col + 1];
                    __nv_bfloat16 h0 = __float2bfloat16_rn(o0);
                    __nv_bfloat16 h1 = __float2bfloat16_rn(o1);
                    __nv_bfloat162 hh; hh.x = h0; hh.y = h1;
                    __nv_bfloat162 ll;
                    ll.x = __float2bfloat16_rn(o0 - __bfloat162float(h0));
                    ll.y = __float2bfloat16_rn(o1 - __bfloat162float(h1));
                    *(__nv_bfloat162*)(g_vh + (size_t)gr * EMBED + col) = hh;
                    *(__nv_bfloat162*)(g_vl + (size_t)gr * EMBED + col) = ll;
                }
    } else {
#pragma unroll
        for (int mi = 0; mi < 4; ++mi)
#pragma unroll
            for (int ni = 0; ni < 4; ++ni)
#pragma unroll
                for (int ci = 0; ci < 4; ci += 2) {
                    int gr = m0 + mrow0 + mi * 16 + trow + (ci ? 8 : 0);
                    int gc = ncol0 + ni * 8 + tcol;
                    int col = nb_glob + gc;
                    float2 o;
                    o.x = acc[mi][ni][ci] + bias[col];
                    o.y = acc[mi][ni][ci + 1] + bias[col + 1];
                    *(float2*)(outf + (size_t)gr * EMBED + col) = o;
                }
    }
}

// -------------------- attention: cp.async pipelined, SW128 smem --------------------
// block 128 threads (4 warps), tile 64 q x 64 d (one head). 32 k-tiles of 64.
// dynamic smem layout (bytes):
#define A_PH 0
#define A_PL 8192
#define A_VH 16384       // [2] x 8192
#define A_VL 32768       // [2] x 8192
#define A_KM 49152       // [2] x 512
#define A_SS 50176       // float[2][64]
#define A_TOTAL 50688

#define ATTN_ISSUE(t_, buf_) do {                                              \
    _Pragma("unroll")                                                          \
    for (int j = 0; j < 4; ++j) {                                              \
        int gi = tid + j * 128;                                                \
        int r = gi >> 3, cb = gi & 7;                                          \
        uint32_t off = sw128((uint32_t)(r * 128 + cb * 16));                   \
        size_t goff = (size_t)((t_) * 64 + r) * EMBED + cb * 8;                \
        cpa16(sb + A_VH + (buf_) * 8192 + off, vhb + goff);                    \
        cpa16(sb + A_VL + (buf_) * 8192 + off, vlb + goff);                    \
    }                                                                          \
    if (tid < 32) cpa16(sb + A_KM + (buf_) * 512 + tid * 16,                   \
                        kmb + (size_t)(t_) * 64 + tid * 2);                    \
    CP_COMMIT();                                                               \
} while (0)

__global__ __launch_bounds__(128) void attn_kernel() {
    extern __shared__ char smem[];
    const uint32_t sb = smem_u32(smem);
    const int tid = threadIdx.x;
    const int lane = tid & 31, wid = tid >> 5;
    const int qt = blockIdx.x;
    const int bh = blockIdx.y;
    const int b = bh >> 4, h = bh & 15;
    const int q0 = qt * 64;
    const size_t mbase = (size_t)b * TSEQ;

    const int qa = tid & 63, kg = tid >> 6;
    const unsigned long long qmr = g_qm[(size_t)h * MTOT + mbase + q0 + qa];

    const __nv_bfloat16* vhb = g_vh + mbase * EMBED + h * 64;
    const __nv_bfloat16* vlb = g_vl + mbase * EMBED + h * 64;
    const unsigned long long* kmb = g_km + (size_t)h * MTOT + mbase;

    // ldmatrix.x4.trans lane addressing (byte offsets within row handled below)
    const int aRow = (lane & 7) + ((lane >> 4) << 3);
    const int aColB = (wid * 16 + ((lane >> 3) & 1) * 8) * 2;
    const int bRow = (lane & 7) + ((lane >> 3) & 1) * 8;
    const int bColB = (((lane >> 4) & 1) * 8) * 2;

    float acc[8][4];
#pragma unroll
    for (int i = 0; i < 8; i++)
#pragma unroll
        for (int j = 0; j < 4; j++) acc[i][j] = 0.0f;
    float rsum = 0.0f;

    ATTN_ISSUE(0, 0);

    for (int kt = 0; kt < 32; ++kt) {
        const int buf = kt & 1;
        CP_WAIT_ALL();
        __syncthreads();            // V[kt]/km[kt] visible; all warps done reading P[kt-1]
        if (kt < 31) ATTN_ISSUE(kt + 1, buf ^ 1);

        // phase A: weights -> Ph/Pl (pure compute, no global deps)
        {
            const unsigned long long* kms =
                (const unsigned long long*)(smem + A_KM + buf * 512);
#pragma unroll
            for (int i = 0; i < 32; ++i) {
                int k = kg * 32 + i;
                int s = __popcll(qmr & kms[k]);
                float w = exp2f((float)s * 0.18033688011112042f);
                __nv_bfloat16 whh = __float2bfloat16_rn(w);
                uint32_t off = sw128((uint32_t)(k * 128 + qa * 2));
                *(__nv_bfloat16*)(smem + A_PH + off) = whh;
                *(__nv_bfloat16*)(smem + A_PL + off) =
                    __float2bfloat16_rn(w - __bfloat162float(whh));
                rsum += w;
            }
        }
        __syncthreads();            // P visible

        // phase B: acc[16q x 64d per warp] += P^T^T @ V (3 split passes)
        const uint32_t sPh = sb + A_PH, sPl = sb + A_PL;
        const uint32_t sVh = sb + A_VH + buf * 8192;
        const uint32_t sVl = sb + A_VL + buf * 8192;
        uint32_t aH[4][4], aL[4][4];
#pragma unroll
        for (int kc = 0; kc < 4; ++kc) {
            uint32_t off = sw128((uint32_t)((kc * 16 + aRow) * 128 + aColB));
            ldsm_x4t(aH[kc][0], aH[kc][1], aH[kc][2], aH[kc][3], sPh + off);
            ldsm_x4t(aL[kc][0], aL[kc][1], aL[kc][2], aL[kc][3], sPl + off);
        }
#pragma unroll
        for (int nt = 0; nt < 4; ++nt) {
            uint32_t bH[4][4], bL[4][4];
#pragma unroll
            for (int kc = 0; kc < 4; ++kc) {
                uint32_t off = sw128((uint32_t)((kc * 16 + bRow) * 128 + nt * 32 + bColB));
                ldsm_x4t(bH[kc][0], bH[kc][1], bH[kc][2], bH[kc][3], sVh + off);
                ldsm_x4t(bL[kc][0], bL[kc][1], bL[kc][2], bL[kc][3], sVl + off);
            }
#pragma unroll
            for (int kc = 0; kc < 4; ++kc) {
                mma16816(acc[nt * 2 + 0], aH[kc], &bH[kc][0]);
                mma16816(acc[nt * 2 + 1], aH[kc], &bH[kc][2]);
                mma16816(acc[nt * 2 + 0], aH[kc], &bL[kc][0]);
                mma16816(acc[nt * 2 + 1], aH[kc], &bL[kc][2]);
                mma16816(acc[nt * 2 + 0], aL[kc], &bH[kc][0]);
                mma16816(acc[nt * 2 + 1], aL[kc], &bH[kc][2]);
            }
        }
    }

    float* ss = (float*)(smem + A_SS);
    ss[kg * 64 + qa] = rsum;
    __syncthreads();

    // epilogue: normalize, split-store ctx hi/lo
    const int r0 = wid * 16 + (lane >> 2);
    const int r1 = r0 + 8;
    const float inv0 = 1.0f / (ss[r0] + ss[64 + r0]);
    const float inv1 = 1.0f / (ss[r1] + ss[64 + r1]);
    const size_t row0 = (mbase + q0 + r0) * EMBED + h * 64;
    const size_t row1 = (mbase + q0 + r1) * EMBED + h * 64;
#pragma unroll
    for (int nt = 0; nt < 8; ++nt) {
        int col = nt * 8 + (lane & 3) * 2;
        float o0 = acc[nt][0] * inv0, o1 = acc[nt][1] * inv0;
        float o2 = acc[nt][2] * inv1, o3 = acc[nt][3] * inv1;
        __nv_bfloat16 h0 = __float2bfloat16_rn(o0), h1 = __float2bfloat16_rn(o1);
        __nv_bfloat16 h2 = __float2bfloat16_rn(o2), h3 = __float2bfloat16_rn(o3);
        __nv_bfloat162 hh0; hh0.x = h0; hh0.y = h1;
        __nv_bfloat162 hh1; hh1.x = h2; hh1.y = h3;
        __nv_bfloat162 ll0, ll1;
        ll0.x = __float2bfloat16_rn(o0 - __bfloat162float(h0));
        ll0.y = __float2bfloat16_rn(o1 - __bfloat162float(h1));
        ll1.x = __float2bfloat16_rn(o2 - __bfloat162float(h2));
        ll1.y = __float2bfloat16_rn(o3 - __bfloat162float(h3));
        *(__nv_bfloat162*)(g_ch + row0 + col) = hh0;
        *(__nv_bfloat162*)(g_cl + row0 + col) = ll0;
        *(__nv_bfloat162*)(g_ch + row1 + col) = hh1;
        *(__nv_bfloat162*)(g_cl + row1 + col) = ll1;
    }
}

// -------------------- launch --------------------
extern "C" void kernel_launch(void* const* d_in, const int* in_sizes, int n_in,
                              void* d_out, int out_size) {
    const float* x  = (const float*)d_in[0];
    const float* Wq = (const float*)d_in[1];
    const float* bq = (const float*)d_in[2];
    const float* Wk = (const float*)d_in[3];
    const float* bk = (const float*)d_in[4];
    const float* Wv = (const float*)d_in[5];
    const float* bv = (const float*)d_in[6];
    const float* Wo = (const float*)d_in[7];
    const float* bo = (const float*)d_in[8];
    float* out = (float*)d_out;

    const int SMEM_MMA = 2 * BUF_B;   // 81920
    cudaFuncSetAttribute(mma_gemm_kernel<0>, cudaFuncAttributeMaxDynamicSharedMemorySize, SMEM_MMA);
    cudaFuncSetAttribute(mma_gemm_kernel<1>, cudaFuncAttributeMaxDynamicSharedMemorySize, SMEM_MMA);
    cudaFuncSetAttribute(attn_kernel, cudaFuncAttributeMaxDynamicSharedMemorySize, A_TOTAL);

    convert_x_kernel<<<4096, 256>>>(x);
    convert_w_kernel<<<4096, 256>>>(Wq, Wk, Wv, Wo);
    mma_gemm_kernel<0><<<dim3(32, 24), 256, SMEM_MMA>>>(bq, bk, bv, bo, nullptr);
    attn_kernel<<<dim3(32, 32), 128, A_TOTAL>>>();
    mma_gemm_kernel<1><<<dim3(32, 8), 256, SMEM_MMA>>>(bq, bk, bv, bo, out);
}

// round 10
// speedup vs baseline: 2.6592x; 1.4245x over previous
#include <cuda_runtime.h>
#include <cuda_fp16.h>
#include <cstdint>

// Problem constants
#define EMBED 1024
#define HEADS 16
#define BATCH 2
#define TSEQ  2048
#define MTOT  4096   // BATCH*TSEQ

// -------------------- device scratch --------------------
// masks stored TRANSPOSED: [head][m] so per-head tiles are contiguous
__device__ unsigned long long g_qm[HEADS * MTOT];
__device__ unsigned long long g_km[HEADS * MTOT];
__device__ __half g_vh[MTOT * EMBED];   // v projection split hi/lo (fp16)
__device__ __half g_vl[MTOT * EMBED];
__device__ __half g_xh[MTOT * EMBED];   // x split hi/lo (fp16)
__device__ __half g_xl[MTOT * EMBED];
__device__ __half g_wh[4096 * EMBED];   // Wq|Wk|Wv|Wo rows, single fp16
__device__ __half g_ch[MTOT * EMBED];   // ctx split hi/lo (written by attn)
__device__ __half g_cl[MTOT * EMBED];

// -------------------- helpers --------------------
__device__ __forceinline__ uint32_t smem_u32(const void* p) {
    uint32_t a;
    asm("{ .reg .u64 t; cvta.to.shared.u64 t, %1; cvt.u32.u64 %0, t; }" : "=r"(a) : "l"(p));
    return a;
}
__device__ __forceinline__ void ldsm_x4(uint32_t& r0, uint32_t& r1, uint32_t& r2,
                                        uint32_t& r3, uint32_t addr) {
    asm volatile("ldmatrix.sync.aligned.m8n8.x4.shared.b16 {%0,%1,%2,%3}, [%4];"
                 : "=r"(r0), "=r"(r1), "=r"(r2), "=r"(r3) : "r"(addr));
}
__device__ __forceinline__ void ldsm_x4t(uint32_t& r0, uint32_t& r1, uint32_t& r2,
                                         uint32_t& r3, uint32_t addr) {
    asm volatile("ldmatrix.sync.aligned.m8n8.x4.trans.shared.b16 {%0,%1,%2,%3}, [%4];"
                 : "=r"(r0), "=r"(r1), "=r"(r2), "=r"(r3) : "r"(addr));
}
__device__ __forceinline__ void mma16816h(float* d, const uint32_t* a, const uint32_t* b) {
    asm volatile(
        "mma.sync.aligned.m16n8k16.row.col.f32.f16.f16.f32 "
        "{%0,%1,%2,%3}, {%4,%5,%6,%7}, {%8,%9}, {%0,%1,%2,%3};"
        : "+f"(d[0]), "+f"(d[1]), "+f"(d[2]), "+f"(d[3])
        : "r"(a[0]), "r"(a[1]), "r"(a[2]), "r"(a[3]), "r"(b[0]), "r"(b[1]));
}
__device__ __forceinline__ void cpa16(uint32_t dst, const void* src) {
    asm volatile("cp.async.cg.shared.global [%0], [%1], 16;" :: "r"(dst), "l"(src));
}
#define CP_COMMIT()   asm volatile("cp.async.commit_group;" ::: "memory")
#define CP_WAIT_ALL() asm volatile("cp.async.wait_group 0;" ::: "memory")

__device__ __forceinline__ uint32_t sw128(uint32_t off) {
    return off ^ ((off >> 3) & 0x70);
}

// -------------------- convert kernels: fp32 -> fp16 --------------------
__device__ __forceinline__ void split_store_h(float v, __half* ph, __half* pl) {
    __half h = __float2half_rn(v);
    *ph = h;
    *pl = __float2half_rn(v - __half2float(h));
}

__global__ __launch_bounds__(256) void convert_x_kernel(const float* __restrict__ x) {
    int i = (blockIdx.x * 256 + threadIdx.x) * 4;
    float4 v = *(const float4*)(x + i);
    split_store_h(v.x, g_xh + i, g_xl + i);
    split_store_h(v.y, g_xh + i + 1, g_xl + i + 1);
    split_store_h(v.z, g_xh + i + 2, g_xl + i + 2);
    split_store_h(v.w, g_xh + i + 3, g_xl + i + 3);
}

__global__ __launch_bounds__(256) void convert_w_kernel(
    const float* __restrict__ Wq, const float* __restrict__ Wk,
    const float* __restrict__ Wv, const float* __restrict__ Wo) {
    int i = (blockIdx.x * 256 + threadIdx.x) * 4;
    int row = i >> 10, col = i & 1023;
    const float* src;
    if (row < 1024)      src = Wq + (size_t)row * EMBED + col;
    else if (row < 2048) src = Wk + (size_t)(row - 1024) * EMBED + col;
    else if (row < 3072) src = Wv + (size_t)(row - 2048) * EMBED + col;
    else                 src = Wo + (size_t)(row - 3072) * EMBED + col;
    float4 v = *(const float4*)src;
    g_wh[i]     = __float2half_rn(v.x);
    g_wh[i + 1] = __float2half_rn(v.y);
    g_wh[i + 2] = __float2half_rn(v.z);
    g_wh[i + 3] = __float2half_rn(v.w);
}

// -------------------- mma.sync GEMM (cp.async pipelined, fp16 2-pass) --------------------
#define KC 32
#define TPAD 40
#define TILE_B (128 * TPAD * 2)   // 10240 B per sub-tile
#define BUF_B (3 * TILE_B)        // AH, AL, BH

#define GEMM_ISSUE(c_, buf_) do {                                              \
    const int kc_ = (c_) * KC;                                                 \
    _Pragma("unroll")                                                          \
    for (int l = 0; l < 6; ++l) {                                              \
        const int st = l >> 1;                                                 \
        const int j = tid + (l & 1) * 256;                                     \
        const int r = j >> 2, g = j & 3;                                       \
        const __half* src = (st == 0) ? Aoff : ((st == 1) ? ALoff : Bh);       \
        uint32_t dst = sb + (buf_) * BUF_B + st * TILE_B +                     \
                       (uint32_t)(r * TPAD + g * 8) * 2;                       \
        cpa16(dst, src + (size_t)r * EMBED + kc_ + g * 8);                     \
    }                                                                          \
    CP_COMMIT();                                                               \
} while (0)

// MODE 0: A = x, W rows 0..3071 (Wq|Wk|Wv). grid (32, 24).
// MODE 1: A = ctx (g_ch/g_cl), W rows 3072..4095 (Wo). grid (32, 8).
template <int MODE>
__global__ __launch_bounds__(256, 2) void mma_gemm_kernel(
    const float* __restrict__ bq, const float* __restrict__ bk,
    const float* __restrict__ bv, const float* __restrict__ bo,
    float* __restrict__ outf)
{
    extern __shared__ char smem[];
    const int tid = threadIdx.x;
    const int wid = tid >> 5, lane = tid & 31;
    const int m0 = blockIdx.x * 128;
    const int nb_glob = blockIdx.y * 128;

    const __half* Ah = (MODE == 0) ? g_xh : g_ch;
    const __half* Al = (MODE == 0) ? g_xl : g_cl;
    const int wrow0 = (MODE == 0) ? nb_glob : (3072 + nb_glob);
    const __half* Bh = g_wh + (size_t)wrow0 * EMBED;
    const __half* Aoff = Ah + (size_t)m0 * EMBED;
    const __half* ALoff = Al + (size_t)m0 * EMBED;

    const int wm = wid >> 2, wn = wid & 3;
    const int mrow0 = wm * 64, ncol0 = wn * 32;

    const int aRow = lane & 15, aCol = (lane >> 4) * 8;
    const int bRow = ((lane >> 4) & 1) * 8 + (lane & 7);
    const int bCol = ((lane >> 3) & 1) * 8;

    float acc[4][4][4];
#pragma unroll
    for (int i = 0; i < 4; i++)
#pragma unroll
        for (int j = 0; j < 4; j++)
#pragma unroll
            for (int r = 0; r < 4; r++) acc[i][j][r] = 0.0f;

    const uint32_t sb = smem_u32(smem);

    GEMM_ISSUE(0, 0);

    for (int c = 0; c < 32; ++c) {
        const int buf = c & 1;
        CP_WAIT_ALL();
        __syncthreads();
        if (c < 31) GEMM_ISSUE(c + 1, buf ^ 1);

        const uint32_t pAh = sb + buf * BUF_B + 0 * TILE_B;
        const uint32_t pAl = sb + buf * BUF_B + 1 * TILE_B;
        const uint32_t pBh = sb + buf * BUF_B + 2 * TILE_B;
#pragma unroll
        for (int kk = 0; kk < KC; kk += 16) {
            uint32_t aF[2][4][4], bF[4][2];
#pragma unroll
            for (int mi = 0; mi < 4; ++mi) {
                uint32_t off = (uint32_t)((mrow0 + mi * 16 + aRow) * TPAD + kk + aCol) * 2;
                ldsm_x4(aF[0][mi][0], aF[0][mi][1], aF[0][mi][2], aF[0][mi][3], pAh + off);
                ldsm_x4(aF[1][mi][0], aF[1][mi][1], aF[1][mi][2], aF[1][mi][3], pAl + off);
            }
#pragma unroll
            for (int n2 = 0; n2 < 2; ++n2) {
                uint32_t off = (uint32_t)((ncol0 + n2 * 16 + bRow) * TPAD + kk + bCol) * 2;
                ldsm_x4(bF[n2 * 2][0], bF[n2 * 2][1],
                        bF[n2 * 2 + 1][0], bF[n2 * 2 + 1][1], pBh + off);
            }
#pragma unroll
            for (int mi = 0; mi < 4; ++mi)
#pragma unroll
                for (int ni = 0; ni < 4; ++ni) mma16816h(acc[mi][ni], aF[0][mi], bF[ni]);
#pragma unroll
            for (int mi = 0; mi < 4; ++mi)
#pragma unroll
                for (int ni = 0; ni < 4; ++ni) mma16816h(acc[mi][ni], aF[1][mi], bF[ni]);
        }
    }

    // ---- epilogue ----
    const int region = (MODE == 0) ? (nb_glob >> 10) : 3;   // 0 q, 1 k, 2 v, 3 out
    const int nloc = nb_glob & 1023;
    const float* bias = (MODE == 1) ? bo : ((region == 0) ? bq : ((region == 1) ? bk : bv));

    const int trow = lane >> 2;
    const int tcol = (lane & 3) * 2;

    if (region <= 1) {
        __syncthreads();
        unsigned char* Sb = (unsigned char*)smem;
#pragma unroll
        for (int mi = 0; mi < 4; ++mi)
#pragma unroll
            for (int ni = 0; ni < 4; ++ni)
#pragma unroll
                for (int ci = 0; ci < 4; ++ci) {
                    int gr = mrow0 + mi * 16 + trow + ((ci >> 1) ? 8 : 0);
                    int gc = ncol0 + ni * 8 + tcol + (ci & 1);
                    float v = acc[mi][ni][ci] + bias[nloc + gc];
                    Sb[gr * 128 + gc] = (unsigned char)(v >= 1.0f ? 1 : 0);
                }
        __syncthreads();
        int row = tid >> 1, half = tid & 1;
        const unsigned long long* pp = (const unsigned long long*)(Sb + row * 128 + half * 64);
        unsigned long long mask = 0;
#pragma unroll
        for (int w = 0; w < 8; ++w)
            mask |= (((pp[w] & 0x0101010101010101ULL) * 0x0102040810204080ULL) >> 56)
                    << (8 * w);
        unsigned long long* dst = (region == 0) ? g_qm : g_km;
        int h0 = nloc >> 6;
        dst[(size_t)(h0 + half) * MTOT + m0 + row] = mask;   // transposed layout
    } else if (MODE == 0) {
#pragma unroll
        for (int mi = 0; mi < 4; ++mi)
#pragma unroll
            for (int ni = 0; ni < 4; ++ni)
#pragma unroll
                for (int ci = 0; ci < 4; ci += 2) {
                    int gr = m0 + mrow0 + mi * 16 + trow + (ci ? 8 : 0);
                    int gc = ncol0 + ni * 8 + tcol;
                    int col = nloc + gc;
                    float o0 = acc[mi][ni][ci] + bias[col];
                    float o1 = acc[mi][ni][ci + 1] + bias[col + 1];
                    __half h0 = __float2half_rn(o0);
                    __half h1 = __float2half_rn(o1);
                    __half2 hh; hh.x = h0; hh.y = h1;
                    __half2 ll;
                    ll.x = __float2half_rn(o0 - __half2float(h0));
                    ll.y = __float2half_rn(o1 - __half2float(h1));
                    *(__half2*)(g_vh + (size_t)gr * EMBED + col) = hh;
                    *(__half2*)(g_vl + (size_t)gr * EMBED + col) = ll;
                }
    } else {
#pragma unroll
        for (int mi = 0; mi < 4; ++mi)
#pragma unroll
            for (int ni = 0; ni < 4; ++ni)
#pragma unroll
                for (int ci = 0; ci < 4; ci += 2) {
                    int gr = m0 + mrow0 + mi * 16 + trow + (ci ? 8 : 0);
                    int gc = ncol0 + ni * 8 + tcol;
                    int col = nb_glob + gc;
                    float2 o;
                    o.x = acc[mi][ni][ci] + bias[col];
                    o.y = acc[mi][ni][ci + 1] + bias[col + 1];
                    *(float2*)(outf + (size_t)gr * EMBED + col) = o;
                }
    }
}

// -------------------- attention: LUT weights (fp16) + 2-pass fp16 AV --------------------
// block 128 threads (4 warps), tile 64 q x 64 d (one head). 32 k-tiles of 64.
// dynamic smem layout (bytes):
#define A_PH 0           // P fp16 [k][q]: 64 x 128 B = 8192
#define A_VH 8192        // [2] x 8192
#define A_VL 24576       // [2] x 8192
#define A_KM 40960       // [2] x 512
#define A_TAB 41984      // 65 x fp16, padded
#define A_SS 42240       // float[2][64]
#define A_TOTAL 42752

#define ATTN_ISSUE(t_, buf_) do {                                              \
    _Pragma("unroll")                                                          \
    for (int j = 0; j < 4; ++j) {                                              \
        int gi = tid + j * 128;                                                \
        int r = gi >> 3, cb = gi & 7;                                          \
        uint32_t off = sw128((uint32_t)(r * 128 + cb * 16));                   \
        size_t goff = (size_t)((t_) * 64 + r) * EMBED + cb * 8;                \
        cpa16(sb + A_VH + (buf_) * 8192 + off, vhb + goff);                    \
        cpa16(sb + A_VL + (buf_) * 8192 + off, vlb + goff);                    \
    }                                                                          \
    if (tid < 32) cpa16(sb + A_KM + (buf_) * 512 + tid * 16,                   \
                        kmb + (size_t)(t_) * 64 + tid * 2);                    \
    CP_COMMIT();                                                               \
} while (0)

__global__ __launch_bounds__(128) void attn_kernel() {
    extern __shared__ char smem[];
    const uint32_t sb = smem_u32(smem);
    const int tid = threadIdx.x;
    const int lane = tid & 31, wid = tid >> 5;
    const int qt = blockIdx.x;
    const int bh = blockIdx.y;
    const int b = bh >> 4, h = bh & 15;
    const int q0 = qt * 64;
    const size_t mbase = (size_t)b * TSEQ;

    const int qa = tid & 63, kg = tid >> 6;
    const unsigned long long qmr = g_qm[(size_t)h * MTOT + mbase + q0 + qa];

    const __half* vhb = g_vh + mbase * EMBED + h * 64;
    const __half* vlb = g_vl + mbase * EMBED + h * 64;
    const unsigned long long* kmb = g_km + (size_t)h * MTOT + mbase;

    // weight LUT: scores are integers 0..64
    if (tid < 65) {
        float w = exp2f((float)tid * 0.18033688011112042f);
        ((__half*)(smem + A_TAB))[tid] = __float2half_rn(w);
    }

    // ldmatrix.x4.trans lane addressing (byte offsets)
    const int aRow = (lane & 7) + ((lane >> 4) << 3);
    const int aColB = (wid * 16 + ((lane >> 3) & 1) * 8) * 2;
    const int bRow = (lane & 7) + ((lane >> 3) & 1) * 8;
    const int bColB = (((lane >> 4) & 1) * 8) * 2;

    float acc[8][4];
#pragma unroll
    for (int i = 0; i < 8; i++)
#pragma unroll
        for (int j = 0; j < 4; j++) acc[i][j] = 0.0f;
    float rsum = 0.0f;

    ATTN_ISSUE(0, 0);

    for (int kt = 0; kt < 32; ++kt) {
        const int buf = kt & 1;
        CP_WAIT_ALL();
        __syncthreads();            // V[kt]/km[kt] visible; P[kt-1] fully consumed; LUT ready
        if (kt < 31) ATTN_ISSUE(kt + 1, buf ^ 1);

        // phase A: fp16 weights via LUT -> P
        {
            const unsigned long long* kms =
                (const unsigned long long*)(smem + A_KM + buf * 512);
            const __half* tab = (const __half*)(smem + A_TAB);
#pragma unroll
            for (int i = 0; i < 32; ++i) {
                int k = kg * 32 + i;
                int s = __popcll(qmr & kms[k]);
                __half hw = tab[s];
                *(__half*)(smem + A_PH + sw128((uint32_t)(k * 128 + qa * 2))) = hw;
                rsum += __half2float(hw);   // consistent with fp16 numerator
            }
        }
        __syncthreads();            // P visible

        // phase B: acc[16q x 64d per warp] += P @ V (2 passes: V hi, V lo)
        const uint32_t sPh = sb + A_PH;
        const uint32_t sVh = sb + A_VH + buf * 8192;
        const uint32_t sVl = sb + A_VL + buf * 8192;
        uint32_t aH[4][4];
#pragma unroll
        for (int kc = 0; kc < 4; ++kc) {
            uint32_t off = sw128((uint32_t)((kc * 16 + aRow) * 128 + aColB));
            ldsm_x4t(aH[kc][0], aH[kc][1], aH[kc][2], aH[kc][3], sPh + off);
        }
#pragma unroll
        for (int nt = 0; nt < 4; ++nt) {
            uint32_t bH[4][4], bL[4][4];
#pragma unroll
            for (int kc = 0; kc < 4; ++kc) {
                uint32_t off = sw128((uint32_t)((kc * 16 + bRow) * 128 + nt * 32 + bColB));
                ldsm_x4t(bH[kc][0], bH[kc][1], bH[kc][2], bH[kc][3], sVh + off);
                ldsm_x4t(bL[kc][0], bL[kc][1], bL[kc][2], bL[kc][3], sVl + off);
            }
#pragma unroll
            for (int kc = 0; kc < 4; ++kc) {
                mma16816h(acc[nt * 2 + 0], aH[kc], &bH[kc][0]);
                mma16816h(acc[nt * 2 + 1], aH[kc], &bH[kc][2]);
                mma16816h(acc[nt * 2 + 0], aH[kc], &bL[kc][0]);
                mma16816h(acc[nt * 2 + 1], aH[kc], &bL[kc][2]);
            }
        }
    }

    float* ss = (float*)(smem + A_SS);
    ss[kg * 64 + qa] = rsum;
    __syncthreads();

    // epilogue: normalize, split-store ctx hi/lo (fp16)
    const int r0 = wid * 16 + (lane >> 2);
    const int r1 = r0 + 8;
    const float inv0 = 1.0f / (ss[r0] + ss[64 + r0]);
    const float inv1 = 1.0f / (ss[r1] + ss[64 + r1]);
    const size_t row0 = (mbase + q0 + r0) * EMBED + h * 64;
    const size_t row1 = (mbase + q0 + r1) * EMBED + h * 64;
#pragma unroll
    for (int nt = 0; nt < 8; ++nt) {
        int col = nt * 8 + (lane & 3) * 2;
        float o0 = acc[nt][0] * inv0, o1 = acc[nt][1] * inv0;
        float o2 = acc[nt][2] * inv1, o3 = acc[nt][3] * inv1;
        __half h0 = __float2half_rn(o0), h1 = __float2half_rn(o1);
        __half h2 = __float2half_rn(o2), h3 = __float2half_rn(o3);
        __half2 hh0; hh0.x = h0; hh0.y = h1;
        __half2 hh1; hh1.x = h2; hh1.y = h3;
        __half2 ll0, ll1;
        ll0.x = __float2half_rn(o0 - __half2float(h0));
        ll0.y = __float2half_rn(o1 - __half2float(h1));
        ll1.x = __float2half_rn(o2 - __half2float(h2));
        ll1.y = __float2half_rn(o3 - __half2float(h3));
        *(__half2*)(g_ch + row0 + col) = hh0;
        *(__half2*)(g_cl + row0 + col) = ll0;
        *(__half2*)(g_ch + row1 + col) = hh1;
        *(__half2*)(g_cl + row1 + col) = ll1;
    }
}

// -------------------- launch --------------------
extern "C" void kernel_launch(void* const* d_in, const int* in_sizes, int n_in,
                              void* d_out, int out_size) {
    const float* x  = (const float*)d_in[0];
    const float* Wq = (const float*)d_in[1];
    const float* bq = (const float*)d_in[2];
    const float* Wk = (const float*)d_in[3];
    const float* bk = (const float*)d_in[4];
    const float* Wv = (const float*)d_in[5];
    const float* bv = (const float*)d_in[6];
    const float* Wo = (const float*)d_in[7];
    const float* bo = (const float*)d_in[8];
    float* out = (float*)d_out;

    const int SMEM_MMA = 2 * BUF_B;   // 61440
    cudaFuncSetAttribute(mma_gemm_kernel<0>, cudaFuncAttributeMaxDynamicSharedMemorySize, SMEM_MMA);
    cudaFuncSetAttribute(mma_gemm_kernel<1>, cudaFuncAttributeMaxDynamicSharedMemorySize, SMEM_MMA);
    cudaFuncSetAttribute(attn_kernel, cudaFuncAttributeMaxDynamicSharedMemorySize, A_TOTAL);

    convert_x_kernel<<<4096, 256>>>(x);
    convert_w_kernel<<<4096, 256>>>(Wq, Wk, Wv, Wo);
    mma_gemm_kernel<0><<<dim3(32, 24), 256, SMEM_MMA>>>(bq, bk, bv, bo, nullptr);
    attn_kernel<<<dim3(32, 32), 128, A_TOTAL>>>();
    mma_gemm_kernel<1><<<dim3(32, 8), 256, SMEM_MMA>>>(bq, bk, bv, bo, out);
}

// round 11
// speedup vs baseline: 3.3224x; 1.2494x over previous
#include <cuda_runtime.h>
#include <cuda_fp16.h>
#include <cstdint>

// Problem constants
#define EMBED 1024
#define HEADS 16
#define BATCH 2
#define TSEQ  2048
#define MTOT  4096   // BATCH*TSEQ

// -------------------- device scratch --------------------
// masks stored TRANSPOSED: [head][m] so per-head tiles are contiguous
__device__ unsigned long long g_qm[HEADS * MTOT];
__device__ unsigned long long g_km[HEADS * MTOT];
__device__ __half g_vh[MTOT * EMBED];   // v projection, single fp16
__device__ __half g_xh[MTOT * EMBED];   // x split hi/lo (fp16)
__device__ __half g_xl[MTOT * EMBED];
__device__ __half g_wh[4096 * EMBED];   // Wq|Wk|Wv|Wo rows, single fp16
__device__ __half g_ch[MTOT * EMBED];   // ctx split hi/lo (written by attn)
__device__ __half g_cl[MTOT * EMBED];

// -------------------- helpers --------------------
__device__ __forceinline__ uint32_t smem_u32(const void* p) {
    uint32_t a;
    asm("{ .reg .u64 t; cvta.to.shared.u64 t, %1; cvt.u32.u64 %0, t; }" : "=r"(a) : "l"(p));
    return a;
}
__device__ __forceinline__ void ldsm_x4(uint32_t& r0, uint32_t& r1, uint32_t& r2,
                                        uint32_t& r3, uint32_t addr) {
    asm volatile("ldmatrix.sync.aligned.m8n8.x4.shared.b16 {%0,%1,%2,%3}, [%4];"
                 : "=r"(r0), "=r"(r1), "=r"(r2), "=r"(r3) : "r"(addr));
}
__device__ __forceinline__ void ldsm_x4t(uint32_t& r0, uint32_t& r1, uint32_t& r2,
                                         uint32_t& r3, uint32_t addr) {
    asm volatile("ldmatrix.sync.aligned.m8n8.x4.trans.shared.b16 {%0,%1,%2,%3}, [%4];"
                 : "=r"(r0), "=r"(r1), "=r"(r2), "=r"(r3) : "r"(addr));
}
__device__ __forceinline__ void mma16816h(float* d, const uint32_t* a, const uint32_t* b) {
    asm volatile(
        "mma.sync.aligned.m16n8k16.row.col.f32.f16.f16.f32 "
        "{%0,%1,%2,%3}, {%4,%5,%6,%7}, {%8,%9}, {%0,%1,%2,%3};"
        : "+f"(d[0]), "+f"(d[1]), "+f"(d[2]), "+f"(d[3])
        : "r"(a[0]), "r"(a[1]), "r"(a[2]), "r"(a[3]), "r"(b[0]), "r"(b[1]));
}
__device__ __forceinline__ void cpa16(uint32_t dst, const void* src) {
    asm volatile("cp.async.cg.shared.global [%0], [%1], 16;" :: "r"(dst), "l"(src));
}
#define CP_COMMIT()   asm volatile("cp.async.commit_group;" ::: "memory")
#define CP_WAIT_ALL() asm volatile("cp.async.wait_group 0;" ::: "memory")
#define CP_WAIT_1()   asm volatile("cp.async.wait_group 1;" ::: "memory")

__device__ __forceinline__ uint32_t sw128(uint32_t off) {
    return off ^ ((off >> 3) & 0x70);
}
// pack two fp32 (already exactly fp16-representable) into fp16x2: {lo, hi}
__device__ __forceinline__ uint32_t f16x2pk(float lo, float hi) {
    uint32_t r;
    asm("cvt.rn.f16x2.f32 %0, %2, %1;" : "=r"(r) : "f"(lo), "f"(hi));
    return r;
}

// -------------------- convert kernels: fp32 -> fp16 --------------------
__device__ __forceinline__ void split_store_h(float v, __half* ph, __half* pl) {
    __half h = __float2half_rn(v);
    *ph = h;
    *pl = __float2half_rn(v - __half2float(h));
}

__global__ __launch_bounds__(256) void convert_x_kernel(const float* __restrict__ x) {
    int i = (blockIdx.x * 256 + threadIdx.x) * 4;
    float4 v = *(const float4*)(x + i);
    split_store_h(v.x, g_xh + i, g_xl + i);
    split_store_h(v.y, g_xh + i + 1, g_xl + i + 1);
    split_store_h(v.z, g_xh + i + 2, g_xl + i + 2);
    split_store_h(v.w, g_xh + i + 3, g_xl + i + 3);
}

__global__ __launch_bounds__(256) void convert_w_kernel(
    const float* __restrict__ Wq, const float* __restrict__ Wk,
    const float* __restrict__ Wv, const float* __restrict__ Wo) {
    int i = (blockIdx.x * 256 + threadIdx.x) * 4;
    int row = i >> 10, col = i & 1023;
    const float* src;
    if (row < 1024)      src = Wq + (size_t)row * EMBED + col;
    else if (row < 2048) src = Wk + (size_t)(row - 1024) * EMBED + col;
    else if (row < 3072) src = Wv + (size_t)(row - 2048) * EMBED + col;
    else                 src = Wo + (size_t)(row - 3072) * EMBED + col;
    float4 v = *(const float4*)src;
    g_wh[i]     = __float2half_rn(v.x);
    g_wh[i + 1] = __float2half_rn(v.y);
    g_wh[i + 2] = __float2half_rn(v.z);
    g_wh[i + 3] = __float2half_rn(v.w);
}

// -------------------- mma.sync GEMM (cp.async pipelined, fp16 2-pass) --------------------
#define KC 32
#define TPAD 40
#define TILE_B (128 * TPAD * 2)   // 10240 B per sub-tile
#define BUF_B (3 * TILE_B)        // AH, AL, BH

#define GEMM_ISSUE(c_, buf_) do {                                              \
    const int kc_ = (c_) * KC;                                                 \
    _Pragma("unroll")                                                          \
    for (int l = 0; l < 6; ++l) {                                              \
        const int st = l >> 1;                                                 \
        const int j = tid + (l & 1) * 256;                                     \
        const int r = j >> 2, g = j & 3;                                       \
        const __half* src = (st == 0) ? Aoff : ((st == 1) ? ALoff : Bh);       \
        uint32_t dst = sb + (buf_) * BUF_B + st * TILE_B +                     \
                       (uint32_t)(r * TPAD + g * 8) * 2;                       \
        cpa16(dst, src + (size_t)r * EMBED + kc_ + g * 8);                     \
    }                                                                          \
    CP_COMMIT();                                                               \
} while (0)

// MODE 0: A = x, W rows 0..3071 (Wq|Wk|Wv). grid (32, 24).
// MODE 1: A = ctx (g_ch/g_cl), W rows 3072..4095 (Wo). grid (32, 8).
template <int MODE>
__global__ __launch_bounds__(256, 2) void mma_gemm_kernel(
    const float* __restrict__ bq, const float* __restrict__ bk,
    const float* __restrict__ bv, const float* __restrict__ bo,
    float* __restrict__ outf)
{
    extern __shared__ char smem[];
    const int tid = threadIdx.x;
    const int wid = tid >> 5, lane = tid & 31;
    const int m0 = blockIdx.x * 128;
    const int nb_glob = blockIdx.y * 128;

    const __half* Ah = (MODE == 0) ? g_xh : g_ch;
    const __half* Al = (MODE == 0) ? g_xl : g_cl;
    const int wrow0 = (MODE == 0) ? nb_glob : (3072 + nb_glob);
    const __half* Bh = g_wh + (size_t)wrow0 * EMBED;
    const __half* Aoff = Ah + (size_t)m0 * EMBED;
    const __half* ALoff = Al + (size_t)m0 * EMBED;

    const int wm = wid >> 2, wn = wid & 3;
    const int mrow0 = wm * 64, ncol0 = wn * 32;

    const int aRow = lane & 15, aCol = (lane >> 4) * 8;
    const int bRow = ((lane >> 4) & 1) * 8 + (lane & 7);
    const int bCol = ((lane >> 3) & 1) * 8;

    float acc[4][4][4];
#pragma unroll
    for (int i = 0; i < 4; i++)
#pragma unroll
        for (int j = 0; j < 4; j++)
#pragma unroll
            for (int r = 0; r < 4; r++) acc[i][j][r] = 0.0f;

    const uint32_t sb = smem_u32(smem);

    GEMM_ISSUE(0, 0);

    for (int c = 0; c < 32; ++c) {
        const int buf = c & 1;
        CP_WAIT_ALL();
        __syncthreads();
        if (c < 31) GEMM_ISSUE(c + 1, buf ^ 1);

        const uint32_t pAh = sb + buf * BUF_B + 0 * TILE_B;
        const uint32_t pAl = sb + buf * BUF_B + 1 * TILE_B;
        const uint32_t pBh = sb + buf * BUF_B + 2 * TILE_B;
#pragma unroll
        for (int kk = 0; kk < KC; kk += 16) {
            uint32_t aF[2][4][4], bF[4][2];
#pragma unroll
            for (int mi = 0; mi < 4; ++mi) {
                uint32_t off = (uint32_t)((mrow0 + mi * 16 + aRow) * TPAD + kk + aCol) * 2;
                ldsm_x4(aF[0][mi][0], aF[0][mi][1], aF[0][mi][2], aF[0][mi][3], pAh + off);
                ldsm_x4(aF[1][mi][0], aF[1][mi][1], aF[1][mi][2], aF[1][mi][3], pAl + off);
            }
#pragma unroll
            for (int n2 = 0; n2 < 2; ++n2) {
                uint32_t off = (uint32_t)((ncol0 + n2 * 16 + bRow) * TPAD + kk + bCol) * 2;
                ldsm_x4(bF[n2 * 2][0], bF[n2 * 2][1],
                        bF[n2 * 2 + 1][0], bF[n2 * 2 + 1][1], pBh + off);
            }
#pragma unroll
            for (int mi = 0; mi < 4; ++mi)
#pragma unroll
                for (int ni = 0; ni < 4; ++ni) mma16816h(acc[mi][ni], aF[0][mi], bF[ni]);
#pragma unroll
            for (int mi = 0; mi < 4; ++mi)
#pragma unroll
                for (int ni = 0; ni < 4; ++ni) mma16816h(acc[mi][ni], aF[1][mi], bF[ni]);
        }
    }

    // ---- epilogue ----
    const int region = (MODE == 0) ? (nb_glob >> 10) : 3;   // 0 q, 1 k, 2 v, 3 out
    const int nloc = nb_glob & 1023;
    const float* bias = (MODE == 1) ? bo : ((region == 0) ? bq : ((region == 1) ? bk : bv));

    const int trow = lane >> 2;
    const int tcol = (lane & 3) * 2;

    if (region <= 1) {
        __syncthreads();
        unsigned char* Sb = (unsigned char*)smem;
#pragma unroll
        for (int mi = 0; mi < 4; ++mi)
#pragma unroll
            for (int ni = 0; ni < 4; ++ni)
#pragma unroll
                for (int ci = 0; ci < 4; ++ci) {
                    int gr = mrow0 + mi * 16 + trow + ((ci >> 1) ? 8 : 0);
                    int gc = ncol0 + ni * 8 + tcol + (ci & 1);
                    float v = acc[mi][ni][ci] + bias[nloc + gc];
                    Sb[gr * 128 + gc] = (unsigned char)(v >= 1.0f ? 1 : 0);
                }
        __syncthreads();
        int row = tid >> 1, half = tid & 1;
        const unsigned long long* pp = (const unsigned long long*)(Sb + row * 128 + half * 64);
        unsigned long long mask = 0;
#pragma unroll
        for (int w = 0; w < 8; ++w)
            mask |= (((pp[w] & 0x0101010101010101ULL) * 0x0102040810204080ULL) >> 56)
                    << (8 * w);
        unsigned long long* dst = (region == 0) ? g_qm : g_km;
        int h0 = nloc >> 6;
        dst[(size_t)(h0 + half) * MTOT + m0 + row] = mask;   // transposed layout
    } else if (MODE == 0) {
        // v region: single fp16 store
#pragma unroll
        for (int mi = 0; mi < 4; ++mi)
#pragma unroll
            for (int ni = 0; ni < 4; ++ni)
#pragma unroll
                for (int ci = 0; ci < 4; ci += 2) {
                    int gr = m0 + mrow0 + mi * 16 + trow + (ci ? 8 : 0);
                    int gc = ncol0 + ni * 8 + tcol;
                    int col = nloc + gc;
                    __half2 hh;
                    hh.x = __float2half_rn(acc[mi][ni][ci] + bias[col]);
                    hh.y = __float2half_rn(acc[mi][ni][ci + 1] + bias[col + 1]);
                    *(__half2*)(g_vh + (size_t)gr * EMBED + col) = hh;
                }
    } else {
#pragma unroll
        for (int mi = 0; mi < 4; ++mi)
#pragma unroll
            for (int ni = 0; ni < 4; ++ni)
#pragma unroll
                for (int ci = 0; ci < 4; ci += 2) {
                    int gr = m0 + mrow0 + mi * 16 + trow + (ci ? 8 : 0);
                    int gc = ncol0 + ni * 8 + tcol;
                    int col = nb_glob + gc;
                    float2 o;
                    o.x = acc[mi][ni][ci] + bias[col];
                    o.y = acc[mi][ni][ci + 1] + bias[col + 1];
                    *(float2*)(outf + (size_t)gr * EMBED + col) = o;
                }
    }
}

// -------------------- attention: in-register P fragments + 1-pass fp16 AV --------------------
// block 128 threads (4 warps). warp w: q rows [q0 + w*16, +16), full 64 d.
// V single fp16, 3-stage cp.async ring. P built directly in mma A-fragment registers.
#define NBUF 3
#define A_V   0                      // NBUF x 8192 (V tiles, SW128)
#define A_KM  (NBUF * 8192)          // NBUF x 512 (km tiles)
#define A_TAB (A_KM + NBUF * 512)    // 65 floats (fp16-exact values)
#define A_TOTAL (A_TAB + 512)

#define ATTN_ISSUE(t_, buf_) do {                                              \
    _Pragma("unroll")                                                          \
    for (int j = 0; j < 4; ++j) {                                              \
        int gi = tid + j * 128;                                                \
        int r = gi >> 3, cb = gi & 7;                                          \
        uint32_t off = sw128((uint32_t)(r * 128 + cb * 16));                   \
        cpa16(sb + A_V + (buf_) * 8192 + off,                                  \
              vhb + (size_t)((t_) * 64 + r) * EMBED + cb * 8);                 \
    }                                                                          \
    if (tid < 32) cpa16(sb + A_KM + (buf_) * 512 + tid * 16,                   \
                        kmb + (size_t)(t_) * 64 + tid * 2);                    \
    CP_COMMIT();                                                               \
} while (0)

__global__ __launch_bounds__(128) void attn_kernel() {
    extern __shared__ char smem[];
    const uint32_t sb = smem_u32(smem);
    const int tid = threadIdx.x;
    const int lane = tid & 31, wid = tid >> 5;
    const int qt = blockIdx.x;
    const int bh = blockIdx.y;
    const int b = bh >> 4, h = bh & 15;
    const int q0 = qt * 64;
    const size_t mbase = (size_t)b * TSEQ;

    const int g = lane >> 2;            // fragment row group
    const int c0 = (lane & 3) * 2;      // fragment col base

    // per-lane q masks for fragment rows (fixed for whole kernel)
    const unsigned long long qmr0 =
        g_qm[(size_t)h * MTOT + mbase + q0 + wid * 16 + g];
    const unsigned long long qmr1 =
        g_qm[(size_t)h * MTOT + mbase + q0 + wid * 16 + g + 8];

    const __half* vhb = g_vh + mbase * EMBED + h * 64;
    const unsigned long long* kmb = g_km + (size_t)h * MTOT + mbase;

    // weight LUT (fp32 holding exactly-fp16 values => numerator/denominator consistent)
    if (tid < 65) {
        float w = exp2f((float)tid * 0.18033688011112042f);
        ((float*)(smem + A_TAB))[tid] = __half2float(__float2half_rn(w));
    }

    // V ldmatrix lane addressing (same as prior passing rounds)
    const int bRow = (lane & 7) + ((lane >> 3) & 1) * 8;
    const int bColB = ((lane >> 4) & 1) * 16;

    float acc[8][4];
#pragma unroll
    for (int i = 0; i < 8; i++)
#pragma unroll
        for (int j = 0; j < 4; j++) acc[i][j] = 0.0f;
    float rsum0 = 0.0f, rsum1 = 0.0f;

    ATTN_ISSUE(0, 0);
    ATTN_ISSUE(1, 1);

    int buf = 0;
    for (int kt = 0; kt < 32; ++kt) {
        CP_WAIT_1();
        __syncthreads();     // V[kt]/km[kt] visible; ring slot (kt+2)%3 fully consumed
        if (kt < 30) {
            int nb = buf + 2; if (nb >= NBUF) nb -= NBUF;
            ATTN_ISSUE(kt + 2, nb);
        }

        // build P fragments in registers
        const unsigned long long* kms =
            (const unsigned long long*)(smem + A_KM + buf * 512);
        const float* tab = (const float*)(smem + A_TAB);
        uint32_t pf[4][4];
#pragma unroll
        for (int kc = 0; kc < 4; ++kc) {
            ulonglong2 kmA = *(const ulonglong2*)(kms + kc * 16 + c0);      // km[c0], km[c0+1]
            ulonglong2 kmB = *(const ulonglong2*)(kms + kc * 16 + c0 + 8);  // km[c0+8], km[c0+9]
            float w00 = tab[__popcll(qmr0 & kmA.x)];
            float w01 = tab[__popcll(qmr0 & kmA.y)];
            float w10 = tab[__popcll(qmr1 & kmA.x)];
            float w11 = tab[__popcll(qmr1 & kmA.y)];
            float w02 = tab[__popcll(qmr0 & kmB.x)];
            float w03 = tab[__popcll(qmr0 & kmB.y)];
            float w12 = tab[__popcll(qmr1 & kmB.x)];
            float w13 = tab[__popcll(qmr1 & kmB.y)];
            pf[kc][0] = f16x2pk(w00, w01);   // row g,   cols c0, c0+1
            pf[kc][1] = f16x2pk(w10, w11);   // row g+8, cols c0, c0+1
            pf[kc][2] = f16x2pk(w02, w03);   // row g,   cols c0+8, c0+9
            pf[kc][3] = f16x2pk(w12, w13);   // row g+8, cols c0+8, c0+9
            rsum0 += (w00 + w01) + (w02 + w03);
            rsum1 += (w10 + w11) + (w12 + w13);
        }

        // AV: acc[16q x 64d per warp] += P @ V (single fp16 pass)
        const uint32_t sV = sb + A_V + buf * 8192;
#pragma unroll
        for (int nt = 0; nt < 4; ++nt) {
            uint32_t bH[4][4];
#pragma unroll
            for (int kc = 0; kc < 4; ++kc) {
                uint32_t off = sw128((uint32_t)((kc * 16 + bRow) * 128 + nt * 32 + bColB));
                ldsm_x4t(bH[kc][0], bH[kc][1], bH[kc][2], bH[kc][3], sV + off);
            }
#pragma unroll
            for (int kc = 0; kc < 4; ++kc) {
                mma16816h(acc[nt * 2 + 0], pf[kc], &bH[kc][0]);
                mma16816h(acc[nt * 2 + 1], pf[kc], &bH[kc][2]);
            }
        }

        if (++buf >= NBUF) buf = 0;
    }

    // reduce row sums across the 4 lanes sharing each fragment row
    rsum0 += __shfl_xor_sync(0xFFFFFFFF, rsum0, 1);
    rsum0 += __shfl_xor_sync(0xFFFFFFFF, rsum0, 2);
    rsum1 += __shfl_xor_sync(0xFFFFFFFF, rsum1, 1);
    rsum1 += __shfl_xor_sync(0xFFFFFFFF, rsum1, 2);
    const float inv0 = 1.0f / rsum0;
    const float inv1 = 1.0f / rsum1;

    // epilogue: normalize, split-store ctx hi/lo (fp16)
    const size_t row0 = (mbase + q0 + wid * 16 + g) * EMBED + h * 64;
    const size_t row1 = (mbase + q0 + wid * 16 + g + 8) * EMBED + h * 64;
#pragma unroll
    for (int nt = 0; nt < 8; ++nt) {
        int col = nt * 8 + c0;
        float o0 = acc[nt][0] * inv0, o1 = acc[nt][1] * inv0;
        float o2 = acc[nt][2] * inv1, o3 = acc[nt][3] * inv1;
        __half h0 = __float2half_rn(o0), h1 = __float2half_rn(o1);
        __half h2 = __float2half_rn(o2), h3 = __float2half_rn(o3);
        __half2 hh0; hh0.x = h0; hh0.y = h1;
        __half2 hh1; hh1.x = h2; hh1.y = h3;
        __half2 ll0, ll1;
        ll0.x = __float2half_rn(o0 - __half2float(h0));
        ll0.y = __float2half_rn(o1 - __half2float(h1));
        ll1.x = __float2half_rn(o2 - __half2float(h2));
        ll1.y = __float2half_rn(o3 - __half2float(h3));
        *(__half2*)(g_ch + row0 + col) = hh0;
        *(__half2*)(g_cl + row0 + col) = ll0;
        *(__half2*)(g_ch + row1 + col) = hh1;
        *(__half2*)(g_cl + row1 + col) = ll1;
    }
}

// -------------------- launch --------------------
extern "C" void kernel_launch(void* const* d_in, const int* in_sizes, int n_in,
                              void* d_out, int out_size) {
    const float* x  = (const float*)d_in[0];
    const float* Wq = (const float*)d_in[1];
    const float* bq = (const float*)d_in[2];
    const float* Wk = (const float*)d_in[3];
    const float* bk = (const float*)d_in[4];
    const float* Wv = (const float*)d_in[5];
    const float* bv = (const float*)d_in[6];
    const float* Wo = (const float*)d_in[7];
    const float* bo = (const float*)d_in[8];
    float* out = (float*)d_out;

    const int SMEM_MMA = 2 * BUF_B;   // 61440
    cudaFuncSetAttribute(mma_gemm_kernel<0>, cudaFuncAttributeMaxDynamicSharedMemorySize, SMEM_MMA);
    cudaFuncSetAttribute(mma_gemm_kernel<1>, cudaFuncAttributeMaxDynamicSharedMemorySize, SMEM_MMA);
    cudaFuncSetAttribute(attn_kernel, cudaFuncAttributeMaxDynamicSharedMemorySize, A_TOTAL);

    convert_x_kernel<<<4096, 256>>>(x);
    convert_w_kernel<<<4096, 256>>>(Wq, Wk, Wv, Wo);
    mma_gemm_kernel<0><<<dim3(32, 24), 256, SMEM_MMA>>>(bq, bk, bv, bo, nullptr);
    attn_kernel<<<dim3(32, 32), 128, A_TOTAL>>>();
    mma_gemm_kernel<1><<<dim3(32, 8), 256, SMEM_MMA>>>(bq, bk, bv, bo, out);
}

// round 12
// speedup vs baseline: 3.6116x; 1.0870x over previous
#include <cuda_runtime.h>
#include <cuda_fp16.h>
#include <cstdint>

// Problem constants
#define EMBED 1024
#define HEADS 16
#define BATCH 2
#define TSEQ  2048
#define MTOT  4096   // BATCH*TSEQ

// -------------------- device scratch --------------------
// masks stored TRANSPOSED: [head][m] so per-head tiles are contiguous
__device__ unsigned long long g_qm[HEADS * MTOT];
__device__ unsigned long long g_km[HEADS * MTOT];
__device__ __half g_vh[MTOT * EMBED];   // v projection, single fp16
__device__ __half g_xh[MTOT * EMBED];   // x split hi/lo (fp16)
__device__ __half g_xl[MTOT * EMBED];
__device__ __half g_wh[4096 * EMBED];   // Wq|Wk|Wv|Wo rows, single fp16
__device__ __half g_ch[MTOT * EMBED];   // ctx split hi/lo (written by attn)
__device__ __half g_cl[MTOT * EMBED];

// -------------------- helpers --------------------
__device__ __forceinline__ uint32_t smem_u32(const void* p) {
    uint32_t a;
    asm("{ .reg .u64 t; cvta.to.shared.u64 t, %1; cvt.u32.u64 %0, t; }" : "=r"(a) : "l"(p));
    return a;
}
__device__ __forceinline__ void ldsm_x4(uint32_t& r0, uint32_t& r1, uint32_t& r2,
                                        uint32_t& r3, uint32_t addr) {
    asm volatile("ldmatrix.sync.aligned.m8n8.x4.shared.b16 {%0,%1,%2,%3}, [%4];"
                 : "=r"(r0), "=r"(r1), "=r"(r2), "=r"(r3) : "r"(addr));
}
__device__ __forceinline__ void ldsm_x4t(uint32_t& r0, uint32_t& r1, uint32_t& r2,
                                         uint32_t& r3, uint32_t addr) {
    asm volatile("ldmatrix.sync.aligned.m8n8.x4.trans.shared.b16 {%0,%1,%2,%3}, [%4];"
                 : "=r"(r0), "=r"(r1), "=r"(r2), "=r"(r3) : "r"(addr));
}
__device__ __forceinline__ void mma16816h(float* d, const uint32_t* a, const uint32_t* b) {
    asm volatile(
        "mma.sync.aligned.m16n8k16.row.col.f32.f16.f16.f32 "
        "{%0,%1,%2,%3}, {%4,%5,%6,%7}, {%8,%9}, {%0,%1,%2,%3};"
        : "+f"(d[0]), "+f"(d[1]), "+f"(d[2]), "+f"(d[3])
        : "r"(a[0]), "r"(a[1]), "r"(a[2]), "r"(a[3]), "r"(b[0]), "r"(b[1]));
}
__device__ __forceinline__ void cpa16(uint32_t dst, const void* src) {
    asm volatile("cp.async.cg.shared.global [%0], [%1], 16;" :: "r"(dst), "l"(src));
}
#define CP_COMMIT()   asm volatile("cp.async.commit_group;" ::: "memory")
#define CP_WAIT_ALL() asm volatile("cp.async.wait_group 0;" ::: "memory")
#define CP_WAIT_1()   asm volatile("cp.async.wait_group 1;" ::: "memory")

__device__ __forceinline__ uint32_t sw128(uint32_t off) {
    return off ^ ((off >> 3) & 0x70);
}
// pack two fp32 (already exactly fp16-representable) into fp16x2: {lo, hi}
__device__ __forceinline__ uint32_t f16x2pk(float lo, float hi) {
    uint32_t r;
    asm("cvt.rn.f16x2.f32 %0, %2, %1;" : "=r"(r) : "f"(lo), "f"(hi));
    return r;
}

// -------------------- convert kernel: fp32 -> fp16 (x split + W single) --------------------
__device__ __forceinline__ void split_store_h(float v, __half* ph, __half* pl) {
    __half h = __float2half_rn(v);
    *ph = h;
    *pl = __float2half_rn(v - __half2float(h));
}

// grid 8192: blocks [0,4096) convert x (split), [4096,8192) convert W (single)
__global__ __launch_bounds__(256) void convert_xw_kernel(
    const float* __restrict__ x,
    const float* __restrict__ Wq, const float* __restrict__ Wk,
    const float* __restrict__ Wv, const float* __restrict__ Wo) {
    if (blockIdx.x < 4096) {
        int i = (blockIdx.x * 256 + threadIdx.x) * 4;
        float4 v = *(const float4*)(x + i);
        split_store_h(v.x, g_xh + i, g_xl + i);
        split_store_h(v.y, g_xh + i + 1, g_xl + i + 1);
        split_store_h(v.z, g_xh + i + 2, g_xl + i + 2);
        split_store_h(v.w, g_xh + i + 3, g_xl + i + 3);
    } else {
        int i = ((blockIdx.x - 4096) * 256 + threadIdx.x) * 4;
        int row = i >> 10, col = i & 1023;
        const float* src;
        if (row < 1024)      src = Wq + (size_t)row * EMBED + col;
        else if (row < 2048) src = Wk + (size_t)(row - 1024) * EMBED + col;
        else if (row < 3072) src = Wv + (size_t)(row - 2048) * EMBED + col;
        else                 src = Wo + (size_t)(row - 3072) * EMBED + col;
        float4 v = *(const float4*)src;
        __half2 a, b;
        a.x = __float2half_rn(v.x); a.y = __float2half_rn(v.y);
        b.x = __float2half_rn(v.z); b.y = __float2half_rn(v.w);
        *(__half2*)(g_wh + i) = a;
        *(__half2*)(g_wh + i + 2) = b;
    }
}

// -------------------- mma.sync GEMM (3-stage cp.async ring, fp16) --------------------
#define KC 32
#define TPAD 40
#define TILE_B (128 * TPAD * 2)   // 10240 B per sub-tile
#define BUF_B (3 * TILE_B)        // AH, AL, BH
#define GNBUF 3
#define SMEM_MMA (GNBUF * BUF_B)  // 92160 B

// needLo==false skips the AL sub-tile load (v region: single-pass)
#define GEMM_ISSUE(c_, buf_) do {                                              \
    const int kc_ = (c_) * KC;                                                 \
    _Pragma("unroll")                                                          \
    for (int l = 0; l < 6; ++l) {                                              \
        const int st = l >> 1;                                                 \
        if (st == 1 && !needLo) continue;                                      \
        const int j = tid + (l & 1) * 256;                                     \
        const int r = j >> 2, g = j & 3;                                       \
        const __half* src = (st == 0) ? Aoff : ((st == 1) ? ALoff : Bh);       \
        uint32_t dst = sb + (buf_) * BUF_B + st * TILE_B +                     \
                       (uint32_t)(r * TPAD + g * 8) * 2;                       \
        cpa16(dst, src + (size_t)r * EMBED + kc_ + g * 8);                     \
    }                                                                          \
    CP_COMMIT();                                                               \
} while (0)

// MODE 0: A = x, W rows 0..3071 (Wq|Wk|Wv). grid (32, 24). v region: 1-pass.
// MODE 1: A = ctx (g_ch/g_cl), W rows 3072..4095 (Wo). grid (32, 8). 2-pass.
template <int MODE>
__global__ __launch_bounds__(256, 2) void mma_gemm_kernel(
    const float* __restrict__ bq, const float* __restrict__ bk,
    const float* __restrict__ bv, const float* __restrict__ bo,
    float* __restrict__ outf)
{
    extern __shared__ char smem[];
    const int tid = threadIdx.x;
    const int wid = tid >> 5, lane = tid & 31;
    const int m0 = blockIdx.x * 128;
    const int nb_glob = blockIdx.y * 128;

    const int region = (MODE == 0) ? (nb_glob >> 10) : 3;   // 0 q, 1 k, 2 v, 3 out
    const bool needLo = !(MODE == 0 && region == 2);

    const __half* Ah = (MODE == 0) ? g_xh : g_ch;
    const __half* Al = (MODE == 0) ? g_xl : g_cl;
    const int wrow0 = (MODE == 0) ? nb_glob : (3072 + nb_glob);
    const __half* Bh = g_wh + (size_t)wrow0 * EMBED;
    const __half* Aoff = Ah + (size_t)m0 * EMBED;
    const __half* ALoff = Al + (size_t)m0 * EMBED;

    const int wm = wid >> 2, wn = wid & 3;
    const int mrow0 = wm * 64, ncol0 = wn * 32;

    const int aRow = lane & 15, aCol = (lane >> 4) * 8;
    const int bRow = ((lane >> 4) & 1) * 8 + (lane & 7);
    const int bCol = ((lane >> 3) & 1) * 8;

    float acc[4][4][4];
#pragma unroll
    for (int i = 0; i < 4; i++)
#pragma unroll
        for (int j = 0; j < 4; j++)
#pragma unroll
            for (int r = 0; r < 4; r++) acc[i][j][r] = 0.0f;

    const uint32_t sb = smem_u32(smem);

    GEMM_ISSUE(0, 0);
    GEMM_ISSUE(1, 1);

    int buf = 0;
    for (int c = 0; c < 32; ++c) {
        if (c < 31) CP_WAIT_1(); else CP_WAIT_ALL();
        __syncthreads();
        if (c < 30) {
            int nb = buf + 2; if (nb >= GNBUF) nb -= GNBUF;
            GEMM_ISSUE(c + 2, nb);
        }

        const uint32_t pAh = sb + buf * BUF_B + 0 * TILE_B;
        const uint32_t pAl = sb + buf * BUF_B + 1 * TILE_B;
        const uint32_t pBh = sb + buf * BUF_B + 2 * TILE_B;
#pragma unroll
        for (int kk = 0; kk < KC; kk += 16) {
            uint32_t aF[2][4][4], bF[4][2];
#pragma unroll
            for (int mi = 0; mi < 4; ++mi) {
                uint32_t off = (uint32_t)((mrow0 + mi * 16 + aRow) * TPAD + kk + aCol) * 2;
                ldsm_x4(aF[0][mi][0], aF[0][mi][1], aF[0][mi][2], aF[0][mi][3], pAh + off);
                if (needLo)
                    ldsm_x4(aF[1][mi][0], aF[1][mi][1], aF[1][mi][2], aF[1][mi][3], pAl + off);
            }
#pragma unroll
            for (int n2 = 0; n2 < 2; ++n2) {
                uint32_t off = (uint32_t)((ncol0 + n2 * 16 + bRow) * TPAD + kk + bCol) * 2;
                ldsm_x4(bF[n2 * 2][0], bF[n2 * 2][1],
                        bF[n2 * 2 + 1][0], bF[n2 * 2 + 1][1], pBh + off);
            }
#pragma unroll
            for (int mi = 0; mi < 4; ++mi)
#pragma unroll
                for (int ni = 0; ni < 4; ++ni) mma16816h(acc[mi][ni], aF[0][mi], bF[ni]);
            if (needLo) {
#pragma unroll
                for (int mi = 0; mi < 4; ++mi)
#pragma unroll
                    for (int ni = 0; ni < 4; ++ni) mma16816h(acc[mi][ni], aF[1][mi], bF[ni]);
            }
        }
        if (++buf >= GNBUF) buf = 0;
    }

    // ---- epilogue ----
    const int nloc = nb_glob & 1023;
    const float* bias = (MODE == 1) ? bo : ((region == 0) ? bq : ((region == 1) ? bk : bv));

    const int trow = lane >> 2;
    const int tcol = (lane & 3) * 2;

    if (region <= 1) {
        __syncthreads();
        unsigned char* Sb = (unsigned char*)smem;
#pragma unroll
        for (int mi = 0; mi < 4; ++mi)
#pragma unroll
            for (int ni = 0; ni < 4; ++ni)
#pragma unroll
                for (int ci = 0; ci < 4; ++ci) {
                    int gr = mrow0 + mi * 16 + trow + ((ci >> 1) ? 8 : 0);
                    int gc = ncol0 + ni * 8 + tcol + (ci & 1);
                    float v = acc[mi][ni][ci] + bias[nloc + gc];
                    Sb[gr * 128 + gc] = (unsigned char)(v >= 1.0f ? 1 : 0);
                }
        __syncthreads();
        int row = tid >> 1, half = tid & 1;
        const unsigned long long* pp = (const unsigned long long*)(Sb + row * 128 + half * 64);
        unsigned long long mask = 0;
#pragma unroll
        for (int w = 0; w < 8; ++w)
            mask |= (((pp[w] & 0x0101010101010101ULL) * 0x0102040810204080ULL) >> 56)
                    << (8 * w);
        unsigned long long* dst = (region == 0) ? g_qm : g_km;
        int h0 = nloc >> 6;
        dst[(size_t)(h0 + half) * MTOT + m0 + row] = mask;   // transposed layout
    } else if (MODE == 0) {
        // v region: single fp16 store
#pragma unroll
        for (int mi = 0; mi < 4; ++mi)
#pragma unroll
            for (int ni = 0; ni < 4; ++ni)
#pragma unroll
                for (int ci = 0; ci < 4; ci += 2) {
                    int gr = m0 + mrow0 + mi * 16 + trow + (ci ? 8 : 0);
                    int gc = ncol0 + ni * 8 + tcol;
                    int col = nloc + gc;
                    __half2 hh;
                    hh.x = __float2half_rn(acc[mi][ni][ci] + bias[col]);
                    hh.y = __float2half_rn(acc[mi][ni][ci + 1] + bias[col + 1]);
                    *(__half2*)(g_vh + (size_t)gr * EMBED + col) = hh;
                }
    } else {
#pragma unroll
        for (int mi = 0; mi < 4; ++mi)
#pragma unroll
            for (int ni = 0; ni < 4; ++ni)
#pragma unroll
                for (int ci = 0; ci < 4; ci += 2) {
                    int gr = m0 + mrow0 + mi * 16 + trow + (ci ? 8 : 0);
                    int gc = ncol0 + ni * 8 + tcol;
                    int col = nb_glob + gc;
                    float2 o;
                    o.x = acc[mi][ni][ci] + bias[col];
                    o.y = acc[mi][ni][ci + 1] + bias[col + 1];
                    *(float2*)(outf + (size_t)gr * EMBED + col) = o;
                }
    }
}

// -------------------- attention: in-register P fragments + 1-pass fp16 AV --------------------
// block 128 threads (4 warps). warp w: q rows [q0 + w*16, +16), full 64 d.
// V single fp16, 3-stage cp.async ring. P built directly in mma A-fragment registers.
#define NBUF 3
#define A_V   0                      // NBUF x 8192 (V tiles, SW128)
#define A_KM  (NBUF * 8192)          // NBUF x 512 (km tiles)
#define A_TAB (A_KM + NBUF * 512)    // 65 floats (fp16-exact values)
#define A_TOTAL (A_TAB + 512)

#define ATTN_ISSUE(t_, buf_) do {                                              \
    _Pragma("unroll")                                                          \
    for (int j = 0; j < 4; ++j) {                                              \
        int gi = tid + j * 128;                                                \
        int r = gi >> 3, cb = gi & 7;                                          \
        uint32_t off = sw128((uint32_t)(r * 128 + cb * 16));                   \
        cpa16(sb + A_V + (buf_) * 8192 + off,                                  \
              vhb + (size_t)((t_) * 64 + r) * EMBED + cb * 8);                 \
    }                                                                          \
    if (tid < 32) cpa16(sb + A_KM + (buf_) * 512 + tid * 16,                   \
                        kmb + (size_t)(t_) * 64 + tid * 2);                    \
    CP_COMMIT();                                                               \
} while (0)

__global__ __launch_bounds__(128) void attn_kernel() {
    extern __shared__ char smem[];
    const uint32_t sb = smem_u32(smem);
    const int tid = threadIdx.x;
    const int lane = tid & 31, wid = tid >> 5;
    const int qt = blockIdx.x;
    const int bh = blockIdx.y;
    const int b = bh >> 4, h = bh & 15;
    const int q0 = qt * 64;
    const size_t mbase = (size_t)b * TSEQ;

    const int g = lane >> 2;            // fragment row group
    const int c0 = (lane & 3) * 2;      // fragment col base

    const unsigned long long qmr0 =
        g_qm[(size_t)h * MTOT + mbase + q0 + wid * 16 + g];
    const unsigned long long qmr1 =
        g_qm[(size_t)h * MTOT + mbase + q0 + wid * 16 + g + 8];

    const __half* vhb = g_vh + mbase * EMBED + h * 64;
    const unsigned long long* kmb = g_km + (size_t)h * MTOT + mbase;

    // weight LUT (fp32 holding exactly-fp16 values => numerator/denominator consistent)
    if (tid < 65) {
        float w = exp2f((float)tid * 0.18033688011112042f);
        ((float*)(smem + A_TAB))[tid] = __half2float(__float2half_rn(w));
    }

    const int bRow = (lane & 7) + ((lane >> 3) & 1) * 8;
    const int bColB = ((lane >> 4) & 1) * 16;

    float acc[8][4];
#pragma unroll
    for (int i = 0; i < 8; i++)
#pragma unroll
        for (int j = 0; j < 4; j++) acc[i][j] = 0.0f;
    float rsum0 = 0.0f, rsum1 = 0.0f;

    ATTN_ISSUE(0, 0);
    ATTN_ISSUE(1, 1);

    int buf = 0;
    for (int kt = 0; kt < 32; ++kt) {
        if (kt < 31) CP_WAIT_1(); else CP_WAIT_ALL();   // race fix: last tile must be complete
        __syncthreads();     // V[kt]/km[kt] visible; ring slot (kt+2)%3 fully consumed
        if (kt < 30) {
            int nb = buf + 2; if (nb >= NBUF) nb -= NBUF;
            ATTN_ISSUE(kt + 2, nb);
        }

        // build P fragments in registers
        const unsigned long long* kms =
            (const unsigned long long*)(smem + A_KM + buf * 512);
        const float* tab = (const float*)(smem + A_TAB);
        uint32_t pf[4][4];
#pragma unroll
        for (int kc = 0; kc < 4; ++kc) {
            ulonglong2 kmA = *(const ulonglong2*)(kms + kc * 16 + c0);      // km[c0], km[c0+1]
            ulonglong2 kmB = *(const ulonglong2*)(kms + kc * 16 + c0 + 8);  // km[c0+8], km[c0+9]
            float w00 = tab[__popcll(qmr0 & kmA.x)];
            float w01 = tab[__popcll(qmr0 & kmA.y)];
            float w10 = tab[__popcll(qmr1 & kmA.x)];
            float w11 = tab[__popcll(qmr1 & kmA.y)];
            float w02 = tab[__popcll(qmr0 & kmB.x)];
            float w03 = tab[__popcll(qmr0 & kmB.y)];
            float w12 = tab[__popcll(qmr1 & kmB.x)];
            float w13 = tab[__popcll(qmr1 & kmB.y)];
            pf[kc][0] = f16x2pk(w00, w01);
            pf[kc][1] = f16x2pk(w10, w11);
            pf[kc][2] = f16x2pk(w02, w03);
            pf[kc][3] = f16x2pk(w12, w13);
            rsum0 += (w00 + w01) + (w02 + w03);
            rsum1 += (w10 + w11) + (w12 + w13);
        }

        // AV: acc[16q x 64d per warp] += P @ V (single fp16 pass)
        const uint32_t sV = sb + A_V + buf * 8192;
#pragma unroll
        for (int nt = 0; nt < 4; ++nt) {
            uint32_t bH[4][4];
#pragma unroll
            for (int kc = 0; kc < 4; ++kc) {
                uint32_t off = sw128((uint32_t)((kc * 16 + bRow) * 128 + nt * 32 + bColB));
                ldsm_x4t(bH[kc][0], bH[kc][1], bH[kc][2], bH[kc][3], sV + off);
            }
#pragma unroll
            for (int kc = 0; kc < 4; ++kc) {
                mma16816h(acc[nt * 2 + 0], pf[kc], &bH[kc][0]);
                mma16816h(acc[nt * 2 + 1], pf[kc], &bH[kc][2]);
            }
        }

        if (++buf >= NBUF) buf = 0;
    }

    // reduce row sums across the 4 lanes sharing each fragment row
    rsum0 += __shfl_xor_sync(0xFFFFFFFF, rsum0, 1);
    rsum0 += __shfl_xor_sync(0xFFFFFFFF, rsum0, 2);
    rsum1 += __shfl_xor_sync(0xFFFFFFFF, rsum1, 1);
    rsum1 += __shfl_xor_sync(0xFFFFFFFF, rsum1, 2);
    const float inv0 = 1.0f / rsum0;
    const float inv1 = 1.0f / rsum1;

    // epilogue: normalize, split-store ctx hi/lo (fp16)
    const size_t row0 = (mbase + q0 + wid * 16 + g) * EMBED + h * 64;
    const size_t row1 = (mbase + q0 + wid * 16 + g + 8) * EMBED + h * 64;
#pragma unroll
    for (int nt = 0; nt < 8; ++nt) {
        int col = nt * 8 + c0;
        float o0 = acc[nt][0] * inv0, o1 = acc[nt][1] * inv0;
        float o2 = acc[nt][2] * inv1, o3 = acc[nt][3] * inv1;
        __half h0 = __float2half_rn(o0), h1 = __float2half_rn(o1);
        __half h2 = __float2half_rn(o2), h3 = __float2half_rn(o3);
        __half2 hh0; hh0.x = h0; hh0.y = h1;
        __half2 hh1; hh1.x = h2; hh1.y = h3;
        __half2 ll0, ll1;
        ll0.x = __float2half_rn(o0 - __half2float(h0));
        ll0.y = __float2half_rn(o1 - __half2float(h1));
        ll1.x = __float2half_rn(o2 - __half2float(h2));
        ll1.y = __float2half_rn(o3 - __half2float(h3));
        *(__half2*)(g_ch + row0 + col) = hh0;
        *(__half2*)(g_cl + row0 + col) = ll0;
        *(__half2*)(g_ch + row1 + col) = hh1;
        *(__half2*)(g_cl + row1 + col) = ll1;
    }
}

// -------------------- launch --------------------
extern "C" void kernel_launch(void* const* d_in, const int* in_sizes, int n_in,
                              void* d_out, int out_size) {
    const float* x  = (const float*)d_in[0];
    const float* Wq = (const float*)d_in[1];
    const float* bq = (const float*)d_in[2];
    const float* Wk = (const float*)d_in[3];
    const float* bk = (const float*)d_in[4];
    const float* Wv = (const float*)d_in[5];
    const float* bv = (const float*)d_in[6];
    const float* Wo = (const float*)d_in[7];
    const float* bo = (const float*)d_in[8];
    float* out = (float*)d_out;

    cudaFuncSetAttribute(mma_gemm_kernel<0>, cudaFuncAttributeMaxDynamicSharedMemorySize, SMEM_MMA);
    cudaFuncSetAttribute(mma_gemm_kernel<1>, cudaFuncAttributeMaxDynamicSharedMemorySize, SMEM_MMA);
    cudaFuncSetAttribute(attn_kernel, cudaFuncAttributeMaxDynamicSharedMemorySize, A_TOTAL);

    convert_xw_kernel<<<8192, 256>>>(x, Wq, Wk, Wv, Wo);
    mma_gemm_kernel<0><<<dim3(32, 24), 256, SMEM_MMA>>>(bq, bk, bv, bo, nullptr);
    attn_kernel<<<dim3(32, 32), 128, A_TOTAL>>>();
    mma_gemm_kernel<1><<<dim3(32, 8), 256, SMEM_MMA>>>(bq, bk, bv, bo, out);
}

// round 13
// speedup vs baseline: 4.2653x; 1.1810x over previous
#include <cuda_runtime.h>
#include <cuda_fp16.h>
#include <cstdint>

// Problem constants
#define EMBED 1024
#define HEADS 16
#define BATCH 2
#define TSEQ  2048
#define MTOT  4096   // BATCH*TSEQ

// -------------------- device scratch --------------------
// masks stored TRANSPOSED: [head][m] so per-head tiles are contiguous
__device__ unsigned long long g_qm[HEADS * MTOT];
__device__ unsigned long long g_km[HEADS * MTOT];
__device__ __half g_vh[MTOT * EMBED];   // v projection, single fp16
__device__ __half g_xh[MTOT * EMBED];   // x, single fp16
__device__ __half g_wh[4096 * EMBED];   // Wq|Wk|Wv|Wo rows, single fp16
__device__ __half g_ch[MTOT * EMBED];   // ctx split hi/lo (written by attn)
__device__ __half g_cl[MTOT * EMBED];

// -------------------- helpers --------------------
__device__ __forceinline__ uint32_t smem_u32(const void* p) {
    uint32_t a;
    asm("{ .reg .u64 t; cvta.to.shared.u64 t, %1; cvt.u32.u64 %0, t; }" : "=r"(a) : "l"(p));
    return a;
}
__device__ __forceinline__ void ldsm_x4(uint32_t& r0, uint32_t& r1, uint32_t& r2,
                                        uint32_t& r3, uint32_t addr) {
    asm volatile("ldmatrix.sync.aligned.m8n8.x4.shared.b16 {%0,%1,%2,%3}, [%4];"
                 : "=r"(r0), "=r"(r1), "=r"(r2), "=r"(r3) : "r"(addr));
}
__device__ __forceinline__ void ldsm_x4t(uint32_t& r0, uint32_t& r1, uint32_t& r2,
                                         uint32_t& r3, uint32_t addr) {
    asm volatile("ldmatrix.sync.aligned.m8n8.x4.trans.shared.b16 {%0,%1,%2,%3}, [%4];"
                 : "=r"(r0), "=r"(r1), "=r"(r2), "=r"(r3) : "r"(addr));
}
__device__ __forceinline__ void mma16816h(float* d, const uint32_t* a, const uint32_t* b) {
    asm volatile(
        "mma.sync.aligned.m16n8k16.row.col.f32.f16.f16.f32 "
        "{%0,%1,%2,%3}, {%4,%5,%6,%7}, {%8,%9}, {%0,%1,%2,%3};"
        : "+f"(d[0]), "+f"(d[1]), "+f"(d[2]), "+f"(d[3])
        : "r"(a[0]), "r"(a[1]), "r"(a[2]), "r"(a[3]), "r"(b[0]), "r"(b[1]));
}
__device__ __forceinline__ void cpa16(uint32_t dst, const void* src) {
    asm volatile("cp.async.cg.shared.global [%0], [%1], 16;" :: "r"(dst), "l"(src));
}
#define CP_COMMIT()   asm volatile("cp.async.commit_group;" ::: "memory")
#define CP_WAIT_ALL() asm volatile("cp.async.wait_group 0;" ::: "memory")
#define CP_WAIT_1()   asm volatile("cp.async.wait_group 1;" ::: "memory")

__device__ __forceinline__ uint32_t sw128(uint32_t off) {
    return off ^ ((off >> 3) & 0x70);
}
// pack two fp32 (already exactly fp16-representable) into fp16x2: {lo, hi}
__device__ __forceinline__ uint32_t f16x2pk(float lo, float hi) {
    uint32_t r;
    asm("cvt.rn.f16x2.f32 %0, %2, %1;" : "=r"(r) : "f"(lo), "f"(hi));
    return r;
}

// -------------------- convert kernel: fp32 -> fp16 (x single + W single) --------------------
// grid 8192: blocks [0,4096) convert x, [4096,8192) convert W
__global__ __launch_bounds__(256) void convert_xw_kernel(
    const float* __restrict__ x,
    const float* __restrict__ Wq, const float* __restrict__ Wk,
    const float* __restrict__ Wv, const float* __restrict__ Wo) {
    __half* dst;
    const float* src;
    int i;
    if (blockIdx.x < 4096) {
        i = (blockIdx.x * 256 + threadIdx.x) * 4;
        src = x + i;
        dst = g_xh + i;
    } else {
        i = ((blockIdx.x - 4096) * 256 + threadIdx.x) * 4;
        int row = i >> 10, col = i & 1023;
        if (row < 1024)      src = Wq + (size_t)row * EMBED + col;
        else if (row < 2048) src = Wk + (size_t)(row - 1024) * EMBED + col;
        else if (row < 3072) src = Wv + (size_t)(row - 2048) * EMBED + col;
        else                 src = Wo + (size_t)(row - 3072) * EMBED + col;
        dst = g_wh + i;
    }
    float4 v = *(const float4*)src;
    __half2 a, b;
    a.x = __float2half_rn(v.x); a.y = __float2half_rn(v.y);
    b.x = __float2half_rn(v.z); b.y = __float2half_rn(v.w);
    *(__half2*)(dst)     = a;
    *(__half2*)(dst + 2) = b;
}

// -------------------- mma.sync GEMM (3-stage cp.async ring, fp16) --------------------
#define KC 32
#define TPAD 40
#define TILE_B (128 * TPAD * 2)   // 10240 B per sub-tile
#define GNBUF 3

// MODE 0: A = x (single pass), W rows 0..3071 (Wq|Wk|Wv). grid (32, 24).
//         SUBT=2: stage {AH, BH}. q/k -> spike masks, v -> fp16.
// MODE 1: A = ctx (2-pass, g_ch/g_cl), W rows 3072..4095 (Wo). grid (32, 8).
//         SUBT=3: stage {AH, AL, BH}.
template <int MODE>
__global__ __launch_bounds__(256, 2) void mma_gemm_kernel(
    const float* __restrict__ bq, const float* __restrict__ bk,
    const float* __restrict__ bv, const float* __restrict__ bo,
    float* __restrict__ outf)
{
    constexpr int SUBT = (MODE == 1) ? 3 : 2;
    constexpr int BUFB = SUBT * TILE_B;
    constexpr bool needLo = (MODE == 1);

    extern __shared__ char smem[];
    const int tid = threadIdx.x;
    const int wid = tid >> 5, lane = tid & 31;
    const int m0 = blockIdx.x * 128;
    const int nb_glob = blockIdx.y * 128;

    const int region = (MODE == 0) ? (nb_glob >> 10) : 3;   // 0 q, 1 k, 2 v, 3 out

    const __half* Ah = (MODE == 0) ? g_xh : g_ch;
    const int wrow0 = (MODE == 0) ? nb_glob : (3072 + nb_glob);
    const __half* Bh = g_wh + (size_t)wrow0 * EMBED;
    const __half* Aoff = Ah + (size_t)m0 * EMBED;
    const __half* ALoff = (MODE == 1) ? (g_cl + (size_t)m0 * EMBED) : Aoff;

    const int wm = wid >> 2, wn = wid & 3;
    const int mrow0 = wm * 64, ncol0 = wn * 32;

    const int aRow = lane & 15, aCol = (lane >> 4) * 8;
    const int bRow = ((lane >> 4) & 1) * 8 + (lane & 7);
    const int bCol = ((lane >> 3) & 1) * 8;

    float acc[4][4][4];
#pragma unroll
    for (int i = 0; i < 4; i++)
#pragma unroll
        for (int j = 0; j < 4; j++)
#pragma unroll
            for (int r = 0; r < 4; r++) acc[i][j][r] = 0.0f;

    const uint32_t sb = smem_u32(smem);

    auto issue = [&](int c_, int buf_) {
#pragma unroll
        for (int l = 0; l < 2 * SUBT; ++l) {
            const int sub = l >> 1;
            const int j = tid + (l & 1) * 256;
            const int r = j >> 2, gq = j & 3;
            const __half* src =
                (sub == 0) ? Aoff : ((sub == SUBT - 1) ? Bh : ALoff);
            uint32_t dst = sb + buf_ * BUFB + sub * TILE_B +
                           (uint32_t)(r * TPAD + gq * 8) * 2;
            cpa16(dst, src + (size_t)r * EMBED + c_ * KC + gq * 8);
        }
        CP_COMMIT();
    };

    issue(0, 0);
    issue(1, 1);

    int buf = 0;
    for (int c = 0; c < 32; ++c) {
        if (c < 31) CP_WAIT_1(); else CP_WAIT_ALL();
        __syncthreads();
        if (c < 30) {
            int nb = buf + 2; if (nb >= GNBUF) nb -= GNBUF;
            issue(c + 2, nb);
        }

        const uint32_t pAh = sb + buf * BUFB;
        const uint32_t pAl = pAh + TILE_B;               // only valid for MODE 1
        const uint32_t pBh = pAh + (SUBT - 1) * TILE_B;
#pragma unroll
        for (int kk = 0; kk < KC; kk += 16) {
            uint32_t aF[2][4][4], bF[4][2];
#pragma unroll
            for (int mi = 0; mi < 4; ++mi) {
                uint32_t off = (uint32_t)((mrow0 + mi * 16 + aRow) * TPAD + kk + aCol) * 2;
                ldsm_x4(aF[0][mi][0], aF[0][mi][1], aF[0][mi][2], aF[0][mi][3], pAh + off);
                if (needLo)
                    ldsm_x4(aF[1][mi][0], aF[1][mi][1], aF[1][mi][2], aF[1][mi][3], pAl + off);
            }
#pragma unroll
            for (int n2 = 0; n2 < 2; ++n2) {
                uint32_t off = (uint32_t)((ncol0 + n2 * 16 + bRow) * TPAD + kk + bCol) * 2;
                ldsm_x4(bF[n2 * 2][0], bF[n2 * 2][1],
                        bF[n2 * 2 + 1][0], bF[n2 * 2 + 1][1], pBh + off);
            }
#pragma unroll
            for (int mi = 0; mi < 4; ++mi)
#pragma unroll
                for (int ni = 0; ni < 4; ++ni) mma16816h(acc[mi][ni], aF[0][mi], bF[ni]);
            if (needLo) {
#pragma unroll
                for (int mi = 0; mi < 4; ++mi)
#pragma unroll
                    for (int ni = 0; ni < 4; ++ni) mma16816h(acc[mi][ni], aF[1][mi], bF[ni]);
            }
        }
        if (++buf >= GNBUF) buf = 0;
    }

    // ---- epilogue ----
    const int nloc = nb_glob & 1023;
    const float* bias = (MODE == 1) ? bo : ((region == 0) ? bq : ((region == 1) ? bk : bv));

    const int trow = lane >> 2;
    const int tcol = (lane & 3) * 2;

    if (region <= 1) {
        __syncthreads();
        unsigned char* Sb = (unsigned char*)smem;
#pragma unroll
        for (int mi = 0; mi < 4; ++mi)
#pragma unroll
            for (int ni = 0; ni < 4; ++ni)
#pragma unroll
                for (int ci = 0; ci < 4; ++ci) {
                    int gr = mrow0 + mi * 16 + trow + ((ci >> 1) ? 8 : 0);
                    int gc = ncol0 + ni * 8 + tcol + (ci & 1);
                    float v = acc[mi][ni][ci] + bias[nloc + gc];
                    Sb[gr * 128 + gc] = (unsigned char)(v >= 1.0f ? 1 : 0);
                }
        __syncthreads();
        int row = tid >> 1, half = tid & 1;
        const unsigned long long* pp = (const unsigned long long*)(Sb + row * 128 + half * 64);
        unsigned long long mask = 0;
#pragma unroll
        for (int w = 0; w < 8; ++w)
            mask |= (((pp[w] & 0x0101010101010101ULL) * 0x0102040810204080ULL) >> 56)
                    << (8 * w);
        unsigned long long* dst = (region == 0) ? g_qm : g_km;
        int h0 = nloc >> 6;
        dst[(size_t)(h0 + half) * MTOT + m0 + row] = mask;   // transposed layout
    } else if (MODE == 0) {
        // v region: single fp16 store
#pragma unroll
        for (int mi = 0; mi < 4; ++mi)
#pragma unroll
            for (int ni = 0; ni < 4; ++ni)
#pragma unroll
                for (int ci = 0; ci < 4; ci += 2) {
                    int gr = m0 + mrow0 + mi * 16 + trow + (ci ? 8 : 0);
                    int gc = ncol0 + ni * 8 + tcol;
                    int col = nloc + gc;
                    __half2 hh;
                    hh.x = __float2half_rn(acc[mi][ni][ci] + bias[col]);
                    hh.y = __float2half_rn(acc[mi][ni][ci + 1] + bias[col + 1]);
                    *(__half2*)(g_vh + (size_t)gr * EMBED + col) = hh;
                }
    } else {
#pragma unroll
        for (int mi = 0; mi < 4; ++mi)
#pragma unroll
            for (int ni = 0; ni < 4; ++ni)
#pragma unroll
                for (int ci = 0; ci < 4; ci += 2) {
                    int gr = m0 + mrow0 + mi * 16 + trow + (ci ? 8 : 0);
                    int gc = ncol0 + ni * 8 + tcol;
                    int col = nb_glob + gc;
                    float2 o;
                    o.x = acc[mi][ni][ci] + bias[col];
                    o.y = acc[mi][ni][ci + 1] + bias[col + 1];
                    *(float2*)(outf + (size_t)gr * EMBED + col) = o;
                }
    }
}

// -------------------- attention: in-register P fragments + 1-pass fp16 AV --------------------
// block 128 threads (4 warps). warp w: q rows [q0 + w*16, +16), full 64 d.
// V single fp16, 3-stage cp.async ring. P built directly in mma A-fragment registers.
#define NBUF 3
#define A_V   0                      // NBUF x 8192 (V tiles, SW128)
#define A_KM  (NBUF * 8192)          // NBUF x 512 (km tiles)
#define A_TAB (A_KM + NBUF * 512)    // 65 floats (fp16-exact values)
#define A_TOTAL (A_TAB + 512)

#define ATTN_ISSUE(t_, buf_) do {                                              \
    _Pragma("unroll")                                                          \
    for (int j = 0; j < 4; ++j) {                                              \
        int gi = tid + j * 128;                                                \
        int r = gi >> 3, cb = gi & 7;                                          \
        uint32_t off = sw128((uint32_t)(r * 128 + cb * 16));                   \
        cpa16(sb + A_V + (buf_) * 8192 + off,                                  \
              vhb + (size_t)((t_) * 64 + r) * EMBED + cb * 8);                 \
    }                                                                          \
    if (tid < 32) cpa16(sb + A_KM + (buf_) * 512 + tid * 16,                   \
                        kmb + (size_t)(t_) * 64 + tid * 2);                    \
    CP_COMMIT();                                                               \
} while (0)

__global__ __launch_bounds__(128) void attn_kernel() {
    extern __shared__ char smem[];
    const uint32_t sb = smem_u32(smem);
    const int tid = threadIdx.x;
    const int lane = tid & 31, wid = tid >> 5;
    const int qt = blockIdx.x;
    const int bh = blockIdx.y;
    const int b = bh >> 4, h = bh & 15;
    const int q0 = qt * 64;
    const size_t mbase = (size_t)b * TSEQ;

    const int g = lane >> 2;            // fragment row group
    const int c0 = (lane & 3) * 2;      // fragment col base

    const unsigned long long qmr0 =
        g_qm[(size_t)h * MTOT + mbase + q0 + wid * 16 + g];
    const unsigned long long qmr1 =
        g_qm[(size_t)h * MTOT + mbase + q0 + wid * 16 + g + 8];

    const __half* vhb = g_vh + mbase * EMBED + h * 64;
    const unsigned long long* kmb = g_km + (size_t)h * MTOT + mbase;

    // weight LUT (fp32 holding exactly-fp16 values => numerator/denominator consistent)
    if (tid < 65) {
        float w = exp2f((float)tid * 0.18033688011112042f);
        ((float*)(smem + A_TAB))[tid] = __half2float(__float2half_rn(w));
    }

    const int bRow = (lane & 7) + ((lane >> 3) & 1) * 8;
    const int bColB = ((lane >> 4) & 1) * 16;

    float acc[8][4];
#pragma unroll
    for (int i = 0; i < 8; i++)
#pragma unroll
        for (int j = 0; j < 4; j++) acc[i][j] = 0.0f;
    float rsum0 = 0.0f, rsum1 = 0.0f;

    ATTN_ISSUE(0, 0);
    ATTN_ISSUE(1, 1);

    int buf = 0;
    for (int kt = 0; kt < 32; ++kt) {
        if (kt < 31) CP_WAIT_1(); else CP_WAIT_ALL();
        __syncthreads();     // V[kt]/km[kt] visible; ring slot (kt+2)%3 fully consumed
        if (kt < 30) {
            int nb = buf + 2; if (nb >= NBUF) nb -= NBUF;
            ATTN_ISSUE(kt + 2, nb);
        }

        // build P fragments in registers
        const unsigned long long* kms =
            (const unsigned long long*)(smem + A_KM + buf * 512);
        const float* tab = (const float*)(smem + A_TAB);
        uint32_t pf[4][4];
#pragma unroll
        for (int kc = 0; kc < 4; ++kc) {
            ulonglong2 kmA = *(const ulonglong2*)(kms + kc * 16 + c0);
            ulonglong2 kmB = *(const ulonglong2*)(kms + kc * 16 + c0 + 8);
            float w00 = tab[__popcll(qmr0 & kmA.x)];
            float w01 = tab[__popcll(qmr0 & kmA.y)];
            float w10 = tab[__popcll(qmr1 & kmA.x)];
            float w11 = tab[__popcll(qmr1 & kmA.y)];
            float w02 = tab[__popcll(qmr0 & kmB.x)];
            float w03 = tab[__popcll(qmr0 & kmB.y)];
            float w12 = tab[__popcll(qmr1 & kmB.x)];
            float w13 = tab[__popcll(qmr1 & kmB.y)];
            pf[kc][0] = f16x2pk(w00, w01);
            pf[kc][1] = f16x2pk(w10, w11);
            pf[kc][2] = f16x2pk(w02, w03);
            pf[kc][3] = f16x2pk(w12, w13);
            rsum0 += (w00 + w01) + (w02 + w03);
            rsum1 += (w10 + w11) + (w12 + w13);
        }

        // AV: acc[16q x 64d per warp] += P @ V (single fp16 pass)
        const uint32_t sV = sb + A_V + buf * 8192;
#pragma unroll
        for (int nt = 0; nt < 4; ++nt) {
            uint32_t bH[4][4];
#pragma unroll
            for (int kc = 0; kc < 4; ++kc) {
                uint32_t off = sw128((uint32_t)((kc * 16 + bRow) * 128 + nt * 32 + bColB));
                ldsm_x4t(bH[kc][0], bH[kc][1], bH[kc][2], bH[kc][3], sV + off);
            }
#pragma unroll
            for (int kc = 0; kc < 4; ++kc) {
                mma16816h(acc[nt * 2 + 0], pf[kc], &bH[kc][0]);
                mma16816h(acc[nt * 2 + 1], pf[kc], &bH[kc][2]);
            }
        }

        if (++buf >= NBUF) buf = 0;
    }

    // reduce row sums across the 4 lanes sharing each fragment row
    rsum0 += __shfl_xor_sync(0xFFFFFFFF, rsum0, 1);
    rsum0 += __shfl_xor_sync(0xFFFFFFFF, rsum0, 2);
    rsum1 += __shfl_xor_sync(0xFFFFFFFF, rsum1, 1);
    rsum1 += __shfl_xor_sync(0xFFFFFFFF, rsum1, 2);
    const float inv0 = 1.0f / rsum0;
    const float inv1 = 1.0f / rsum1;

    // epilogue: normalize, split-store ctx hi/lo (fp16)
    const size_t row0 = (mbase + q0 + wid * 16 + g) * EMBED + h * 64;
    const size_t row1 = (mbase + q0 + wid * 16 + g + 8) * EMBED + h * 64;
#pragma unroll
    for (int nt = 0; nt < 8; ++nt) {
        int col = nt * 8 + c0;
        float o0 = acc[nt][0] * inv0, o1 = acc[nt][1] * inv0;
        float o2 = acc[nt][2] * inv1, o3 = acc[nt][3] * inv1;
        __half h0 = __float2half_rn(o0), h1 = __float2half_rn(o1);
        __half h2 = __float2half_rn(o2), h3 = __float2half_rn(o3);
        __half2 hh0; hh0.x = h0; hh0.y = h1;
        __half2 hh1; hh1.x = h2; hh1.y = h3;
        __half2 ll0, ll1;
        ll0.x = __float2half_rn(o0 - __half2float(h0));
        ll0.y = __float2half_rn(o1 - __half2float(h1));
        ll1.x = __float2half_rn(o2 - __half2float(h2));
        ll1.y = __float2half_rn(o3 - __half2float(h3));
        *(__half2*)(g_ch + row0 + col) = hh0;
        *(__half2*)(g_cl + row0 + col) = ll0;
        *(__half2*)(g_ch + row1 + col) = hh1;
        *(__half2*)(g_cl + row1 + col) = ll1;
    }
}

// -------------------- launch --------------------
extern "C" void kernel_launch(void* const* d_in, const int* in_sizes, int n_in,
                              void* d_out, int out_size) {
    const float* x  = (const float*)d_in[0];
    const float* Wq = (const float*)d_in[1];
    const float* bq = (const float*)d_in[2];
    const float* Wk = (const float*)d_in[3];
    const float* bk = (const float*)d_in[4];
    const float* Wv = (const float*)d_in[5];
    const float* bv = (const float*)d_in[6];
    const float* Wo = (const float*)d_in[7];
    const float* bo = (const float*)d_in[8];
    float* out = (float*)d_out;

    const int SMEM_G0 = GNBUF * 2 * TILE_B;   // 61440
    const int SMEM_G1 = GNBUF * 3 * TILE_B;   // 92160
    cudaFuncSetAttribute(mma_gemm_kernel<0>, cudaFuncAttributeMaxDynamicSharedMemorySize, SMEM_G0);
    cudaFuncSetAttribute(mma_gemm_kernel<1>, cudaFuncAttributeMaxDynamicSharedMemorySize, SMEM_G1);
    cudaFuncSetAttribute(attn_kernel, cudaFuncAttributeMaxDynamicSharedMemorySize, A_TOTAL);

    convert_xw_kernel<<<8192, 256>>>(x, Wq, Wk, Wv, Wo);
    mma_gemm_kernel<0><<<dim3(32, 24), 256, SMEM_G0>>>(bq, bk, bv, bo, nullptr);
    attn_kernel<<<dim3(32, 32), 128, A_TOTAL>>>();
    mma_gemm_kernel<1><<<dim3(32, 8), 256, SMEM_G1>>>(bq, bk, bv, bo, out);
}

// round 15
// speedup vs baseline: 4.7752x; 1.1195x over previous
#include <cuda_runtime.h>
#include <cuda_fp16.h>
#include <cstdint>

// Problem constants
#define EMBED 1024
#define HEADS 16
#define BATCH 2
#define TSEQ  2048
#define MTOT  4096   // BATCH*TSEQ

// -------------------- device scratch --------------------
// masks stored TRANSPOSED: [head][m] so per-head tiles are contiguous
__device__ unsigned long long g_qm[HEADS * MTOT];
__device__ unsigned long long g_km[HEADS * MTOT];
__device__ __half g_vh[MTOT * EMBED];   // v projection, single fp16
__device__ __half g_xh[MTOT * EMBED];   // x, single fp16
__device__ __half g_wh[4096 * EMBED];   // Wq|Wk|Wv|Wo rows, single fp16
__device__ __half g_ch[MTOT * EMBED];   // ctx, single fp16 (written by attn)

// -------------------- helpers --------------------
__device__ __forceinline__ uint32_t smem_u32(const void* p) {
    uint32_t a;
    asm("{ .reg .u64 t; cvta.to.shared.u64 t, %1; cvt.u32.u64 %0, t; }" : "=r"(a) : "l"(p));
    return a;
}
__device__ __forceinline__ void ldsm_x4(uint32_t& r0, uint32_t& r1, uint32_t& r2,
                                        uint32_t& r3, uint32_t addr) {
    asm volatile("ldmatrix.sync.aligned.m8n8.x4.shared.b16 {%0,%1,%2,%3}, [%4];"
                 : "=r"(r0), "=r"(r1), "=r"(r2), "=r"(r3) : "r"(addr));
}
__device__ __forceinline__ void ldsm_x4t(uint32_t& r0, uint32_t& r1, uint32_t& r2,
                                         uint32_t& r3, uint32_t addr) {
    asm volatile("ldmatrix.sync.aligned.m8n8.x4.trans.shared.b16 {%0,%1,%2,%3}, [%4];"
                 : "=r"(r0), "=r"(r1), "=r"(r2), "=r"(r3) : "r"(addr));
}
__device__ __forceinline__ void mma16816h(float* d, const uint32_t* a, const uint32_t* b) {
    asm volatile(
        "mma.sync.aligned.m16n8k16.row.col.f32.f16.f16.f32 "
        "{%0,%1,%2,%3}, {%4,%5,%6,%7}, {%8,%9}, {%0,%1,%2,%3};"
        : "+f"(d[0]), "+f"(d[1]), "+f"(d[2]), "+f"(d[3])
        : "r"(a[0]), "r"(a[1]), "r"(a[2]), "r"(a[3]), "r"(b[0]), "r"(b[1]));
}
__device__ __forceinline__ void cpa16(uint32_t dst, const void* src) {
    asm volatile("cp.async.cg.shared.global [%0], [%1], 16;" :: "r"(dst), "l"(src));
}
#define CP_COMMIT()   asm volatile("cp.async.commit_group;" ::: "memory")
#define CP_WAIT_ALL() asm volatile("cp.async.wait_group 0;" ::: "memory")
#define CP_WAIT_1()   asm volatile("cp.async.wait_group 1;" ::: "memory")

__device__ __forceinline__ uint32_t sw128(uint32_t off) {
    return off ^ ((off >> 3) & 0x70);
}
// pack two fp32 (already exactly fp16-representable) into fp16x2: {lo, hi}
__device__ __forceinline__ uint32_t f16x2pk(float lo, float hi) {
    uint32_t r;
    asm("cvt.rn.f16x2.f32 %0, %2, %1;" : "=r"(r) : "f"(lo), "f"(hi));
    return r;
}

// -------------------- convert kernel: fp32 -> fp16 (x + W) --------------------
// grid 8192: blocks [0,4096) convert x, [4096,8192) convert W
__global__ __launch_bounds__(256) void convert_xw_kernel(
    const float* __restrict__ x,
    const float* __restrict__ Wq, const float* __restrict__ Wk,
    const float* __restrict__ Wv, const float* __restrict__ Wo) {
    __half* dst;
    const float* src;
    int i;
    if (blockIdx.x < 4096) {
        i = (blockIdx.x * 256 + threadIdx.x) * 4;
        src = x + i;
        dst = g_xh + i;
    } else {
        i = ((blockIdx.x - 4096) * 256 + threadIdx.x) * 4;
        int row = i >> 10, col = i & 1023;
        if (row < 1024)      src = Wq + (size_t)row * EMBED + col;
        else if (row < 2048) src = Wk + (size_t)(row - 1024) * EMBED + col;
        else if (row < 3072) src = Wv + (size_t)(row - 2048) * EMBED + col;
        else                 src = Wo + (size_t)(row - 3072) * EMBED + col;
        dst = g_wh + i;
    }
    float4 v = *(const float4*)src;
    __half2 a, b;
    a.x = __float2half_rn(v.x); a.y = __float2half_rn(v.y);
    b.x = __float2half_rn(v.z); b.y = __float2half_rn(v.w);
    *(__half2*)(dst)     = a;
    *(__half2*)(dst + 2) = b;
}

// -------------------- mma.sync GEMM (3-stage cp.async ring, fp16, single pass) --------------------
#define KC 32
#define TPAD 40
#define TILE_B (128 * TPAD * 2)   // 10240 B per sub-tile
#define GNBUF 3
#define BUFB (2 * TILE_B)         // {A, B} per stage
#define SMEM_G (GNBUF * BUFB)     // 61440

// MODE 0: A = x, W rows 0..3071 (Wq|Wk|Wv). grid (32, 24). q/k -> masks, v -> fp16.
// MODE 1: A = ctx, W rows 3072..4095 (Wo). grid (32, 8). -> fp32 out.
template <int MODE>
__global__ __launch_bounds__(256, 2) void mma_gemm_kernel(
    const float* __restrict__ bq, const float* __restrict__ bk,
    const float* __restrict__ bv, const float* __restrict__ bo,
    float* __restrict__ outf)
{
    extern __shared__ char smem[];
    const int tid = threadIdx.x;
    const int wid = tid >> 5, lane = tid & 31;
    const int m0 = blockIdx.x * 128;
    const int nb_glob = blockIdx.y * 128;

    const int region = (MODE == 0) ? (nb_glob >> 10) : 3;   // 0 q, 1 k, 2 v, 3 out

    const __half* Ah = (MODE == 0) ? g_xh : g_ch;
    const int wrow0 = (MODE == 0) ? nb_glob : (3072 + nb_glob);
    const __half* Bh = g_wh + (size_t)wrow0 * EMBED;
    const __half* Aoff = Ah + (size_t)m0 * EMBED;

    const int wm = wid >> 2, wn = wid & 3;
    const int mrow0 = wm * 64, ncol0 = wn * 32;

    const int aRow = lane & 15, aCol = (lane >> 4) * 8;
    const int bRow = ((lane >> 4) & 1) * 8 + (lane & 7);
    const int bCol = ((lane >> 3) & 1) * 8;

    float acc[4][4][4];
#pragma unroll
    for (int i = 0; i < 4; i++)
#pragma unroll
        for (int j = 0; j < 4; j++)
#pragma unroll
            for (int r = 0; r < 4; r++) acc[i][j][r] = 0.0f;

    const uint32_t sb = smem_u32(smem);

    auto issue = [&](int c_, int buf_) {
#pragma unroll
        for (int l = 0; l < 4; ++l) {
            const int sub = l >> 1;
            const int j = tid + (l & 1) * 256;
            const int r = j >> 2, gq = j & 3;
            const __half* src = (sub == 0) ? Aoff : Bh;
            uint32_t dst = sb + buf_ * BUFB + sub * TILE_B +
                           (uint32_t)(r * TPAD + gq * 8) * 2;
            cpa16(dst, src + (size_t)r * EMBED + c_ * KC + gq * 8);
        }
        CP_COMMIT();
    };

    issue(0, 0);
    issue(1, 1);

    int buf = 0;
    for (int c = 0; c < 32; ++c) {
        if (c < 31) CP_WAIT_1(); else CP_WAIT_ALL();
        __syncthreads();
        if (c < 30) {
            int nb = buf + 2; if (nb >= GNBUF) nb -= GNBUF;
            issue(c + 2, nb);
        }

        const uint32_t pAh = sb + buf * BUFB;
        const uint32_t pBh = pAh + TILE_B;
#pragma unroll
        for (int kk = 0; kk < KC; kk += 16) {
            uint32_t aF[4][4], bF[4][2];
#pragma unroll
            for (int mi = 0; mi < 4; ++mi) {
                uint32_t off = (uint32_t)((mrow0 + mi * 16 + aRow) * TPAD + kk + aCol) * 2;
                ldsm_x4(aF[mi][0], aF[mi][1], aF[mi][2], aF[mi][3], pAh + off);
            }
#pragma unroll
            for (int n2 = 0; n2 < 2; ++n2) {
                uint32_t off = (uint32_t)((ncol0 + n2 * 16 + bRow) * TPAD + kk + bCol) * 2;
                ldsm_x4(bF[n2 * 2][0], bF[n2 * 2][1],
                        bF[n2 * 2 + 1][0], bF[n2 * 2 + 1][1], pBh + off);
            }
#pragma unroll
            for (int mi = 0; mi < 4; ++mi)
#pragma unroll
                for (int ni = 0; ni < 4; ++ni) mma16816h(acc[mi][ni], aF[mi], bF[ni]);
        }
        if (++buf >= GNBUF) buf = 0;
    }

    // ---- epilogue ----
    const int nloc = nb_glob & 1023;
    const float* bias = (MODE == 1) ? bo : ((region == 0) ? bq : ((region == 1) ? bk : bv));

    const int trow = lane >> 2;
    const int tcol = (lane & 3) * 2;

    if (region <= 1) {
        __syncthreads();
        unsigned char* Sb = (unsigned char*)smem;
#pragma unroll
        for (int mi = 0; mi < 4; ++mi)
#pragma unroll
            for (int ni = 0; ni < 4; ++ni)
#pragma unroll
                for (int ci = 0; ci < 4; ++ci) {
                    int gr = mrow0 + mi * 16 + trow + ((ci >> 1) ? 8 : 0);
                    int gc = ncol0 + ni * 8 + tcol + (ci & 1);
                    float v = acc[mi][ni][ci] + bias[nloc + gc];
                    Sb[gr * 128 + gc] = (unsigned char)(v >= 1.0f ? 1 : 0);
                }
        __syncthreads();
        int row = tid >> 1, half = tid & 1;
        const unsigned long long* pp = (const unsigned long long*)(Sb + row * 128 + half * 64);
        unsigned long long mask = 0;
#pragma unroll
        for (int w = 0; w < 8; ++w)
            mask |= (((pp[w] & 0x0101010101010101ULL) * 0x0102040810204080ULL) >> 56)
                    << (8 * w);
        unsigned long long* dst = (region == 0) ? g_qm : g_km;
        int h0 = nloc >> 6;
        dst[(size_t)(h0 + half) * MTOT + m0 + row] = mask;   // transposed layout
    } else if (MODE == 0) {
        // v region: single fp16 store
#pragma unroll
        for (int mi = 0; mi < 4; ++mi)
#pragma unroll
            for (int ni = 0; ni < 4; ++ni)
#pragma unroll
                for (int ci = 0; ci < 4; ci += 2) {
                    int gr = m0 + mrow0 + mi * 16 + trow + (ci ? 8 : 0);
                    int gc = ncol0 + ni * 8 + tcol;
                    int col = nloc + gc;
                    __half2 hh;
                    hh.x = __float2half_rn(acc[mi][ni][ci] + bias[col]);
                    hh.y = __float2half_rn(acc[mi][ni][ci + 1] + bias[col + 1]);
                    *(__half2*)(g_vh + (size_t)gr * EMBED + col) = hh;
                }
    } else {
#pragma unroll
        for (int mi = 0; mi < 4; ++mi)
#pragma unroll
            for (int ni = 0; ni < 4; ++ni)
#pragma unroll
                for (int ci = 0; ci < 4; ci += 2) {
                    int gr = m0 + mrow0 + mi * 16 + trow + (ci ? 8 : 0);
                    int gc = ncol0 + ni * 8 + tcol;
                    int col = nb_glob + gc;
                    float2 o;
                    o.x = acc[mi][ni][ci] + bias[col];
                    o.y = acc[mi][ni][ci + 1] + bias[col + 1];
                    *(float2*)(outf + (size_t)gr * EMBED + col) = o;
                }
    }
}

// -------------------- attention: in-register P fragments + 1-pass fp16 AV --------------------
// block 128 threads (4 warps). warp w: q rows [q0 + w*16, +16), full 64 d.
// V single fp16, 3-stage cp.async ring. P built directly in mma A-fragment registers.
#define NBUF 3
#define A_V   0                      // NBUF x 8192 (V tiles, SW128)
#define A_KM  (NBUF * 8192)          // NBUF x 512 (km tiles)
#define A_TAB (A_KM + NBUF * 512)    // 65 floats (fp16-exact values)
#define A_TOTAL (A_TAB + 512)

#define ATTN_ISSUE(t_, buf_) do {                                              \
    _Pragma("unroll")                                                          \
    for (int j = 0; j < 4; ++j) {                                              \
        int gi = tid + j * 128;                                                \
        int r = gi >> 3, cb = gi & 7;                                          \
        uint32_t off = sw128((uint32_t)(r * 128 + cb * 16));                   \
        cpa16(sb + A_V + (buf_) * 8192 + off,                                  \
              vhb + (size_t)((t_) * 64 + r) * EMBED + cb * 8);                 \
    }                                                                          \
    if (tid < 32) cpa16(sb + A_KM + (buf_) * 512 + tid * 16,                   \
                        kmb + (size_t)(t_) * 64 + tid * 2);                    \
    CP_COMMIT();                                                               \
} while (0)

__global__ __launch_bounds__(128) void attn_kernel() {
    extern __shared__ char smem[];
    const uint32_t sb = smem_u32(smem);
    const int tid = threadIdx.x;
    const int lane = tid & 31, wid = tid >> 5;
    const int qt = blockIdx.x;
    const int bh = blockIdx.y;
    const int b = bh >> 4, h = bh & 15;
    const int q0 = qt * 64;
    const size_t mbase = (size_t)b * TSEQ;

    const int g = lane >> 2;            // fragment row group
    const int c0 = (lane & 3) * 2;      // fragment col base

    const unsigned long long qmr0 =
        g_qm[(size_t)h * MTOT + mbase + q0 + wid * 16 + g];
    const unsigned long long qmr1 =
        g_qm[(size_t)h * MTOT + mbase + q0 + wid * 16 + g + 8];

    const __half* vhb = g_vh + mbase * EMBED + h * 64;
    const unsigned long long* kmb = g_km + (size_t)h * MTOT + mbase;

    // weight LUT (fp32 holding exactly-fp16 values => numerator/denominator consistent)
    if (tid < 65) {
        float w = exp2f((float)tid * 0.18033688011112042f);
        ((float*)(smem + A_TAB))[tid] = __half2float(__float2half_rn(w));
    }

    const int bRow = (lane & 7) + ((lane >> 3) & 1) * 8;
    const int bColB = ((lane >> 4) & 1) * 16;

    float acc[8][4];
#pragma unroll
    for (int i = 0; i < 8; i++)
#pragma unroll
        for (int j = 0; j < 4; j++) acc[i][j] = 0.0f;
    float rsum0 = 0.0f, rsum1 = 0.0f;

    ATTN_ISSUE(0, 0);
    ATTN_ISSUE(1, 1);

    int buf = 0;
    for (int kt = 0; kt < 32; ++kt) {
        if (kt < 31) CP_WAIT_1(); else CP_WAIT_ALL();
        __syncthreads();     // V[kt]/km[kt] visible; ring slot (kt+2)%3 fully consumed
        if (kt < 30) {
            int nb = buf + 2; if (nb >= NBUF) nb -= NBUF;
            ATTN_ISSUE(kt + 2, nb);
        }

        // build P fragments in registers
        const unsigned long long* kms =
            (const unsigned long long*)(smem + A_KM + buf * 512);
        const float* tab = (const float*)(smem + A_TAB);
        uint32_t pf[4][4];
#pragma unroll
        for (int kc = 0; kc < 4; ++kc) {
            ulonglong2 kmA = *(const ulonglong2*)(kms + kc * 16 + c0);
            ulonglong2 kmB = *(const ulonglong2*)(kms + kc * 16 + c0 + 8);
            float w00 = tab[__popcll(qmr0 & kmA.x)];
            float w01 = tab[__popcll(qmr0 & kmA.y)];
            float w10 = tab[__popcll(qmr1 & kmA.x)];
            float w11 = tab[__popcll(qmr1 & kmA.y)];
            float w02 = tab[__popcll(qmr0 & kmB.x)];
            float w03 = tab[__popcll(qmr0 & kmB.y)];
            float w12 = tab[__popcll(qmr1 & kmB.x)];
            float w13 = tab[__popcll(qmr1 & kmB.y)];
            pf[kc][0] = f16x2pk(w00, w01);
            pf[kc][1] = f16x2pk(w10, w11);
            pf[kc][2] = f16x2pk(w02, w03);
            pf[kc][3] = f16x2pk(w12, w13);
            rsum0 += (w00 + w01) + (w02 + w03);
            rsum1 += (w10 + w11) + (w12 + w13);
        }

        // AV: acc[16q x 64d per warp] += P @ V (single fp16 pass)
        const uint32_t sV = sb + A_V + buf * 8192;
#pragma unroll
        for (int nt = 0; nt < 4; ++nt) {
            uint32_t bH[4][4];
#pragma unroll
            for (int kc = 0; kc < 4; ++kc) {
                uint32_t off = sw128((uint32_t)((kc * 16 + bRow) * 128 + nt * 32 + bColB));
                ldsm_x4t(bH[kc][0], bH[kc][1], bH[kc][2], bH[kc][3], sV + off);
            }
#pragma unroll
            for (int kc = 0; kc < 4; ++kc) {
                mma16816h(acc[nt * 2 + 0], pf[kc], &bH[kc][0]);
                mma16816h(acc[nt * 2 + 1], pf[kc], &bH[kc][2]);
            }
        }

        if (++buf >= NBUF) buf = 0;
    }

    // reduce row sums across the 4 lanes sharing each fragment row
    rsum0 += __shfl_xor_sync(0xFFFFFFFF, rsum0, 1);
    rsum0 += __shfl_xor_sync(0xFFFFFFFF, rsum0, 2);
    rsum1 += __shfl_xor_sync(0xFFFFFFFF, rsum1, 1);
    rsum1 += __shfl_xor_sync(0xFFFFFFFF, rsum1, 2);
    const float inv0 = 1.0f / rsum0;
    const float inv1 = 1.0f / rsum1;

    // epilogue: normalize, single fp16 ctx store
    const size_t row0 = (mbase + q0 + wid * 16 + g) * EMBED + h * 64;
    const size_t row1 = (mbase + q0 + wid * 16 + g + 8) * EMBED + h * 64;
#pragma unroll
    for (int nt = 0; nt < 8; ++nt) {
        int col = nt * 8 + c0;
        __half2 hh0, hh1;
        hh0.x = __float2half_rn(acc[nt][0] * inv0);
        hh0.y = __float2half_rn(acc[nt][1] * inv0);
        hh1.x = __float2half_rn(acc[nt][2] * inv1);
        hh1.y = __float2half_rn(acc[nt][3] * inv1);
        *(__half2*)(g_ch + row0 + col) = hh0;
        *(__half2*)(g_ch + row1 + col) = hh1;
    }
}

// -------------------- launch --------------------
extern "C" void kernel_launch(void* const* d_in, const int* in_sizes, int n_in,
                              void* d_out, int out_size) {
    const float* x  = (const float*)d_in[0];
    const float* Wq = (const float*)d_in[1];
    const float* bq = (const float*)d_in[2];
    const float* Wk = (const float*)d_in[3];
    const float* bk = (const float*)d_in[4];
    const float* Wv = (const float*)d_in[5];
    const float* bv = (const float*)d_in[6];
    const float* Wo = (const float*)d_in[7];
    const float* bo = (const float*)d_in[8];
    float* out = (float*)d_out;

    cudaFuncSetAttribute(mma_gemm_kernel<0>, cudaFuncAttributeMaxDynamicSharedMemorySize, SMEM_G);
    cudaFuncSetAttribute(mma_gemm_kernel<1>, cudaFuncAttributeMaxDynamicSharedMemorySize, SMEM_G);
    cudaFuncSetAttribute(attn_kernel, cudaFuncAttributeMaxDynamicSharedMemorySize, A_TOTAL);

    convert_xw_kernel<<<8192, 256>>>(x, Wq, Wk, Wv, Wo);
    mma_gemm_kernel<0><<<dim3(32, 24), 256, SMEM_G>>>(bq, bk, bv, bo, nullptr);
    attn_kernel<<<dim3(32, 32), 128, A_TOTAL>>>();
    mma_gemm_kernel<1><<<dim3(32, 8), 256, SMEM_G>>>(bq, bk, bv, bo, out);
}

// round 16
// speedup vs baseline: 4.9001x; 1.0262x over previous
#include <cuda_runtime.h>
#include <cuda_fp16.h>
#include <cstdint>

// Problem constants
#define EMBED 1024
#define HEADS 16
#define BATCH 2
#define TSEQ  2048
#define MTOT  4096   // BATCH*TSEQ

// -------------------- device scratch --------------------
// masks stored TRANSPOSED: [head][m] so per-head tiles are contiguous
__device__ unsigned long long g_qm[HEADS * MTOT];
__device__ unsigned long long g_km[HEADS * MTOT];
__device__ __half g_vh[MTOT * EMBED];   // v projection, single fp16
__device__ __half g_xh[MTOT * EMBED];   // x, single fp16
__device__ __half g_wh[4096 * EMBED];   // Wq|Wk|Wv|Wo rows, single fp16
__device__ __half g_ch[MTOT * EMBED];   // ctx, single fp16 (written by attn)

// -------------------- helpers --------------------
__device__ __forceinline__ uint32_t smem_u32(const void* p) {
    uint32_t a;
    asm("{ .reg .u64 t; cvta.to.shared.u64 t, %1; cvt.u32.u64 %0, t; }" : "=r"(a) : "l"(p));
    return a;
}
__device__ __forceinline__ void ldsm_x4(uint32_t& r0, uint32_t& r1, uint32_t& r2,
                                        uint32_t& r3, uint32_t addr) {
    asm volatile("ldmatrix.sync.aligned.m8n8.x4.shared.b16 {%0,%1,%2,%3}, [%4];"
                 : "=r"(r0), "=r"(r1), "=r"(r2), "=r"(r3) : "r"(addr));
}
__device__ __forceinline__ void ldsm_x4t(uint32_t& r0, uint32_t& r1, uint32_t& r2,
                                         uint32_t& r3, uint32_t addr) {
    asm volatile("ldmatrix.sync.aligned.m8n8.x4.trans.shared.b16 {%0,%1,%2,%3}, [%4];"
                 : "=r"(r0), "=r"(r1), "=r"(r2), "=r"(r3) : "r"(addr));
}
__device__ __forceinline__ void mma16816h(float* d, const uint32_t* a, const uint32_t* b) {
    asm volatile(
        "mma.sync.aligned.m16n8k16.row.col.f32.f16.f16.f32 "
        "{%0,%1,%2,%3}, {%4,%5,%6,%7}, {%8,%9}, {%0,%1,%2,%3};"
        : "+f"(d[0]), "+f"(d[1]), "+f"(d[2]), "+f"(d[3])
        : "r"(a[0]), "r"(a[1]), "r"(a[2]), "r"(a[3]), "r"(b[0]), "r"(b[1]));
}
__device__ __forceinline__ void cpa16(uint32_t dst, const void* src) {
    asm volatile("cp.async.cg.shared.global [%0], [%1], 16;" :: "r"(dst), "l"(src));
}
#define CP_COMMIT()   asm volatile("cp.async.commit_group;" ::: "memory")
#define CP_WAIT_ALL() asm volatile("cp.async.wait_group 0;" ::: "memory")
#define CP_WAIT_1()   asm volatile("cp.async.wait_group 1;" ::: "memory")

__device__ __forceinline__ uint32_t sw128(uint32_t off) {
    return off ^ ((off >> 3) & 0x70);
}
// pack two fp32 (already exactly fp16-representable) into fp16x2: {lo, hi}
__device__ __forceinline__ uint32_t f16x2pk(float lo, float hi) {
    uint32_t r;
    asm("cvt.rn.f16x2.f32 %0, %2, %1;" : "=r"(r) : "f"(lo), "f"(hi));
    return r;
}

// -------------------- convert kernel: fp32 -> fp16 (x + W) --------------------
// grid 8192: blocks [0,4096) convert x, [4096,8192) convert W
__global__ __launch_bounds__(256) void convert_xw_kernel(
    const float* __restrict__ x,
    const float* __restrict__ Wq, const float* __restrict__ Wk,
    const float* __restrict__ Wv, const float* __restrict__ Wo) {
    __half* dst;
    const float* src;
    int i;
    if (blockIdx.x < 4096) {
        i = (blockIdx.x * 256 + threadIdx.x) * 4;
        src = x + i;
        dst = g_xh + i;
    } else {
        i = ((blockIdx.x - 4096) * 256 + threadIdx.x) * 4;
        int row = i >> 10, col = i & 1023;
        if (row < 1024)      src = Wq + (size_t)row * EMBED + col;
        else if (row < 2048) src = Wk + (size_t)(row - 1024) * EMBED + col;
        else if (row < 3072) src = Wv + (size_t)(row - 2048) * EMBED + col;
        else                 src = Wo + (size_t)(row - 3072) * EMBED + col;
        dst = g_wh + i;
    }
    float4 v = *(const float4*)src;
    __half2 a, b;
    a.x = __float2half_rn(v.x); a.y = __float2half_rn(v.y);
    b.x = __float2half_rn(v.z); b.y = __float2half_rn(v.w);
    *(__half2*)(dst)     = a;
    *(__half2*)(dst + 2) = b;
}

// -------------------- mma.sync GEMM (3-stage cp.async ring, fp16, single pass) --------------------
#define KC 32
#define TPAD 40
#define TILE_B (128 * TPAD * 2)   // 10240 B per sub-tile
#define GNBUF 3
#define BUFB (2 * TILE_B)         // {A, B} per stage
#define SMEM_G (GNBUF * BUFB)     // 61440

// MODE 0: A = x, W rows 0..3071 (Wq|Wk|Wv). grid (32, 24). q/k -> masks, v -> fp16.
// MODE 1: A = ctx, W rows 3072..4095 (Wo). grid (32, 8). -> fp32 out.
template <int MODE>
__global__ __launch_bounds__(256, 2) void mma_gemm_kernel(
    const float* __restrict__ bq, const float* __restrict__ bk,
    const float* __restrict__ bv, const float* __restrict__ bo,
    float* __restrict__ outf)
{
    extern __shared__ char smem[];
    const int tid = threadIdx.x;
    const int wid = tid >> 5, lane = tid & 31;
    const int m0 = blockIdx.x * 128;
    const int nb_glob = blockIdx.y * 128;

    const int region = (MODE == 0) ? (nb_glob >> 10) : 3;   // 0 q, 1 k, 2 v, 3 out

    const __half* Ah = (MODE == 0) ? g_xh : g_ch;
    const int wrow0 = (MODE == 0) ? nb_glob : (3072 + nb_glob);
    const __half* Bh = g_wh + (size_t)wrow0 * EMBED;
    const __half* Aoff = Ah + (size_t)m0 * EMBED;

    const int wm = wid >> 2, wn = wid & 3;
    const int mrow0 = wm * 64, ncol0 = wn * 32;

    const int aRow = lane & 15, aCol = (lane >> 4) * 8;
    const int bRow = ((lane >> 4) & 1) * 8 + (lane & 7);
    const int bCol = ((lane >> 3) & 1) * 8;

    float acc[4][4][4];
#pragma unroll
    for (int i = 0; i < 4; i++)
#pragma unroll
        for (int j = 0; j < 4; j++)
#pragma unroll
            for (int r = 0; r < 4; r++) acc[i][j][r] = 0.0f;

    const uint32_t sb = smem_u32(smem);

    auto issue = [&](int c_, int buf_) {
#pragma unroll
        for (int l = 0; l < 4; ++l) {
            const int sub = l >> 1;
            const int j = tid + (l & 1) * 256;
            const int r = j >> 2, gq = j & 3;
            const __half* src = (sub == 0) ? Aoff : Bh;
            uint32_t dst = sb + buf_ * BUFB + sub * TILE_B +
                           (uint32_t)(r * TPAD + gq * 8) * 2;
            cpa16(dst, src + (size_t)r * EMBED + c_ * KC + gq * 8);
        }
        CP_COMMIT();
    };

    issue(0, 0);
    issue(1, 1);

    int buf = 0;
    for (int c = 0; c < 32; ++c) {
        if (c < 31) CP_WAIT_1(); else CP_WAIT_ALL();
        __syncthreads();
        if (c < 30) {
            int nb = buf + 2; if (nb >= GNBUF) nb -= GNBUF;
            issue(c + 2, nb);
        }

        const uint32_t pAh = sb + buf * BUFB;
        const uint32_t pBh = pAh + TILE_B;
#pragma unroll
        for (int kk = 0; kk < KC; kk += 16) {
            uint32_t aF[4][4], bF[4][2];
#pragma unroll
            for (int mi = 0; mi < 4; ++mi) {
                uint32_t off = (uint32_t)((mrow0 + mi * 16 + aRow) * TPAD + kk + aCol) * 2;
                ldsm_x4(aF[mi][0], aF[mi][1], aF[mi][2], aF[mi][3], pAh + off);
            }
#pragma unroll
            for (int n2 = 0; n2 < 2; ++n2) {
                uint32_t off = (uint32_t)((ncol0 + n2 * 16 + bRow) * TPAD + kk + bCol) * 2;
                ldsm_x4(bF[n2 * 2][0], bF[n2 * 2][1],
                        bF[n2 * 2 + 1][0], bF[n2 * 2 + 1][1], pBh + off);
            }
#pragma unroll
            for (int mi = 0; mi < 4; ++mi)
#pragma unroll
                for (int ni = 0; ni < 4; ++ni) mma16816h(acc[mi][ni], aF[mi], bF[ni]);
        }
        if (++buf >= GNBUF) buf = 0;
    }

    // ---- epilogue ----
    const int nloc = nb_glob & 1023;
    const float* bias = (MODE == 1) ? bo : ((region == 0) ? bq : ((region == 1) ? bk : bv));

    const int trow = lane >> 2;
    const int tcol = (lane & 3) * 2;

    if (region <= 1) {
        __syncthreads();
        unsigned char* Sb = (unsigned char*)smem;
#pragma unroll
        for (int mi = 0; mi < 4; ++mi)
#pragma unroll
            for (int ni = 0; ni < 4; ++ni)
#pragma unroll
                for (int ci = 0; ci < 4; ++ci) {
                    int gr = mrow0 + mi * 16 + trow + ((ci >> 1) ? 8 : 0);
                    int gc = ncol0 + ni * 8 + tcol + (ci & 1);
                    float v = acc[mi][ni][ci] + bias[nloc + gc];
                    Sb[gr * 128 + gc] = (unsigned char)(v >= 1.0f ? 1 : 0);
                }
        __syncthreads();
        int row = tid >> 1, half = tid & 1;
        const unsigned long long* pp = (const unsigned long long*)(Sb + row * 128 + half * 64);
        unsigned long long mask = 0;
#pragma unroll
        for (int w = 0; w < 8; ++w)
            mask |= (((pp[w] & 0x0101010101010101ULL) * 0x0102040810204080ULL) >> 56)
                    << (8 * w);
        unsigned long long* dst = (region == 0) ? g_qm : g_km;
        int h0 = nloc >> 6;
        dst[(size_t)(h0 + half) * MTOT + m0 + row] = mask;   // transposed layout
    } else if (MODE == 0) {
        // v region: single fp16 store
#pragma unroll
        for (int mi = 0; mi < 4; ++mi)
#pragma unroll
            for (int ni = 0; ni < 4; ++ni)
#pragma unroll
                for (int ci = 0; ci < 4; ci += 2) {
                    int gr = m0 + mrow0 + mi * 16 + trow + (ci ? 8 : 0);
                    int gc = ncol0 + ni * 8 + tcol;
                    int col = nloc + gc;
                    __half2 hh;
                    hh.x = __float2half_rn(acc[mi][ni][ci] + bias[col]);
                    hh.y = __float2half_rn(acc[mi][ni][ci + 1] + bias[col + 1]);
                    *(__half2*)(g_vh + (size_t)gr * EMBED + col) = hh;
                }
    } else {
#pragma unroll
        for (int mi = 0; mi < 4; ++mi)
#pragma unroll
            for (int ni = 0; ni < 4; ++ni)
#pragma unroll
                for (int ci = 0; ci < 4; ci += 2) {
                    int gr = m0 + mrow0 + mi * 16 + trow + (ci ? 8 : 0);
                    int gc = ncol0 + ni * 8 + tcol;
                    int col = nb_glob + gc;
                    float2 o;
                    o.x = acc[mi][ni][ci] + bias[col];
                    o.y = acc[mi][ni][ci + 1] + bias[col + 1];
                    *(float2*)(outf + (size_t)gr * EMBED + col) = o;
                }
    }
}

// -------------------- attention: in-register P fragments + 1-pass fp16 AV --------------------
// block 128 threads (4 warps). warp w: q rows [q0 + w*16, +16), full 64 d.
// V single fp16, 3-stage cp.async ring. P built directly in mma A-fragment registers.
// Softmax denominator computed on the tensor core via an all-ones B fragment.
#define NBUF 3
#define A_V   0                      // NBUF x 8192 (V tiles, SW128)
#define A_KM  (NBUF * 8192)          // NBUF x 512 (km tiles)
#define A_TAB (A_KM + NBUF * 512)    // 65 floats (fp16-exact values)
#define A_TOTAL (A_TAB + 512)

#define ATTN_ISSUE(t_, buf_) do {                                              \
    _Pragma("unroll")                                                          \
    for (int j = 0; j < 4; ++j) {                                              \
        int gi = tid + j * 128;                                                \
        int r = gi >> 3, cb = gi & 7;                                          \
        uint32_t off = sw128((uint32_t)(r * 128 + cb * 16));                   \
        cpa16(sb + A_V + (buf_) * 8192 + off,                                  \
              vhb + (size_t)((t_) * 64 + r) * EMBED + cb * 8);                 \
    }                                                                          \
    if (tid < 32) cpa16(sb + A_KM + (buf_) * 512 + tid * 16,                   \
                        kmb + (size_t)(t_) * 64 + tid * 2);                    \
    CP_COMMIT();                                                               \
} while (0)

__global__ __launch_bounds__(128) void attn_kernel() {
    extern __shared__ char smem[];
    const uint32_t sb = smem_u32(smem);
    const int tid = threadIdx.x;
    const int lane = tid & 31, wid = tid >> 5;
    const int qt = blockIdx.x;
    const int bh = blockIdx.y;
    const int b = bh >> 4, h = bh & 15;
    const int q0 = qt * 64;
    const size_t mbase = (size_t)b * TSEQ;

    const int g = lane >> 2;            // fragment row group
    const int c0 = (lane & 3) * 2;      // fragment col base

    const unsigned long long qmr0 =
        g_qm[(size_t)h * MTOT + mbase + q0 + wid * 16 + g];
    const unsigned long long qmr1 =
        g_qm[(size_t)h * MTOT + mbase + q0 + wid * 16 + g + 8];

    const __half* vhb = g_vh + mbase * EMBED + h * 64;
    const unsigned long long* kmb = g_km + (size_t)h * MTOT + mbase;

    // weight LUT (fp32 holding exactly-fp16 values => numerator/denominator consistent)
    if (tid < 65) {
        float w = exp2f((float)tid * 0.18033688011112042f);
        ((float*)(smem + A_TAB))[tid] = __half2float(__float2half_rn(w));
    }

    const int bRow = (lane & 7) + ((lane >> 3) & 1) * 8;
    const int bColB = ((lane >> 4) & 1) * 16;

    // all-ones B fragment (fp16 1.0 pairs) for the denominator MMA
    const uint32_t onesF[2] = {0x3C003C00u, 0x3C003C00u};

    float acc[8][4];
#pragma unroll
    for (int i = 0; i < 8; i++)
#pragma unroll
        for (int j = 0; j < 4; j++) acc[i][j] = 0.0f;
    float acc_s[4] = {0.0f, 0.0f, 0.0f, 0.0f};   // row-sum accumulator (denominator)

    ATTN_ISSUE(0, 0);
    ATTN_ISSUE(1, 1);

    int buf = 0;
    for (int kt = 0; kt < 32; ++kt) {
        if (kt < 31) CP_WAIT_1(); else CP_WAIT_ALL();
        __syncthreads();     // V[kt]/km[kt] visible; ring slot (kt+2)%3 fully consumed
        if (kt < 30) {
            int nb = buf + 2; if (nb >= NBUF) nb -= NBUF;
            ATTN_ISSUE(kt + 2, nb);
        }

        // build P fragments in registers; denominator via ones-MMA
        const unsigned long long* kms =
            (const unsigned long long*)(smem + A_KM + buf * 512);
        const float* tab = (const float*)(smem + A_TAB);
        uint32_t pf[4][4];
#pragma unroll
        for (int kc = 0; kc < 4; ++kc) {
            ulonglong2 kmA = *(const ulonglong2*)(kms + kc * 16 + c0);
            ulonglong2 kmB = *(const ulonglong2*)(kms + kc * 16 + c0 + 8);
            float w00 = tab[__popcll(qmr0 & kmA.x)];
            float w01 = tab[__popcll(qmr0 & kmA.y)];
            float w10 = tab[__popcll(qmr1 & kmA.x)];
            float w11 = tab[__popcll(qmr1 & kmA.y)];
            float w02 = tab[__popcll(qmr0 & kmB.x)];
            float w03 = tab[__popcll(qmr0 & kmB.y)];
            float w12 = tab[__popcll(qmr1 & kmB.x)];
            float w13 = tab[__popcll(qmr1 & kmB.y)];
            pf[kc][0] = f16x2pk(w00, w01);
            pf[kc][1] = f16x2pk(w10, w11);
            pf[kc][2] = f16x2pk(w02, w03);
            pf[kc][3] = f16x2pk(w12, w13);
            mma16816h(acc_s, pf[kc], onesF);   // D_s[q][n] += sum_k w ; replicated over n
        }

        // AV: acc[16q x 64d per warp] += P @ V (single fp16 pass)
        const uint32_t sV = sb + A_V + buf * 8192;
#pragma unroll
        for (int nt = 0; nt < 4; ++nt) {
            uint32_t bH[4][4];
#pragma unroll
            for (int kc = 0; kc < 4; ++kc) {
                uint32_t off = sw128((uint32_t)((kc * 16 + bRow) * 128 + nt * 32 + bColB));
                ldsm_x4t(bH[kc][0], bH[kc][1], bH[kc][2], bH[kc][3], sV + off);
            }
#pragma unroll
            for (int kc = 0; kc < 4; ++kc) {
                mma16816h(acc[nt * 2 + 0], pf[kc], &bH[kc][0]);
                mma16816h(acc[nt * 2 + 1], pf[kc], &bH[kc][2]);
            }
        }

        if (++buf >= NBUF) buf = 0;
    }

    // denominators come straight from the ones-MMA accumulator (no shuffles needed)
    const float inv0 = 1.0f / acc_s[0];
    const float inv1 = 1.0f / acc_s[2];

    // epilogue: normalize, single fp16 ctx store
    const size_t row0 = (mbase + q0 + wid * 16 + g) * EMBED + h * 64;
    const size_t row1 = (mbase + q0 + wid * 16 + g + 8) * EMBED + h * 64;
#pragma unroll
    for (int nt = 0; nt < 8; ++nt) {
        int col = nt * 8 + c0;
        __half2 hh0, hh1;
        hh0.x = __float2half_rn(acc[nt][0] * inv0);
        hh0.y = __float2half_rn(acc[nt][1] * inv0);
        hh1.x = __float2half_rn(acc[nt][2] * inv1);
        hh1.y = __float2half_rn(acc[nt][3] * inv1);
        *(__half2*)(g_ch + row0 + col) = hh0;
        *(__half2*)(g_ch + row1 + col) = hh1;
    }
}

// -------------------- launch --------------------
extern "C" void kernel_launch(void* const* d_in, const int* in_sizes, int n_in,
                              void* d_out, int out_size) {
    const float* x  = (const float*)d_in[0];
    const float* Wq = (const float*)d_in[1];
    const float* bq = (const float*)d_in[2];
    const float* Wk = (const float*)d_in[3];
    const float* bk = (const float*)d_in[4];
    const float* Wv = (const float*)d_in[5];
    const float* bv = (const float*)d_in[6];
    const float* Wo = (const float*)d_in[7];
    const float* bo = (const float*)d_in[8];
    float* out = (float*)d_out;

    cudaFuncSetAttribute(mma_gemm_kernel<0>, cudaFuncAttributeMaxDynamicSharedMemorySize, SMEM_G);
    cudaFuncSetAttribute(mma_gemm_kernel<1>, cudaFuncAttributeMaxDynamicSharedMemorySize, SMEM_G);
    cudaFuncSetAttribute(attn_kernel, cudaFuncAttributeMaxDynamicSharedMemorySize, A_TOTAL);

    convert_xw_kernel<<<8192, 256>>>(x, Wq, Wk, Wv, Wo);
    mma_gemm_kernel<0><<<dim3(32, 24), 256, SMEM_G>>>(bq, bk, bv, bo, nullptr);
    attn_kernel<<<dim3(32, 32), 128, A_TOTAL>>>();
    mma_gemm_kernel<1><<<dim3(32, 8), 256, SMEM_G>>>(bq, bk, bv, bo, out);
}

// round 17
// speedup vs baseline: 4.9832x; 1.0169x over previous
#include <cuda_runtime.h>
#include <cuda_fp16.h>
#include <cstdint>

// Problem constants
#define EMBED 1024
#define HEADS 16
#define BATCH 2
#define TSEQ  2048
#define MTOT  4096   // BATCH*TSEQ

// -------------------- device scratch --------------------
// masks stored TRANSPOSED: [head][m] so per-head tiles are contiguous
__device__ unsigned long long g_qm[HEADS * MTOT];
__device__ unsigned long long g_km[HEADS * MTOT];
__device__ __half g_vh[MTOT * EMBED];   // v projection, single fp16
__device__ __half g_xh[MTOT * EMBED];   // x, single fp16
__device__ __half g_wh[4096 * EMBED];   // Wq|Wk|Wv|Wo rows, single fp16
__device__ __half g_ch[MTOT * EMBED];   // ctx, single fp16 (written by attn)

// -------------------- helpers --------------------
__device__ __forceinline__ uint32_t smem_u32(const void* p) {
    uint32_t a;
    asm("{ .reg .u64 t; cvta.to.shared.u64 t, %1; cvt.u32.u64 %0, t; }" : "=r"(a) : "l"(p));
    return a;
}
__device__ __forceinline__ void ldsm_x4(uint32_t& r0, uint32_t& r1, uint32_t& r2,
                                        uint32_t& r3, uint32_t addr) {
    asm volatile("ldmatrix.sync.aligned.m8n8.x4.shared.b16 {%0,%1,%2,%3}, [%4];"
                 : "=r"(r0), "=r"(r1), "=r"(r2), "=r"(r3) : "r"(addr));
}
__device__ __forceinline__ void ldsm_x4t(uint32_t& r0, uint32_t& r1, uint32_t& r2,
                                         uint32_t& r3, uint32_t addr) {
    asm volatile("ldmatrix.sync.aligned.m8n8.x4.trans.shared.b16 {%0,%1,%2,%3}, [%4];"
                 : "=r"(r0), "=r"(r1), "=r"(r2), "=r"(r3) : "r"(addr));
}
__device__ __forceinline__ void mma16816h(float* d, const uint32_t* a, const uint32_t* b) {
    asm volatile(
        "mma.sync.aligned.m16n8k16.row.col.f32.f16.f16.f32 "
        "{%0,%1,%2,%3}, {%4,%5,%6,%7}, {%8,%9}, {%0,%1,%2,%3};"
        : "+f"(d[0]), "+f"(d[1]), "+f"(d[2]), "+f"(d[3])
        : "r"(a[0]), "r"(a[1]), "r"(a[2]), "r"(a[3]), "r"(b[0]), "r"(b[1]));
}
__device__ __forceinline__ void cpa16(uint32_t dst, const void* src) {
    asm volatile("cp.async.cg.shared.global [%0], [%1], 16;" :: "r"(dst), "l"(src));
}
#define CP_COMMIT()   asm volatile("cp.async.commit_group;" ::: "memory")
#define CP_WAIT_ALL() asm volatile("cp.async.wait_group 0;" ::: "memory")
#define CP_WAIT_1()   asm volatile("cp.async.wait_group 1;" ::: "memory")

__device__ __forceinline__ uint32_t sw128(uint32_t off) {
    return off ^ ((off >> 3) & 0x70);
}
// pack two fp32 (already exactly fp16-representable) into fp16x2: {lo, hi}
__device__ __forceinline__ uint32_t f16x2pk(float lo, float hi) {
    uint32_t r;
    asm("cvt.rn.f16x2.f32 %0, %2, %1;" : "=r"(r) : "f"(lo), "f"(hi));
    return r;
}

// -------------------- convert kernel: fp32 -> fp16 (x + W) --------------------
// grid 4096: blocks [0,2048) convert x, [2048,4096) convert W; 2 float4 per thread
__global__ __launch_bounds__(256) void convert_xw_kernel(
    const float* __restrict__ x,
    const float* __restrict__ Wq, const float* __restrict__ Wk,
    const float* __restrict__ Wv, const float* __restrict__ Wo) {
#pragma unroll
    for (int u = 0; u < 2; ++u) {
        __half* dst;
        const float* src;
        int i;
        if (blockIdx.x < 2048) {
            i = ((blockIdx.x * 512) + threadIdx.x * 2 + u) * 4;
            src = x + i;
            dst = g_xh + i;
        } else {
            i = (((blockIdx.x - 2048) * 512) + threadIdx.x * 2 + u) * 4;
            int row = i >> 10, col = i & 1023;
            if (row < 1024)      src = Wq + (size_t)row * EMBED + col;
            else if (row < 2048) src = Wk + (size_t)(row - 1024) * EMBED + col;
            else if (row < 3072) src = Wv + (size_t)(row - 2048) * EMBED + col;
            else                 src = Wo + (size_t)(row - 3072) * EMBED + col;
            dst = g_wh + i;
        }
        float4 v = *(const float4*)src;
        __half2 a, b;
        a.x = __float2half_rn(v.x); a.y = __float2half_rn(v.y);
        b.x = __float2half_rn(v.z); b.y = __float2half_rn(v.w);
        *(__half2*)(dst)     = a;
        *(__half2*)(dst + 2) = b;
    }
}

// -------------------- mma.sync GEMM (3-stage cp.async ring, fp16, single pass) --------------------
#define KC 32
#define TPAD 40
#define TILE_B (128 * TPAD * 2)   // 10240 B per sub-tile
#define GNBUF 3
#define BUFB (2 * TILE_B)         // {A, B} per stage
#define SMEM_G (GNBUF * BUFB)     // 61440

// MODE 0: A = x, W rows 0..3071 (Wq|Wk|Wv). grid (32, 24). q/k -> masks, v -> fp16.
// MODE 1: A = ctx, W rows 3072..4095 (Wo). grid (32, 8). -> fp32 out.
template <int MODE>
__global__ __launch_bounds__(256, 2) void mma_gemm_kernel(
    const float* __restrict__ bq, const float* __restrict__ bk,
    const float* __restrict__ bv, const float* __restrict__ bo,
    float* __restrict__ outf)
{
    extern __shared__ char smem[];
    const int tid = threadIdx.x;
    const int wid = tid >> 5, lane = tid & 31;
    const int m0 = blockIdx.x * 128;
    const int nb_glob = blockIdx.y * 128;

    const int region = (MODE == 0) ? (nb_glob >> 10) : 3;   // 0 q, 1 k, 2 v, 3 out

    const __half* Ah = (MODE == 0) ? g_xh : g_ch;
    const int wrow0 = (MODE == 0) ? nb_glob : (3072 + nb_glob);
    const __half* Bh = g_wh + (size_t)wrow0 * EMBED;
    const __half* Aoff = Ah + (size_t)m0 * EMBED;

    const int wm = wid >> 2, wn = wid & 3;
    const int mrow0 = wm * 64, ncol0 = wn * 32;

    const int aRow = lane & 15, aCol = (lane >> 4) * 8;
    const int bRow = ((lane >> 4) & 1) * 8 + (lane & 7);
    const int bCol = ((lane >> 3) & 1) * 8;

    float acc[4][4][4];
#pragma unroll
    for (int i = 0; i < 4; i++)
#pragma unroll
        for (int j = 0; j < 4; j++)
#pragma unroll
            for (int r = 0; r < 4; r++) acc[i][j][r] = 0.0f;

    const uint32_t sb = smem_u32(smem);

    auto issue = [&](int c_, int buf_) {
#pragma unroll
        for (int l = 0; l < 4; ++l) {
            const int sub = l >> 1;
            const int j = tid + (l & 1) * 256;
            const int r = j >> 2, gq = j & 3;
            const __half* src = (sub == 0) ? Aoff : Bh;
            uint32_t dst = sb + buf_ * BUFB + sub * TILE_B +
                           (uint32_t)(r * TPAD + gq * 8) * 2;
            cpa16(dst, src + (size_t)r * EMBED + c_ * KC + gq * 8);
        }
        CP_COMMIT();
    };

    issue(0, 0);
    issue(1, 1);

    int buf = 0;
    for (int c = 0; c < 32; ++c) {
        if (c < 31) CP_WAIT_1(); else CP_WAIT_ALL();
        __syncthreads();
        if (c < 30) {
            int nb = buf + 2; if (nb >= GNBUF) nb -= GNBUF;
            issue(c + 2, nb);
        }

        const uint32_t pAh = sb + buf * BUFB;
        const uint32_t pBh = pAh + TILE_B;
#pragma unroll
        for (int kk = 0; kk < KC; kk += 16) {
            uint32_t aF[4][4], bF[4][2];
#pragma unroll
            for (int mi = 0; mi < 4; ++mi) {
                uint32_t off = (uint32_t)((mrow0 + mi * 16 + aRow) * TPAD + kk + aCol) * 2;
                ldsm_x4(aF[mi][0], aF[mi][1], aF[mi][2], aF[mi][3], pAh + off);
            }
#pragma unroll
            for (int n2 = 0; n2 < 2; ++n2) {
                uint32_t off = (uint32_t)((ncol0 + n2 * 16 + bRow) * TPAD + kk + bCol) * 2;
                ldsm_x4(bF[n2 * 2][0], bF[n2 * 2][1],
                        bF[n2 * 2 + 1][0], bF[n2 * 2 + 1][1], pBh + off);
            }
#pragma unroll
            for (int mi = 0; mi < 4; ++mi)
#pragma unroll
                for (int ni = 0; ni < 4; ++ni) mma16816h(acc[mi][ni], aF[mi], bF[ni]);
        }
        if (++buf >= GNBUF) buf = 0;
    }

    // ---- epilogue ----
    const int nloc = nb_glob & 1023;
    const float* bias = (MODE == 1) ? bo : ((region == 0) ? bq : ((region == 1) ? bk : bv));

    const int trow = lane >> 2;
    const int tcol = (lane & 3) * 2;

    if (region <= 1) {
        __syncthreads();
        unsigned char* Sb = (unsigned char*)smem;
#pragma unroll
        for (int mi = 0; mi < 4; ++mi)
#pragma unroll
            for (int ni = 0; ni < 4; ++ni)
#pragma unroll
                for (int ci = 0; ci < 4; ++ci) {
                    int gr = mrow0 + mi * 16 + trow + ((ci >> 1) ? 8 : 0);
                    int gc = ncol0 + ni * 8 + tcol + (ci & 1);
                    float v = acc[mi][ni][ci] + bias[nloc + gc];
                    Sb[gr * 128 + gc] = (unsigned char)(v >= 1.0f ? 1 : 0);
                }
        __syncthreads();
        int row = tid >> 1, half = tid & 1;
        const unsigned long long* pp = (const unsigned long long*)(Sb + row * 128 + half * 64);
        unsigned long long mask = 0;
#pragma unroll
        for (int w = 0; w < 8; ++w)
            mask |= (((pp[w] & 0x0101010101010101ULL) * 0x0102040810204080ULL) >> 56)
                    << (8 * w);
        unsigned long long* dst = (region == 0) ? g_qm : g_km;
        int h0 = nloc >> 6;
        dst[(size_t)(h0 + half) * MTOT + m0 + row] = mask;   // transposed layout
    } else if (MODE == 0) {
        // v region: single fp16 store
#pragma unroll
        for (int mi = 0; mi < 4; ++mi)
#pragma unroll
            for (int ni = 0; ni < 4; ++ni)
#pragma unroll
                for (int ci = 0; ci < 4; ci += 2) {
                    int gr = m0 + mrow0 + mi * 16 + trow + (ci ? 8 : 0);
                    int gc = ncol0 + ni * 8 + tcol;
                    int col = nloc + gc;
                    __half2 hh;
                    hh.x = __float2half_rn(acc[mi][ni][ci] + bias[col]);
                    hh.y = __float2half_rn(acc[mi][ni][ci + 1] + bias[col + 1]);
                    *(__half2*)(g_vh + (size_t)gr * EMBED + col) = hh;
                }
    } else {
#pragma unroll
        for (int mi = 0; mi < 4; ++mi)
#pragma unroll
            for (int ni = 0; ni < 4; ++ni)
#pragma unroll
                for (int ci = 0; ci < 4; ci += 2) {
                    int gr = m0 + mrow0 + mi * 16 + trow + (ci ? 8 : 0);
                    int gc = ncol0 + ni * 8 + tcol;
                    int col = nb_glob + gc;
                    float2 o;
                    o.x = acc[mi][ni][ci] + bias[col];
                    o.y = acc[mi][ni][ci + 1] + bias[col + 1];
                    *(float2*)(outf + (size_t)gr * EMBED + col) = o;
                }
    }
}

// -------------------- attention: 128-k tiles, in-register P, 1-pass fp16 AV --------------------
// block 128 threads (4 warps). warp w: q rows [q0 + w*16, +16), full 64 d.
// V single fp16, 2-stage depth-1 cp.async ring, 16 tiles of 128 k (2 internal 64-k halves).
// Softmax denominator via all-ones B-fragment MMA.
#define NBUF 2
#define VT_B 16384                    // V tile: 128 rows x 128 B
#define A_V   0                       // NBUF x 16384
#define A_KM  (NBUF * VT_B)           // NBUF x 1024 (128 masks)
#define A_TAB (A_KM + NBUF * 1024)    // 65 floats (fp16-exact values)
#define A_TOTAL (A_TAB + 512)

#define ATTN_ISSUE(t_, buf_) do {                                              \
    _Pragma("unroll")                                                          \
    for (int j = 0; j < 8; ++j) {                                              \
        int gi = tid + j * 128;                                                \
        int r = gi >> 3, cb = gi & 7;                                          \
        uint32_t off = sw128((uint32_t)(r * 128 + cb * 16));                   \
        cpa16(sb + A_V + (buf_) * VT_B + off,                                  \
              vhb + (size_t)((t_) * 128 + r) * EMBED + cb * 8);                \
    }                                                                          \
    if (tid < 64) cpa16(sb + A_KM + (buf_) * 1024 + tid * 16,                  \
                        kmb + (size_t)(t_) * 128 + tid * 2);                   \
    CP_COMMIT();                                                               \
} while (0)

__global__ __launch_bounds__(128) void attn_kernel() {
    extern __shared__ char smem[];
    const uint32_t sb = smem_u32(smem);
    const int tid = threadIdx.x;
    const int lane = tid & 31, wid = tid >> 5;
    const int qt = blockIdx.x;
    const int bh = blockIdx.y;
    const int b = bh >> 4, h = bh & 15;
    const int q0 = qt * 64;
    const size_t mbase = (size_t)b * TSEQ;

    const int g = lane >> 2;            // fragment row group
    const int c0 = (lane & 3) * 2;      // fragment col base

    const unsigned long long qmr0 =
        g_qm[(size_t)h * MTOT + mbase + q0 + wid * 16 + g];
    const unsigned long long qmr1 =
        g_qm[(size_t)h * MTOT + mbase + q0 + wid * 16 + g + 8];

    const __half* vhb = g_vh + mbase * EMBED + h * 64;
    const unsigned long long* kmb = g_km + (size_t)h * MTOT + mbase;

    // weight LUT (fp32 holding exactly-fp16 values => numerator/denominator consistent)
    if (tid < 65) {
        float w = exp2f((float)tid * 0.18033688011112042f);
        ((float*)(smem + A_TAB))[tid] = __half2float(__float2half_rn(w));
    }

    const int bRow = (lane & 7) + ((lane >> 3) & 1) * 8;
    const int bColB = ((lane >> 4) & 1) * 16;

    // all-ones B fragment (fp16 1.0 pairs) for the denominator MMA
    const uint32_t onesF[2] = {0x3C003C00u, 0x3C003C00u};

    float acc[8][4];
#pragma unroll
    for (int i = 0; i < 8; i++)
#pragma unroll
        for (int j = 0; j < 4; j++) acc[i][j] = 0.0f;
    float acc_s[4] = {0.0f, 0.0f, 0.0f, 0.0f};   // row-sum accumulator (denominator)

    ATTN_ISSUE(0, 0);

    int buf = 0;
    for (int kt = 0; kt < 16; ++kt) {
        CP_WAIT_ALL();
        __syncthreads();     // V[kt]/km[kt] visible; other buffer fully consumed
        if (kt < 15) ATTN_ISSUE(kt + 1, buf ^ 1);

        const unsigned long long* kms =
            (const unsigned long long*)(smem + A_KM + buf * 1024);
        const float* tab = (const float*)(smem + A_TAB);
        const uint32_t sV = sb + A_V + buf * VT_B;

#pragma unroll
        for (int hf = 0; hf < 2; ++hf) {
            const unsigned long long* kmh = kms + hf * 64;
            // build P fragments in registers; denominator via ones-MMA
            uint32_t pf[4][4];
#pragma unroll
            for (int kc = 0; kc < 4; ++kc) {
                ulonglong2 kmA = *(const ulonglong2*)(kmh + kc * 16 + c0);
                ulonglong2 kmB = *(const ulonglong2*)(kmh + kc * 16 + c0 + 8);
                float w00 = tab[__popcll(qmr0 & kmA.x)];
                float w01 = tab[__popcll(qmr0 & kmA.y)];
                float w10 = tab[__popcll(qmr1 & kmA.x)];
                float w11 = tab[__popcll(qmr1 & kmA.y)];
                float w02 = tab[__popcll(qmr0 & kmB.x)];
                float w03 = tab[__popcll(qmr0 & kmB.y)];
                float w12 = tab[__popcll(qmr1 & kmB.x)];
                float w13 = tab[__popcll(qmr1 & kmB.y)];
                pf[kc][0] = f16x2pk(w00, w01);
                pf[kc][1] = f16x2pk(w10, w11);
                pf[kc][2] = f16x2pk(w02, w03);
                pf[kc][3] = f16x2pk(w12, w13);
                mma16816h(acc_s, pf[kc], onesF);
            }
            // AV: acc[16q x 64d per warp] += P @ V[half]
#pragma unroll
            for (int nt = 0; nt < 4; ++nt) {
                uint32_t bH[4][4];
#pragma unroll
                for (int kc = 0; kc < 4; ++kc) {
                    uint32_t off = sw128(
                        (uint32_t)((hf * 64 + kc * 16 + bRow) * 128 + nt * 32 + bColB));
                    ldsm_x4t(bH[kc][0], bH[kc][1], bH[kc][2], bH[kc][3], sV + off);
                }
#pragma unroll
                for (int kc = 0; kc < 4; ++kc) {
                    mma16816h(acc[nt * 2 + 0], pf[kc], &bH[kc][0]);
                    mma16816h(acc[nt * 2 + 1], pf[kc], &bH[kc][2]);
                }
            }
        }
        buf ^= 1;
    }

    // denominators come straight from the ones-MMA accumulator
    const float inv0 = 1.0f / acc_s[0];
    const float inv1 = 1.0f / acc_s[2];

    // epilogue: normalize, single fp16 ctx store
    const size_t row0 = (mbase + q0 + wid * 16 + g) * EMBED + h * 64;
    const size_t row1 = (mbase + q0 + wid * 16 + g + 8) * EMBED + h * 64;
#pragma unroll
    for (int nt = 0; nt < 8; ++nt) {
        int col = nt * 8 + c0;
        __half2 hh0, hh1;
        hh0.x = __float2half_rn(acc[nt][0] * inv0);
        hh0.y = __float2half_rn(acc[nt][1] * inv0);
        hh1.x = __float2half_rn(acc[nt][2] * inv1);
        hh1.y = __float2half_rn(acc[nt][3] * inv1);
        *(__half2*)(g_ch + row0 + col) = hh0;
        *(__half2*)(g_ch + row1 + col) = hh1;
    }
}

// -------------------- launch --------------------
extern "C" void kernel_launch(void* const* d_in, const int* in_sizes, int n_in,
                              void* d_out, int out_size) {
    const float* x  = (const float*)d_in[0];
    const float* Wq = (const float*)d_in[1];
    const float* bq = (const float*)d_in[2];
    const float* Wk = (const float*)d_in[3];
    const float* bk = (const float*)d_in[4];
    const float* Wv = (const float*)d_in[5];
    const float* bv = (const float*)d_in[6];
    const float* Wo = (const float*)d_in[7];
    const float* bo = (const float*)d_in[8];
    float* out = (float*)d_out;

    cudaFuncSetAttribute(mma_gemm_kernel<0>, cudaFuncAttributeMaxDynamicSharedMemorySize, SMEM_G);
    cudaFuncSetAttribute(mma_gemm_kernel<1>, cudaFuncAttributeMaxDynamicSharedMemorySize, SMEM_G);
    cudaFuncSetAttribute(attn_kernel, cudaFuncAttributeMaxDynamicSharedMemorySize, A_TOTAL);

    convert_xw_kernel<<<4096, 256>>>(x, Wq, Wk, Wv, Wo);
    mma_gemm_kernel<0><<<dim3(32, 24), 256, SMEM_G>>>(bq, bk, bv, bo, nullptr);
    attn_kernel<<<dim3(32, 32), 128, A_TOTAL>>>();
    mma_gemm_kernel<1><<<dim3(32, 8), 256, SMEM_G>>>(bq, bk, bv, bo, out);
}